// round 3
// baseline (speedup 1.0000x reference)
#include <cuda_runtime.h>
#include <math.h>

namespace {
constexpr int H        = 128;
constexpr int PITCH    = 132;   // padded shared row: conflict-free LDS.128, 16B aligned
constexpr int NNODE    = 13;
constexpr int NJN      = 12;
constexpr int TT       = 3;
constexpr int OBSW     = 47;
constexpr int OBS_LEN  = TT * OBSW;  // 141
constexpr int GPB      = 8;          // graphs per block (1 warp per graph)
constexpr int NTHREADS = 256;
constexpr int NLAYER   = 3;
constexpr int BASE_F   = 33;
constexpr int JOINT_F  = 9;

struct Smem {
    float wrel[H * PITCH];
    float wroot[H * PITCH];
    float web[BASE_F * PITCH];
    float wej[JOINT_F * PITCH];
    float xs[GPB][NNODE][H];
    float obs_s[GPB][144];
    float beb[H];
    float bej[H];
    float brel[NLAYER][H];
    float wdec[H];
    float bdec;
};

using u64 = unsigned long long;

__device__ __forceinline__ float elu1(float v) { return v > 0.f ? v : expm1f(v); }
__device__ __forceinline__ float4 elu4(float4 v) {
    return make_float4(elu1(v.x), elu1(v.y), elu1(v.z), elu1(v.w));
}

// ---- packed f32x2 ops (sm_100+; one fma-pipe slot per 2 fp32 MACs) ----
__device__ __forceinline__ void fma2(u64& d, u64 a, u64 b) {
    asm("fma.rn.f32x2 %0, %1, %2, %0;" : "+l"(d) : "l"(a), "l"(b));
}
__device__ __forceinline__ u64 add2(u64 a, u64 b) {
    u64 r; asm("add.rn.f32x2 %0, %1, %2;" : "=l"(r) : "l"(a), "l"(b)); return r;
}
__device__ __forceinline__ u64 dup2(float x) {
    u64 r; asm("mov.b64 %0, {%1, %1};" : "=l"(r) : "f"(x)); return r;
}
__device__ __forceinline__ void unpk(float& lo, float& hi, u64 p) {
    asm("mov.b64 {%0, %1}, %2;" : "=f"(lo), "=f"(hi) : "l"(p));
}
} // namespace

#define FMA4S(Y, A, W)                                                    \
    do {                                                                  \
        (Y).x = fmaf((A), (W).x, (Y).x);                                  \
        (Y).y = fmaf((A), (W).y, (Y).y);                                  \
        (Y).z = fmaf((A), (W).z, (Y).z);                                  \
        (Y).w = fmaf((A), (W).w, (Y).w);                                  \
    } while (0)

__global__ __launch_bounds__(NTHREADS, 1) void gnn_fused_kernel(
    const float* __restrict__ obs,
    const float* __restrict__ We_b, const float* __restrict__ be_b,
    const float* __restrict__ We_j, const float* __restrict__ be_j,
    const float* __restrict__ W_rel, const float* __restrict__ W_root,
    const float* __restrict__ b_rel,
    const float* __restrict__ W_dec, const float* __restrict__ b_dec,
    float* __restrict__ out, int B)
{
    extern __shared__ char smem_raw[];
    Smem& s = *reinterpret_cast<Smem*>(smem_raw);
    const int tid  = threadIdx.x;
    const int lane = tid & 31;
    const int warp = tid >> 5;

    // ---- stage encoder weights (transposed) + biases ----
    for (int i = tid; i < H * BASE_F; i += NTHREADS) {
        int o = i / BASE_F, f = i - o * BASE_F;
        s.web[f * PITCH + o] = We_b[i];
    }
    for (int i = tid; i < H * JOINT_F; i += NTHREADS) {
        int o = i / JOINT_F, f = i - o * JOINT_F;
        s.wej[f * PITCH + o] = We_j[i];
    }
    if (tid < H) {
        s.beb[tid]  = be_b[tid];
        s.bej[tid]  = be_j[tid];
        s.wdec[tid] = W_dec[tid];
    }
    for (int i = tid; i < NLAYER * H; i += NTHREADS)
        (&s.brel[0][0])[i] = b_rel[i];
    if (tid == 0) s.bdec = b_dec[0];

    const int  b      = blockIdx.x * GPB + warp;
    const bool active = (b < B);
    if (active) {
        for (int i = lane; i < OBS_LEN; i += 32)
            s.obs_s[warp][i] = obs[b * OBS_LEN + i];
    }
    __syncthreads();

    const int o0 = lane * 4;

    // ---------------- encoders (1.4% of FLOPs, keep scalar) ----------------
    if (active) {
        const int BIDX[11] = {0, 1, 2, 3, 4, 5, 6, 7, 8, 45, 46};
        float4 acc = *reinterpret_cast<const float4*>(&s.beb[o0]);
        #pragma unroll
        for (int t = 0; t < TT; t++) {
            #pragma unroll
            for (int i = 0; i < 11; i++) {
                float  feat = s.obs_s[warp][t * OBSW + BIDX[i]];
                float4 wb   = *reinterpret_cast<const float4*>(&s.web[(t * 11 + i) * PITCH + o0]);
                FMA4S(acc, feat, wb);
            }
        }
        *reinterpret_cast<float4*>(&s.xs[warp][0][o0]) = elu4(acc);

        float4 aj[NJN];
        float4 bj = *reinterpret_cast<const float4*>(&s.bej[o0]);
        #pragma unroll
        for (int j = 0; j < NJN; j++) aj[j] = bj;
        #pragma unroll
        for (int f = 0; f < JOINT_F; f++) {
            int    t  = f / 3, c = f % 3;
            float4 wj = *reinterpret_cast<const float4*>(&s.wej[f * PITCH + o0]);
            #pragma unroll
            for (int j = 0; j < NJN; j++) {
                float feat = s.obs_s[warp][t * OBSW + 9 + c * 12 + j];
                FMA4S(aj[j], feat, wj);
            }
        }
        #pragma unroll
        for (int j = 0; j < NJN; j++)
            *reinterpret_cast<float4*>(&s.xs[warp][1 + j][o0]) = elu4(aj[j]);
    }

    // ---------------- GraphConv layers (packed f32x2 inner loop) ----------------
    for (int l = 0; l < NLAYER; l++) {
        __syncthreads();
        {
            const float* wr = W_rel  + l * H * H;
            const float* wo = W_root + l * H * H;
            for (int i = tid; i < H * H; i += NTHREADS) {
                int o = i >> 7, h = i & (H - 1);
                s.wrel[h * PITCH + o]  = wr[i];
                s.wroot[h * PITCH + o] = wo[i];
            }
        }
        __syncthreads();

        if (active) {
            // y[n]: 4 outputs per thread = 2 f32x2 pairs
            u64 y[NNODE][2];
            #pragma unroll
            for (int n = 0; n < NNODE; n++) { y[n][0] = 0ull; y[n][1] = 0ull; }

            #pragma unroll 2
            for (int h = 0; h < H; h += 2) {
                // weight rows h and h+1, 4 outputs each = 2 pairs each
                const ulonglong2 wrA = *reinterpret_cast<const ulonglong2*>(&s.wrel[(h + 0) * PITCH + o0]);
                const ulonglong2 wrB = *reinterpret_cast<const ulonglong2*>(&s.wrel[(h + 1) * PITCH + o0]);
                const ulonglong2 woA = *reinterpret_cast<const ulonglong2*>(&s.wroot[(h + 0) * PITCH + o0]);
                const ulonglong2 woB = *reinterpret_cast<const ulonglong2*>(&s.wroot[(h + 1) * PITCH + o0]);

                // duplicated-pair x values: xd[n][c] = {x[n][h+c], x[n][h+c]}
                u64 xd[NNODE][2];
                #pragma unroll
                for (int n = 0; n < NNODE; n++) {
                    u64 xp = *reinterpret_cast<const u64*>(&s.xs[warp][n][h]);
                    float lo, hi;
                    unpk(lo, hi, xp);
                    xd[n][0] = dup2(lo);
                    xd[n][1] = dup2(hi);
                }

                // agg (duplicated pairs), fixed tree in-neighbors
                u64 a[NNODE][2];
                #pragma unroll
                for (int c = 0; c < 2; c++) {
                    a[0][c]  = add2(add2(xd[1][c], xd[4][c]), add2(xd[7][c], xd[10][c]));
                    a[1][c]  = add2(xd[0][c],  xd[2][c]);
                    a[2][c]  = add2(xd[1][c],  xd[3][c]);
                    a[3][c]  = xd[2][c];
                    a[4][c]  = add2(xd[0][c],  xd[5][c]);
                    a[5][c]  = add2(xd[4][c],  xd[6][c]);
                    a[6][c]  = xd[5][c];
                    a[7][c]  = add2(xd[0][c],  xd[8][c]);
                    a[8][c]  = add2(xd[7][c],  xd[9][c]);
                    a[9][c]  = xd[8][c];
                    a[10][c] = add2(xd[0][c],  xd[11][c]);
                    a[11][c] = add2(xd[10][c], xd[12][c]);
                    a[12][c] = xd[11][c];
                }

                // y[n] += a[n]*Wrel[h..h+1] + x[n]*Wroot[h..h+1]  (8 FFMA2 per node)
                #pragma unroll
                for (int n = 0; n < NNODE; n++) {
                    fma2(y[n][0], a[n][0],  wrA.x);
                    fma2(y[n][1], a[n][0],  wrA.y);
                    fma2(y[n][0], a[n][1],  wrB.x);
                    fma2(y[n][1], a[n][1],  wrB.y);
                    fma2(y[n][0], xd[n][0], woA.x);
                    fma2(y[n][1], xd[n][0], woA.y);
                    fma2(y[n][0], xd[n][1], woB.x);
                    fma2(y[n][1], xd[n][1], woB.y);
                }
            }

            const float4 br = *reinterpret_cast<const float4*>(&s.brel[l][o0]);
            #pragma unroll
            for (int n = 0; n < NNODE; n++) {
                float y0, y1, y2, y3;
                unpk(y0, y1, y[n][0]);
                unpk(y2, y3, y[n][1]);
                float4 v = make_float4(y0 + br.x, y1 + br.y, y2 + br.z, y3 + br.w);
                *reinterpret_cast<float4*>(&s.xs[warp][n][o0]) = elu4(v);
            }
        }
    }

    // ---------------- decoder ----------------
    if (active) {
        __syncwarp();
        float4 wd = *reinterpret_cast<const float4*>(&s.wdec[o0]);
        float  bd = s.bdec;
        #pragma unroll
        for (int j = 0; j < NJN; j++) {
            float4 xv = *reinterpret_cast<const float4*>(&s.xs[warp][1 + j][o0]);
            float  p  = xv.x * wd.x + xv.y * wd.y + xv.z * wd.z + xv.w * wd.w;
            #pragma unroll
            for (int off = 16; off > 0; off >>= 1)
                p += __shfl_xor_sync(0xffffffffu, p, off);
            if (lane == 0) out[b * NJN + j] = p + bd;
        }
    }
}

extern "C" void kernel_launch(void* const* d_in, const int* in_sizes, int n_in,
                              void* d_out, int out_size)
{
    const float* obs    = (const float*)d_in[0];
    const float* We_b   = (const float*)d_in[1];
    const float* be_b   = (const float*)d_in[2];
    const float* We_j   = (const float*)d_in[3];
    const float* be_j   = (const float*)d_in[4];
    const float* W_rel  = (const float*)d_in[5];
    const float* W_root = (const float*)d_in[6];
    const float* b_rel  = (const float*)d_in[7];
    const float* W_dec  = (const float*)d_in[8];
    const float* b_dec  = (const float*)d_in[9];
    float*       out    = (float*)d_out;

    const int B    = in_sizes[0] / OBS_LEN;
    const int grid = (B + GPB - 1) / GPB;
    const size_t shmem = sizeof(Smem);

    cudaFuncSetAttribute(gnn_fused_kernel,
                         cudaFuncAttributeMaxDynamicSharedMemorySize, (int)shmem);

    gnn_fused_kernel<<<grid, NTHREADS, shmem>>>(
        obs, We_b, be_b, We_j, be_j, W_rel, W_root, b_rel, W_dec, b_dec, out, B);
}

// round 5
// speedup vs baseline: 1.4905x; 1.4905x over previous
#include <cuda_runtime.h>
#include <cuda_bf16.h>
#include <stdint.h>
#include <math.h>

namespace {
constexpr int H = 128, NNODE = 13, NJN = 12, OBS_LEN = 141, NLAYER = 3;
constexpr int GPT = 9;               // graphs per CTA -> 117 rows, padded to 128
constexpr int MROWS = 128;
constexpr int NTHREADS = 256;
constexpr int BASE_F = 33, JOINT_F = 9;

constexpr uint32_t PITCHB = 272;     // bytes per bf16 row: 128 elems + 8 pad (conflict-free ldmatrix)
constexpr uint32_t MATB   = MROWS * PITCHB;  // 34816

constexpr uint32_t OFF_XH = 0;
constexpr uint32_t OFF_XL = MATB;
constexpr uint32_t OFF_GH = 2 * MATB;
constexpr uint32_t OFF_GL = 3 * MATB;
constexpr uint32_t OFF_WH = 4 * MATB;
constexpr uint32_t OFF_WL = 5 * MATB;
constexpr uint32_t OFF_OBS = 6 * MATB;             // 9 x 144 floats = 5184 B
constexpr uint32_t OFF_BIAS = OFF_OBS + GPT * 144 * 4;
constexpr uint32_t BO_BEB = 0, BO_BEJ = 512, BO_BREL = 1024, BO_WDEC = 2560, BO_BDEC = 3072;
constexpr uint32_t OFF_WEB = OFF_WH;               // encoder weights live in W area pre-layer0
constexpr uint32_t OFF_WEJ = OFF_WH + 16896;
constexpr uint32_t SMEM_DYN = OFF_BIAS + 3104;     // ~217.2 KB

__device__ __constant__ int8_t NSRC[13] = {4,2,2,1,2,2,1,2,2,1,2,2,1};
__device__ __constant__ int8_t SRCS[13][4] = {
    {1,4,7,10},{0,2,0,0},{1,3,0,0},{2,0,0,0},{0,5,0,0},{4,6,0,0},{5,0,0,0},
    {0,8,0,0},{7,9,0,0},{8,0,0,0},{0,11,0,0},{10,12,0,0},{11,0,0,0}};
__device__ __constant__ int8_t BIDX[11] = {0,1,2,3,4,5,6,7,8,45,46};

// pre-split weights: [layer][rel=0/root=1][hi=0/lo=1][n*128+k]  (bf16, 384 KB)
__device__ __nv_bfloat16 g_wsplit[NLAYER][2][2][H * H];

__device__ __forceinline__ uint32_t smem_u32(const void* p) {
    uint32_t a;
    asm("{ .reg .u64 t; cvta.to.shared.u64 t, %1; cvt.u32.u64 %0, t; }" : "=r"(a) : "l"(p));
    return a;
}
__device__ __forceinline__ float elu1(float v) { return v > 0.f ? v : expm1f(v); }

__device__ __forceinline__ void ldsm4(uint32_t& r0, uint32_t& r1, uint32_t& r2, uint32_t& r3,
                                      uint32_t addr) {
    asm volatile("ldmatrix.sync.aligned.m8n8.x4.shared.b16 {%0,%1,%2,%3}, [%4];"
                 : "=r"(r0), "=r"(r1), "=r"(r2), "=r"(r3) : "r"(addr));
}
__device__ __forceinline__ void mma16816(float* c, const uint32_t* a, uint32_t b0, uint32_t b1) {
    asm volatile(
        "mma.sync.aligned.m16n8k16.row.col.f32.bf16.bf16.f32 "
        "{%0,%1,%2,%3}, {%4,%5,%6,%7}, {%8,%9}, {%0,%1,%2,%3};"
        : "+f"(c[0]), "+f"(c[1]), "+f"(c[2]), "+f"(c[3])
        : "r"(a[0]), "r"(a[1]), "r"(a[2]), "r"(a[3]), "r"(b0), "r"(b1));
}

__device__ __forceinline__ void split_store8(char* sm, uint32_t offH, uint32_t offL,
                                             uint32_t doff, const float* v) {
    uint4 hh, ll;
    uint32_t* ph = (uint32_t*)&hh;
    uint32_t* pl = (uint32_t*)&ll;
#pragma unroll
    for (int k = 0; k < 4; k++) {
        float a = v[2 * k], b = v[2 * k + 1];
        __nv_bfloat16 ha = __float2bfloat16_rn(a), hb = __float2bfloat16_rn(b);
        float ra = a - __bfloat162float(ha), rb = b - __bfloat162float(hb);
        __nv_bfloat16 la = __float2bfloat16_rn(ra), lb = __float2bfloat16_rn(rb);
        ph[k] = (uint32_t)__bfloat16_as_ushort(ha) | ((uint32_t)__bfloat16_as_ushort(hb) << 16);
        pl[k] = (uint32_t)__bfloat16_as_ushort(la) | ((uint32_t)__bfloat16_as_ushort(lb) << 16);
    }
    *(uint4*)(sm + offH + doff) = hh;
    *(uint4*)(sm + offL + doff) = ll;
}
__device__ __forceinline__ void acc8(float* s, uint4 hh, uint4 ll) {
    const uint32_t* ph = (const uint32_t*)&hh;
    const uint32_t* pl = (const uint32_t*)&ll;
#pragma unroll
    for (int k = 0; k < 4; k++) {
        uint32_t wh = ph[k], wl = pl[k];
        s[2 * k]     += __uint_as_float(wh << 16) + __uint_as_float(wl << 16);
        s[2 * k + 1] += __uint_as_float(wh & 0xffff0000u) + __uint_as_float(wl & 0xffff0000u);
    }
}
__device__ __forceinline__ void split_store2(char* sm, uint32_t doff, float a, float b) {
    __nv_bfloat16 ha = __float2bfloat16_rn(a), hb = __float2bfloat16_rn(b);
    float ra = a - __bfloat162float(ha), rb = b - __bfloat162float(hb);
    __nv_bfloat16 la = __float2bfloat16_rn(ra), lb = __float2bfloat16_rn(rb);
    *(uint32_t*)(sm + OFF_XH + doff) =
        (uint32_t)__bfloat16_as_ushort(ha) | ((uint32_t)__bfloat16_as_ushort(hb) << 16);
    *(uint32_t*)(sm + OFF_XL + doff) =
        (uint32_t)__bfloat16_as_ushort(la) | ((uint32_t)__bfloat16_as_ushort(lb) << 16);
}

// 3-term split GEMM: acc += AH@BH^T + AL@BH^T + AH@BL^T   (A rows m0..m0+15, all 128 cols)
__device__ __forceinline__ void gemm3(uint32_t aH, uint32_t aL, uint32_t bH, uint32_t bL,
                                      float acc[16][4], int lane, int m0) {
    const uint32_t arow = (uint32_t)(m0 + (lane & 15));
    const uint32_t acol = (uint32_t)((lane >> 4) << 4);          // 0 or 16 bytes
    const uint32_t brow = (uint32_t)((lane & 7) + ((lane >> 4) << 3));
    const uint32_t bcol = (uint32_t)(((lane >> 3) & 1) << 4);
    const uint32_t aH0 = aH + arow * PITCHB + acol;
    const uint32_t aL0 = aL + arow * PITCHB + acol;
    const uint32_t bH0 = bH + brow * PITCHB + bcol;
    const uint32_t bL0 = bL + brow * PITCHB + bcol;
#pragma unroll 2
    for (int k = 0; k < 8; k++) {
        const uint32_t kb = (uint32_t)k * 32u;
        uint32_t ah[4], al[4];
        ldsm4(ah[0], ah[1], ah[2], ah[3], aH0 + kb);
        ldsm4(al[0], al[1], al[2], al[3], aL0 + kb);
#pragma unroll
        for (int np = 0; np < 8; np++) {
            const uint32_t noff = (uint32_t)np * (16u * PITCHB) + kb;
            uint32_t h0, h1, h2, h3, l0, l1, l2, l3;
            ldsm4(h0, h1, h2, h3, bH0 + noff);
            ldsm4(l0, l1, l2, l3, bL0 + noff);
            mma16816(acc[2 * np],     ah, h0, h1);
            mma16816(acc[2 * np + 1], ah, h2, h3);
            mma16816(acc[2 * np],     al, h0, h1);
            mma16816(acc[2 * np + 1], al, h2, h3);
            mma16816(acc[2 * np],     ah, l0, l1);
            mma16816(acc[2 * np + 1], ah, l2, l3);
        }
    }
}
} // namespace

__global__ void split_weights_kernel(const float* __restrict__ W_rel,
                                     const float* __restrict__ W_root) {
    int i = blockIdx.x * blockDim.x + threadIdx.x;
    if (i >= NLAYER * 2 * H * H) return;
    int l = i / (2 * H * H);
    int r = i % (2 * H * H);
    int g = r / (H * H);
    int e = r % (H * H);
    float w = (g == 0) ? W_rel[l * H * H + e] : W_root[l * H * H + e];
    __nv_bfloat16 hi = __float2bfloat16_rn(w);
    float rem = w - __bfloat162float(hi);
    g_wsplit[l][g][0][e] = hi;
    g_wsplit[l][g][1][e] = __float2bfloat16_rn(rem);
}

__global__ __launch_bounds__(NTHREADS, 1) void gnn_mma_kernel(
    const float* __restrict__ obs,
    const float* __restrict__ We_b, const float* __restrict__ be_b,
    const float* __restrict__ We_j, const float* __restrict__ be_j,
    const float* __restrict__ b_rel,
    const float* __restrict__ W_dec, const float* __restrict__ b_dec,
    float* __restrict__ out, int B)
{
    extern __shared__ char sm[];
    const uint32_t sb = smem_u32(sm);
    const int tid = threadIdx.x, lane = tid & 31, wid = tid >> 5;
    const int m0 = wid * 16;
    const int g0 = blockIdx.x * GPT;
    const int ng = min(GPT, B - g0);
    const int rows_real = ng * NNODE;

    // ---- stage biases / encoder weights (transposed) / obs ----
    if (tid < H) {
        ((float*)(sm + OFF_BIAS + BO_BEB))[tid]  = be_b[tid];
        ((float*)(sm + OFF_BIAS + BO_BEJ))[tid]  = be_j[tid];
        ((float*)(sm + OFF_BIAS + BO_WDEC))[tid] = W_dec[tid];
    }
    for (int i = tid; i < NLAYER * H; i += NTHREADS)
        ((float*)(sm + OFF_BIAS + BO_BREL))[i] = b_rel[i];
    if (tid == 0) ((float*)(sm + OFF_BIAS + BO_BDEC))[0] = b_dec[0];
    for (int i = tid; i < H * BASE_F; i += NTHREADS) {
        int h = i / BASE_F, f = i - h * BASE_F;
        ((float*)(sm + OFF_WEB))[f * H + h] = We_b[i];
    }
    for (int i = tid; i < H * JOINT_F; i += NTHREADS) {
        int h = i / JOINT_F, f = i - h * JOINT_F;
        ((float*)(sm + OFF_WEJ))[f * H + h] = We_j[i];
    }
    for (int i = tid; i < ng * OBS_LEN; i += NTHREADS) {
        int g = i / OBS_LEN, k = i - g * OBS_LEN;
        ((float*)(sm + OFF_OBS))[g * 144 + k] = obs[(size_t)(g0 + g) * OBS_LEN + k];
    }
    __syncthreads();

    // ---- encoder: X hi/lo (zero the pad rows) ----
    for (int idx = tid; idx < MROWS * 16; idx += NTHREADS) {
        int row = idx >> 4, c0 = (idx & 15) << 3;
        uint32_t doff = (uint32_t)row * PITCHB + (uint32_t)c0 * 2;
        if (row >= rows_real) {
            uint4 z = make_uint4(0, 0, 0, 0);
            *(uint4*)(sm + OFF_XH + doff) = z;
            *(uint4*)(sm + OFF_XL + doff) = z;
            continue;
        }
        int g = row / NNODE, n = row - g * NNODE;
        const float* ob = (const float*)(sm + OFF_OBS) + g * 144;
        float acc[8];
        if (n == 0) {
            const float* be = (const float*)(sm + OFF_BIAS + BO_BEB);
#pragma unroll
            for (int e = 0; e < 8; e++) acc[e] = be[c0 + e];
#pragma unroll
            for (int t = 0; t < 3; t++)
#pragma unroll
                for (int i2 = 0; i2 < 11; i2++) {
                    float ft = ob[t * 47 + BIDX[i2]];
                    const float* w = (const float*)(sm + OFF_WEB) + (t * 11 + i2) * H + c0;
#pragma unroll
                    for (int e = 0; e < 8; e++) acc[e] = fmaf(ft, w[e], acc[e]);
                }
        } else {
            int j = n - 1;
            const float* be = (const float*)(sm + OFF_BIAS + BO_BEJ);
#pragma unroll
            for (int e = 0; e < 8; e++) acc[e] = be[c0 + e];
#pragma unroll
            for (int f = 0; f < 9; f++) {
                float ft = ob[(f / 3) * 47 + 9 + (f % 3) * 12 + j];
                const float* w = (const float*)(sm + OFF_WEJ) + f * H + c0;
#pragma unroll
                for (int e = 0; e < 8; e++) acc[e] = fmaf(ft, w[e], acc[e]);
            }
        }
#pragma unroll
        for (int e = 0; e < 8; e++) acc[e] = elu1(acc[e]);
        split_store8(sm, OFF_XH, OFF_XL, doff, acc);
    }

    // ---- layers ----
    for (int l = 0; l < NLAYER; l++) {
        __syncthreads();  // X ready; W area free of readers

        // agg pass: G = scatter-sum of X (fp32 reconstruct, re-split)
        for (int idx = tid; idx < MROWS * 16; idx += NTHREADS) {
            int row = idx >> 4, c0 = (idx & 15) << 3;
            uint32_t doff = (uint32_t)row * PITCHB + (uint32_t)c0 * 2;
            float s[8] = {0.f, 0.f, 0.f, 0.f, 0.f, 0.f, 0.f, 0.f};
            if (row < rows_real) {
                int gb = (row / NNODE) * NNODE, n = row - gb;
                int cnt = NSRC[n];
                for (int k2 = 0; k2 < cnt; k2++) {
                    uint32_t soff = (uint32_t)(gb + SRCS[n][k2]) * PITCHB + (uint32_t)c0 * 2;
                    acc8(s, *(const uint4*)(sm + OFF_XH + soff),
                            *(const uint4*)(sm + OFF_XL + soff));
                }
            }
            split_store8(sm, OFF_GH, OFF_GL, doff, s);
        }
        // stage W_rel hi/lo
        {
            const uint4* srcH = (const uint4*)&g_wsplit[l][0][0][0];
            const uint4* srcL = (const uint4*)&g_wsplit[l][0][1][0];
            for (int idx = tid; idx < H * 16; idx += NTHREADS) {
                uint32_t d = (uint32_t)(idx >> 4) * PITCHB + (uint32_t)(idx & 15) * 16;
                *(uint4*)(sm + OFF_WH + d) = srcH[idx];
                *(uint4*)(sm + OFF_WL + d) = srcL[idx];
            }
        }
        __syncthreads();

        float acc[16][4];
#pragma unroll
        for (int nt = 0; nt < 16; nt++)
#pragma unroll
            for (int e = 0; e < 4; e++) acc[nt][e] = 0.f;

        gemm3(sb + OFF_GH, sb + OFF_GL, sb + OFF_WH, sb + OFF_WL, acc, lane, m0);
        __syncthreads();  // all warps done reading W_rel

        // stage W_root hi/lo
        {
            const uint4* srcH = (const uint4*)&g_wsplit[l][1][0][0];
            const uint4* srcL = (const uint4*)&g_wsplit[l][1][1][0];
            for (int idx = tid; idx < H * 16; idx += NTHREADS) {
                uint32_t d = (uint32_t)(idx >> 4) * PITCHB + (uint32_t)(idx & 15) * 16;
                *(uint4*)(sm + OFF_WH + d) = srcH[idx];
                *(uint4*)(sm + OFF_WL + d) = srcL[idx];
            }
        }
        __syncthreads();

        gemm3(sb + OFF_XH, sb + OFF_XL, sb + OFF_WH, sb + OFF_WL, acc, lane, m0);

        // epilogue: bias + elu + split -> X (own 16 rows only; no extra sync needed)
        {
            const float* brl = (const float*)(sm + OFF_BIAS + BO_BREL) + l * H;
            const int r0 = m0 + (lane >> 2);
            const int cb = 2 * (lane & 3);
#pragma unroll
            for (int nt = 0; nt < 16; nt++) {
                const int col = nt * 8 + cb;
                const float b0 = brl[col], b1 = brl[col + 1];
                if (r0 < rows_real)
                    split_store2(sm, (uint32_t)r0 * PITCHB + (uint32_t)col * 2,
                                 elu1(acc[nt][0] + b0), elu1(acc[nt][1] + b1));
                if (r0 + 8 < rows_real)
                    split_store2(sm, (uint32_t)(r0 + 8) * PITCHB + (uint32_t)col * 2,
                                 elu1(acc[nt][2] + b0), elu1(acc[nt][3] + b1));
            }
        }
    }
    __syncthreads();

    // ---- decoder ----
    if (tid < ng * NJN) {
        int g = tid / NJN, j = tid - g * NJN;
        uint32_t roff = (uint32_t)(g * NNODE + 1 + j) * PITCHB;
        const float* wd = (const float*)(sm + OFF_BIAS + BO_WDEC);
        float acc = ((const float*)(sm + OFF_BIAS + BO_BDEC))[0];
        for (int c = 0; c < H; c += 8) {
            uint32_t soff = roff + (uint32_t)c * 2;
            float x[8] = {0.f, 0.f, 0.f, 0.f, 0.f, 0.f, 0.f, 0.f};
            acc8(x, *(const uint4*)(sm + OFF_XH + soff), *(const uint4*)(sm + OFF_XL + soff));
#pragma unroll
            for (int e = 0; e < 8; e++) acc = fmaf(x[e], wd[c + e], acc);
        }
        out[(size_t)(g0 + g) * NJN + j] = acc;
    }
}

extern "C" void kernel_launch(void* const* d_in, const int* in_sizes, int n_in,
                              void* d_out, int out_size)
{
    const float* obs    = (const float*)d_in[0];
    const float* We_b   = (const float*)d_in[1];
    const float* be_b   = (const float*)d_in[2];
    const float* We_j   = (const float*)d_in[3];
    const float* be_j   = (const float*)d_in[4];
    const float* W_rel  = (const float*)d_in[5];
    const float* W_root = (const float*)d_in[6];
    const float* b_rel  = (const float*)d_in[7];
    const float* W_dec  = (const float*)d_in[8];
    const float* b_dec  = (const float*)d_in[9];
    float*       out    = (float*)d_out;

    const int B = in_sizes[0] / OBS_LEN;

    split_weights_kernel<<<(NLAYER * 2 * H * H + 255) / 256, 256>>>(W_rel, W_root);

    const int ntiles = (B + GPT - 1) / GPT;
    cudaFuncSetAttribute(gnn_mma_kernel,
                         cudaFuncAttributeMaxDynamicSharedMemorySize, (int)SMEM_DYN);
    gnn_mma_kernel<<<ntiles, NTHREADS, SMEM_DYN>>>(
        obs, We_b, be_b, We_j, be_j, b_rel, W_dec, b_dec, out, B);
}

// round 6
// speedup vs baseline: 1.5891x; 1.0662x over previous
#include <cuda_runtime.h>
#include <cuda_bf16.h>
#include <stdint.h>
#include <math.h>

namespace {
constexpr int H = 128, NNODE = 13, NJN = 12, OBS_LEN = 141, NLAYER = 3;
constexpr int GPT = 9;               // graphs per CTA -> 117 rows, padded to 128
constexpr int MROWS = 128;
constexpr int NTHREADS = 512;        // 16 warps: 8 M-slices x 2 N-halves
constexpr int BASE_F = 33, JOINT_F = 9;

constexpr uint32_t PITCHB = 272;     // bf16 row: 128 elems + 8 pad (conflict-free ldmatrix)
constexpr uint32_t MATB   = MROWS * PITCHB;        // 34816
constexpr uint32_t PITCHZ = 132;     // Z1 fp32 row pitch (floats)

constexpr uint32_t OFF_XH  = 0;
constexpr uint32_t OFF_XL  = MATB;
constexpr uint32_t OFF_W1H = 2 * MATB;             // W_rel hi   (Z1 fp32 overlays W1H/W1L)
constexpr uint32_t OFF_W1L = 3 * MATB;
constexpr uint32_t OFF_W2H = 4 * MATB;             // W_root hi
constexpr uint32_t OFF_W2L = 5 * MATB;
constexpr uint32_t OFF_Z1  = OFF_W1H;              // 128*132*4 = 67584 <= 69632
constexpr uint32_t OFF_OBS = 6 * MATB;             // 9 x 144 floats
constexpr uint32_t OFF_BIAS = OFF_OBS + GPT * 144 * 4;
constexpr uint32_t BO_BEB = 0, BO_BEJ = 512, BO_BREL = 1024, BO_WDEC = 2560, BO_BDEC = 3072;
constexpr uint32_t OFF_WEB = OFF_W1H;              // encoder weights (pre-layer0 only)
constexpr uint32_t OFF_WEJ = OFF_W1H + 16896;
constexpr uint32_t SMEM_DYN = OFF_BIAS + 3104;     // ~212.1 KB

__device__ __constant__ int8_t NSRC[13] = {4,2,2,1,2,2,1,2,2,1,2,2,1};
__device__ __constant__ int8_t SRCS[13][4] = {
    {1,4,7,10},{0,2,0,0},{1,3,0,0},{2,0,0,0},{0,5,0,0},{4,6,0,0},{5,0,0,0},
    {0,8,0,0},{7,9,0,0},{8,0,0,0},{0,11,0,0},{10,12,0,0},{11,0,0,0}};
__device__ __constant__ int8_t BIDX[11] = {0,1,2,3,4,5,6,7,8,45,46};

// pre-split weights: [layer][rel=0/root=1][hi=0/lo=1][n*128+k]
__device__ __nv_bfloat16 g_wsplit[NLAYER][2][2][H * H];

__device__ __forceinline__ uint32_t smem_u32(const void* p) {
    uint32_t a;
    asm("{ .reg .u64 t; cvta.to.shared.u64 t, %1; cvt.u32.u64 %0, t; }" : "=r"(a) : "l"(p));
    return a;
}
__device__ __forceinline__ float elu1(float v) { return v > 0.f ? v : expm1f(v); }

__device__ __forceinline__ void ldsm4(uint32_t& r0, uint32_t& r1, uint32_t& r2, uint32_t& r3,
                                      uint32_t addr) {
    asm volatile("ldmatrix.sync.aligned.m8n8.x4.shared.b16 {%0,%1,%2,%3}, [%4];"
                 : "=r"(r0), "=r"(r1), "=r"(r2), "=r"(r3) : "r"(addr));
}
__device__ __forceinline__ void mma16816(float* c, const uint32_t* a, uint32_t b0, uint32_t b1) {
    asm volatile(
        "mma.sync.aligned.m16n8k16.row.col.f32.bf16.bf16.f32 "
        "{%0,%1,%2,%3}, {%4,%5,%6,%7}, {%8,%9}, {%0,%1,%2,%3};"
        : "+f"(c[0]), "+f"(c[1]), "+f"(c[2]), "+f"(c[3])
        : "r"(a[0]), "r"(a[1]), "r"(a[2]), "r"(a[3]), "r"(b0), "r"(b1));
}

__device__ __forceinline__ void split_store8(char* sm, uint32_t offH, uint32_t offL,
                                             uint32_t doff, const float* v) {
    uint4 hh, ll;
    uint32_t* ph = (uint32_t*)&hh;
    uint32_t* pl = (uint32_t*)&ll;
#pragma unroll
    for (int k = 0; k < 4; k++) {
        float a = v[2 * k], b = v[2 * k + 1];
        __nv_bfloat16 ha = __float2bfloat16_rn(a), hb = __float2bfloat16_rn(b);
        float ra = a - __bfloat162float(ha), rb = b - __bfloat162float(hb);
        __nv_bfloat16 la = __float2bfloat16_rn(ra), lb = __float2bfloat16_rn(rb);
        ph[k] = (uint32_t)__bfloat16_as_ushort(ha) | ((uint32_t)__bfloat16_as_ushort(hb) << 16);
        pl[k] = (uint32_t)__bfloat16_as_ushort(la) | ((uint32_t)__bfloat16_as_ushort(lb) << 16);
    }
    *(uint4*)(sm + offH + doff) = hh;
    *(uint4*)(sm + offL + doff) = ll;
}
__device__ __forceinline__ void acc8(float* s, uint4 hh, uint4 ll) {
    const uint32_t* ph = (const uint32_t*)&hh;
    const uint32_t* pl = (const uint32_t*)&ll;
#pragma unroll
    for (int k = 0; k < 4; k++) {
        uint32_t wh = ph[k], wl = pl[k];
        s[2 * k]     += __uint_as_float(wh << 16) + __uint_as_float(wl << 16);
        s[2 * k + 1] += __uint_as_float(wh & 0xffff0000u) + __uint_as_float(wl & 0xffff0000u);
    }
}
__device__ __forceinline__ void split_store2(char* sm, uint32_t doff, float a, float b) {
    __nv_bfloat16 ha = __float2bfloat16_rn(a), hb = __float2bfloat16_rn(b);
    float ra = a - __bfloat162float(ha), rb = b - __bfloat162float(hb);
    __nv_bfloat16 la = __float2bfloat16_rn(ra), lb = __float2bfloat16_rn(rb);
    *(uint32_t*)(sm + OFF_XH + doff) =
        (uint32_t)__bfloat16_as_ushort(ha) | ((uint32_t)__bfloat16_as_ushort(hb) << 16);
    *(uint32_t*)(sm + OFF_XL + doff) =
        (uint32_t)__bfloat16_as_ushort(la) | ((uint32_t)__bfloat16_as_ushort(lb) << 16);
}

// 3-term split GEMM over a 16-row x 64-col output slice:
// acc += AH@BH^T + AL@BH^T + AH@BL^T
__device__ __forceinline__ void gemm3(uint32_t aH, uint32_t aL, uint32_t bH, uint32_t bL,
                                      float acc[8][4], int lane, int m0, int npbase) {
    const uint32_t arow = (uint32_t)(m0 + (lane & 15));
    const uint32_t acol = (uint32_t)((lane >> 4) << 4);          // 0 or 16 bytes
    const uint32_t brow = (uint32_t)((lane & 7) + ((lane >> 4) << 3));
    const uint32_t bcol = (uint32_t)(((lane >> 3) & 1) << 4);
    const uint32_t aH0 = aH + arow * PITCHB + acol;
    const uint32_t aL0 = aL + arow * PITCHB + acol;
    const uint32_t bH0 = bH + ((uint32_t)npbase * 16u + brow) * PITCHB + bcol;
    const uint32_t bL0 = bL + ((uint32_t)npbase * 16u + brow) * PITCHB + bcol;
#pragma unroll 2
    for (int k = 0; k < 8; k++) {
        const uint32_t kb = (uint32_t)k * 32u;
        uint32_t ah[4], al[4];
        ldsm4(ah[0], ah[1], ah[2], ah[3], aH0 + kb);
        ldsm4(al[0], al[1], al[2], al[3], aL0 + kb);
#pragma unroll
        for (int np = 0; np < 4; np++) {
            const uint32_t noff = (uint32_t)np * (16u * PITCHB) + kb;
            uint32_t h0, h1, h2, h3, l0, l1, l2, l3;
            ldsm4(h0, h1, h2, h3, bH0 + noff);
            ldsm4(l0, l1, l2, l3, bL0 + noff);
            mma16816(acc[2 * np],     ah, h0, h1);
            mma16816(acc[2 * np + 1], ah, h2, h3);
            mma16816(acc[2 * np],     al, h0, h1);
            mma16816(acc[2 * np + 1], al, h2, h3);
            mma16816(acc[2 * np],     ah, l0, l1);
            mma16816(acc[2 * np + 1], ah, l2, l3);
        }
    }
}
} // namespace

__global__ void split_weights_kernel(const float* __restrict__ W_rel,
                                     const float* __restrict__ W_root) {
    int i = blockIdx.x * blockDim.x + threadIdx.x;
    if (i >= NLAYER * 2 * H * H) return;
    int l = i / (2 * H * H);
    int r = i % (2 * H * H);
    int g = r / (H * H);
    int e = r % (H * H);
    float w = (g == 0) ? W_rel[l * H * H + e] : W_root[l * H * H + e];
    __nv_bfloat16 hi = __float2bfloat16_rn(w);
    float rem = w - __bfloat162float(hi);
    g_wsplit[l][g][0][e] = hi;
    g_wsplit[l][g][1][e] = __float2bfloat16_rn(rem);
}

__global__ __launch_bounds__(NTHREADS, 1) void gnn_mma_kernel(
    const float* __restrict__ obs,
    const float* __restrict__ We_b, const float* __restrict__ be_b,
    const float* __restrict__ We_j, const float* __restrict__ be_j,
    const float* __restrict__ b_rel,
    const float* __restrict__ W_dec, const float* __restrict__ b_dec,
    float* __restrict__ out, int B)
{
    extern __shared__ char sm[];
    const uint32_t sb = smem_u32(sm);
    const int tid = threadIdx.x, lane = tid & 31, wid = tid >> 5;
    const int m0 = (wid >> 1) * 16;          // 16-row slice
    const int nh = wid & 1;                  // 64-col half
    const int npbase = nh * 4;
    const int g0 = blockIdx.x * GPT;
    const int ng = min(GPT, B - g0);
    const int rows_real = ng * NNODE;

    // ---- stage biases / encoder weights (transposed) / obs ----
    if (tid < H) {
        ((float*)(sm + OFF_BIAS + BO_BEB))[tid]  = be_b[tid];
        ((float*)(sm + OFF_BIAS + BO_BEJ))[tid]  = be_j[tid];
        ((float*)(sm + OFF_BIAS + BO_WDEC))[tid] = W_dec[tid];
    }
    for (int i = tid; i < NLAYER * H; i += NTHREADS)
        ((float*)(sm + OFF_BIAS + BO_BREL))[i] = b_rel[i];
    if (tid == 0) ((float*)(sm + OFF_BIAS + BO_BDEC))[0] = b_dec[0];
    for (int i = tid; i < H * BASE_F; i += NTHREADS) {
        int h = i / BASE_F, f = i - h * BASE_F;
        ((float*)(sm + OFF_WEB))[f * H + h] = We_b[i];
    }
    for (int i = tid; i < H * JOINT_F; i += NTHREADS) {
        int h = i / JOINT_F, f = i - h * JOINT_F;
        ((float*)(sm + OFF_WEJ))[f * H + h] = We_j[i];
    }
    for (int i = tid; i < ng * OBS_LEN; i += NTHREADS) {
        int g = i / OBS_LEN, k = i - g * OBS_LEN;
        ((float*)(sm + OFF_OBS))[g * 144 + k] = obs[(size_t)(g0 + g) * OBS_LEN + k];
    }
    __syncthreads();

    // ---- encoder: X hi/lo (zero the pad rows) ----
    for (int idx = tid; idx < MROWS * 16; idx += NTHREADS) {
        int row = idx >> 4, c0 = (idx & 15) << 3;
        uint32_t doff = (uint32_t)row * PITCHB + (uint32_t)c0 * 2;
        if (row >= rows_real) {
            uint4 z = make_uint4(0, 0, 0, 0);
            *(uint4*)(sm + OFF_XH + doff) = z;
            *(uint4*)(sm + OFF_XL + doff) = z;
            continue;
        }
        int g = row / NNODE, n = row - g * NNODE;
        const float* ob = (const float*)(sm + OFF_OBS) + g * 144;
        float acc[8];
        if (n == 0) {
            const float* be = (const float*)(sm + OFF_BIAS + BO_BEB);
#pragma unroll
            for (int e = 0; e < 8; e++) acc[e] = be[c0 + e];
#pragma unroll
            for (int t = 0; t < 3; t++)
#pragma unroll
                for (int i2 = 0; i2 < 11; i2++) {
                    float ft = ob[t * 47 + BIDX[i2]];
                    const float* w = (const float*)(sm + OFF_WEB) + (t * 11 + i2) * H + c0;
#pragma unroll
                    for (int e = 0; e < 8; e++) acc[e] = fmaf(ft, w[e], acc[e]);
                }
        } else {
            int j = n - 1;
            const float* be = (const float*)(sm + OFF_BIAS + BO_BEJ);
#pragma unroll
            for (int e = 0; e < 8; e++) acc[e] = be[c0 + e];
#pragma unroll
            for (int f = 0; f < 9; f++) {
                float ft = ob[(f / 3) * 47 + 9 + (f % 3) * 12 + j];
                const float* w = (const float*)(sm + OFF_WEJ) + f * H + c0;
#pragma unroll
                for (int e = 0; e < 8; e++) acc[e] = fmaf(ft, w[e], acc[e]);
            }
        }
#pragma unroll
        for (int e = 0; e < 8; e++) acc[e] = elu1(acc[e]);
        split_store8(sm, OFF_XH, OFF_XL, doff, acc);
    }

    // ---- layers:  x' = elu( S·(X@Wrel^T) + X@Wroot^T + b ) ----
    for (int l = 0; l < NLAYER; l++) {
        __syncthreads();  // X ready; W1/W2 areas free of readers (incl. encoder wts / Z1)

        // stage Wrel -> W1, Wroot -> W2 (hi/lo)
        {
            const uint4* relH = (const uint4*)&g_wsplit[l][0][0][0];
            const uint4* relL = (const uint4*)&g_wsplit[l][0][1][0];
            const uint4* rooH = (const uint4*)&g_wsplit[l][1][0][0];
            const uint4* rooL = (const uint4*)&g_wsplit[l][1][1][0];
            for (int idx = tid; idx < H * 16; idx += NTHREADS) {
                uint32_t d = (uint32_t)(idx >> 4) * PITCHB + (uint32_t)(idx & 15) * 16;
                *(uint4*)(sm + OFF_W1H + d) = relH[idx];
                *(uint4*)(sm + OFF_W1L + d) = relL[idx];
                *(uint4*)(sm + OFF_W2H + d) = rooH[idx];
                *(uint4*)(sm + OFF_W2L + d) = rooL[idx];
            }
        }
        __syncthreads();

        float acc[8][4];
#pragma unroll
        for (int nt = 0; nt < 8; nt++)
#pragma unroll
            for (int e = 0; e < 4; e++) acc[nt][e] = 0.f;

        // Z1 = X @ Wrel^T
        gemm3(sb + OFF_XH, sb + OFF_XL, sb + OFF_W1H, sb + OFF_W1L, acc, lane, m0, npbase);
        __syncthreads();  // all warps done reading W1 -> safe to overlay Z1

        // spill Z1 (fp32) into the W1 area
        {
            float* z1 = (float*)(sm + OFF_Z1);
            const int r0 = m0 + (lane >> 2);
            const int cb = nh * 64 + 2 * (lane & 3);
#pragma unroll
            for (int nt = 0; nt < 8; nt++) {
                const int col = cb + nt * 8;
                *(float2*)&z1[(uint32_t)r0 * PITCHZ + col]       = make_float2(acc[nt][0], acc[nt][1]);
                *(float2*)&z1[(uint32_t)(r0 + 8) * PITCHZ + col] = make_float2(acc[nt][2], acc[nt][3]);
            }
        }

        // Z2 = X @ Wroot^T  (reuse acc; W2 untouched, Z1 store is to disjoint area)
#pragma unroll
        for (int nt = 0; nt < 8; nt++)
#pragma unroll
            for (int e = 0; e < 4; e++) acc[nt][e] = 0.f;
        gemm3(sb + OFF_XH, sb + OFF_XL, sb + OFF_W2H, sb + OFF_W2L, acc, lane, m0, npbase);
        __syncthreads();  // Z1 complete everywhere; gemm2 done reading X

        // fused epilogue: x' = elu( S·Z1 + Z2 + b ), split-store into X
        {
            const float* z1  = (const float*)(sm + OFF_Z1);
            const float* brl = (const float*)(sm + OFF_BIAS + BO_BREL) + l * H;
            const int r0 = m0 + (lane >> 2);
            const int cb = nh * 64 + 2 * (lane & 3);
#pragma unroll
            for (int half = 0; half < 2; half++) {
                const int r = r0 + half * 8;
                if (r >= rows_real) continue;
                const int g  = r / NNODE;
                const int n  = r - g * NNODE;
                const int gb = g * NNODE;
                const int cnt = NSRC[n];
#pragma unroll
                for (int nt = 0; nt < 8; nt++) {
                    const int col = cb + nt * 8;
                    float v0 = acc[nt][2 * half]     + brl[col];
                    float v1 = acc[nt][2 * half + 1] + brl[col + 1];
                    for (int k2 = 0; k2 < cnt; k2++) {
                        const float* zr = &z1[(uint32_t)(gb + SRCS[n][k2]) * PITCHZ + col];
                        v0 += zr[0];
                        v1 += zr[1];
                    }
                    split_store2(sm, (uint32_t)r * PITCHB + (uint32_t)col * 2,
                                 elu1(v0), elu1(v1));
                }
            }
        }
    }
    __syncthreads();

    // ---- decoder ----
    if (tid < ng * NJN) {
        int g = tid / NJN, j = tid - g * NJN;
        uint32_t roff = (uint32_t)(g * NNODE + 1 + j) * PITCHB;
        const float* wd = (const float*)(sm + OFF_BIAS + BO_WDEC);
        float acc = ((const float*)(sm + OFF_BIAS + BO_BDEC))[0];
        for (int c = 0; c < H; c += 8) {
            uint32_t soff = roff + (uint32_t)c * 2;
            float x[8] = {0.f, 0.f, 0.f, 0.f, 0.f, 0.f, 0.f, 0.f};
            acc8(x, *(const uint4*)(sm + OFF_XH + soff), *(const uint4*)(sm + OFF_XL + soff));
#pragma unroll
            for (int e = 0; e < 8; e++) acc = fmaf(x[e], wd[c + e], acc);
        }
        out[(size_t)(g0 + g) * NJN + j] = acc;
    }
}

extern "C" void kernel_launch(void* const* d_in, const int* in_sizes, int n_in,
                              void* d_out, int out_size)
{
    const float* obs    = (const float*)d_in[0];
    const float* We_b   = (const float*)d_in[1];
    const float* be_b   = (const float*)d_in[2];
    const float* We_j   = (const float*)d_in[3];
    const float* be_j   = (const float*)d_in[4];
    const float* W_rel  = (const float*)d_in[5];
    const float* W_root = (const float*)d_in[6];
    const float* b_rel  = (const float*)d_in[7];
    const float* W_dec  = (const float*)d_in[8];
    const float* b_dec  = (const float*)d_in[9];
    float*       out    = (float*)d_out;

    const int B = in_sizes[0] / OBS_LEN;

    split_weights_kernel<<<(NLAYER * 2 * H * H + 255) / 256, 256>>>(W_rel, W_root);

    const int ntiles = (B + GPT - 1) / GPT;
    cudaFuncSetAttribute(gnn_mma_kernel,
                         cudaFuncAttributeMaxDynamicSharedMemorySize, (int)SMEM_DYN);
    gnn_mma_kernel<<<ntiles, NTHREADS, SMEM_DYN>>>(
        obs, We_b, be_b, We_j, be_j, b_rel, W_dec, b_dec, out, B);
}

// round 7
// speedup vs baseline: 1.6367x; 1.0300x over previous
#include <cuda_runtime.h>
#include <cuda_bf16.h>
#include <stdint.h>
#include <math.h>

namespace {
constexpr int H = 128, NNODE = 13, NJN = 12, OBS_LEN = 141, NLAYER = 3;
constexpr int GPT = 9;               // graphs per CTA -> 117 rows, padded to 128
constexpr int MROWS = 128;
constexpr int NTHREADS = 512;        // 16 warps: 4 M-slices x 4 N-quarters
constexpr int BASE_F = 33, JOINT_F = 9;

constexpr uint32_t PITCHB = 272;     // bf16 row: 128 elems + 8 pad (conflict-free ldmatrix)
constexpr uint32_t MATB   = MROWS * PITCHB;        // 34816
constexpr uint32_t PITCHZ = 132;     // Z1 fp32 row pitch (floats)

constexpr uint32_t OFF_XH  = 0;
constexpr uint32_t OFF_XL  = MATB;
constexpr uint32_t OFF_W1H = 2 * MATB;             // W_rel hi   (Z1 fp32 overlays W1H+W1L)
constexpr uint32_t OFF_W1L = 3 * MATB;
constexpr uint32_t OFF_W2H = 4 * MATB;             // W_root hi
constexpr uint32_t OFF_W2L = 5 * MATB;
constexpr uint32_t OFF_Z1  = OFF_W1H;              // 128*132*4 = 67584 <= 2*34816
constexpr uint32_t OFF_OBS = 6 * MATB;             // 9 x 144 floats
constexpr uint32_t OFF_BIAS = OFF_OBS + GPT * 144 * 4;
constexpr uint32_t BO_BEB = 0, BO_BEJ = 512, BO_BREL = 1024, BO_WDEC = 2560, BO_BDEC = 3072;
constexpr uint32_t OFF_WEB = OFF_W1H;              // encoder weights (pre-layer0 only)
constexpr uint32_t OFF_WEJ = OFF_W1H + 16896;
constexpr uint32_t SMEM_DYN = OFF_BIAS + 3104;     // ~212.1 KB

__device__ __constant__ int8_t NSRC[13] = {4,2,2,1,2,2,1,2,2,1,2,2,1};
__device__ __constant__ int8_t SRCS[13][4] = {
    {1,4,7,10},{0,2,0,0},{1,3,0,0},{2,0,0,0},{0,5,0,0},{4,6,0,0},{5,0,0,0},
    {0,8,0,0},{7,9,0,0},{8,0,0,0},{0,11,0,0},{10,12,0,0},{11,0,0,0}};
__device__ __constant__ int8_t BIDX[11] = {0,1,2,3,4,5,6,7,8,45,46};

// pre-split weights: [layer][rel=0/root=1][hi=0/lo=1][n*128+k]
__device__ __nv_bfloat16 g_wsplit[NLAYER][2][2][H * H];

__device__ __forceinline__ uint32_t smem_u32(const void* p) {
    uint32_t a;
    asm("{ .reg .u64 t; cvta.to.shared.u64 t, %1; cvt.u32.u64 %0, t; }" : "=r"(a) : "l"(p));
    return a;
}
__device__ __forceinline__ float elu1(float v) { return v > 0.f ? v : expm1f(v); }

__device__ __forceinline__ void ldsm4(uint32_t& r0, uint32_t& r1, uint32_t& r2, uint32_t& r3,
                                      uint32_t addr) {
    asm volatile("ldmatrix.sync.aligned.m8n8.x4.shared.b16 {%0,%1,%2,%3}, [%4];"
                 : "=r"(r0), "=r"(r1), "=r"(r2), "=r"(r3) : "r"(addr));
}
__device__ __forceinline__ void mma16816(float* c, const uint32_t* a, uint32_t b0, uint32_t b1) {
    asm volatile(
        "mma.sync.aligned.m16n8k16.row.col.f32.bf16.bf16.f32 "
        "{%0,%1,%2,%3}, {%4,%5,%6,%7}, {%8,%9}, {%0,%1,%2,%3};"
        : "+f"(c[0]), "+f"(c[1]), "+f"(c[2]), "+f"(c[3])
        : "r"(a[0]), "r"(a[1]), "r"(a[2]), "r"(a[3]), "r"(b0), "r"(b1));
}

__device__ __forceinline__ void split_store8(char* sm, uint32_t offH, uint32_t offL,
                                             uint32_t doff, const float* v) {
    uint4 hh, ll;
    uint32_t* ph = (uint32_t*)&hh;
    uint32_t* pl = (uint32_t*)&ll;
#pragma unroll
    for (int k = 0; k < 4; k++) {
        float a = v[2 * k], b = v[2 * k + 1];
        __nv_bfloat16 ha = __float2bfloat16_rn(a), hb = __float2bfloat16_rn(b);
        float ra = a - __bfloat162float(ha), rb = b - __bfloat162float(hb);
        __nv_bfloat16 la = __float2bfloat16_rn(ra), lb = __float2bfloat16_rn(rb);
        ph[k] = (uint32_t)__bfloat16_as_ushort(ha) | ((uint32_t)__bfloat16_as_ushort(hb) << 16);
        pl[k] = (uint32_t)__bfloat16_as_ushort(la) | ((uint32_t)__bfloat16_as_ushort(lb) << 16);
    }
    *(uint4*)(sm + offH + doff) = hh;
    *(uint4*)(sm + offL + doff) = ll;
}
__device__ __forceinline__ void acc8(float* s, uint4 hh, uint4 ll) {
    const uint32_t* ph = (const uint32_t*)&hh;
    const uint32_t* pl = (const uint32_t*)&ll;
#pragma unroll
    for (int k = 0; k < 4; k++) {
        uint32_t wh = ph[k], wl = pl[k];
        s[2 * k]     += __uint_as_float(wh << 16) + __uint_as_float(wl << 16);
        s[2 * k + 1] += __uint_as_float(wh & 0xffff0000u) + __uint_as_float(wl & 0xffff0000u);
    }
}
__device__ __forceinline__ void split_store2(char* sm, uint32_t doff, float a, float b) {
    __nv_bfloat16 ha = __float2bfloat16_rn(a), hb = __float2bfloat16_rn(b);
    float ra = a - __bfloat162float(ha), rb = b - __bfloat162float(hb);
    __nv_bfloat16 la = __float2bfloat16_rn(ra), lb = __float2bfloat16_rn(rb);
    *(uint32_t*)(sm + OFF_XH + doff) =
        (uint32_t)__bfloat16_as_ushort(ha) | ((uint32_t)__bfloat16_as_ushort(hb) << 16);
    *(uint32_t*)(sm + OFF_XL + doff) =
        (uint32_t)__bfloat16_as_ushort(la) | ((uint32_t)__bfloat16_as_ushort(lb) << 16);
}
} // namespace

__global__ void split_weights_kernel(const float* __restrict__ W_rel,
                                     const float* __restrict__ W_root) {
    int i = blockIdx.x * blockDim.x + threadIdx.x;
    if (i >= NLAYER * 2 * H * H) return;
    int l = i / (2 * H * H);
    int r = i % (2 * H * H);
    int g = r / (H * H);
    int e = r % (H * H);
    float w = (g == 0) ? W_rel[l * H * H + e] : W_root[l * H * H + e];
    __nv_bfloat16 hi = __float2bfloat16_rn(w);
    float rem = w - __bfloat162float(hi);
    g_wsplit[l][g][0][e] = hi;
    g_wsplit[l][g][1][e] = __float2bfloat16_rn(rem);
}

__global__ __launch_bounds__(NTHREADS, 1) void gnn_mma_kernel(
    const float* __restrict__ obs,
    const float* __restrict__ We_b, const float* __restrict__ be_b,
    const float* __restrict__ We_j, const float* __restrict__ be_j,
    const float* __restrict__ b_rel,
    const float* __restrict__ W_dec, const float* __restrict__ b_dec,
    float* __restrict__ out, int B)
{
    extern __shared__ char sm[];
    const uint32_t sb = smem_u32(sm);
    const int tid = threadIdx.x, lane = tid & 31, wid = tid >> 5;
    const int m0 = (wid >> 2) * 32;          // 32-row slice
    const int n0 = (wid & 3) * 32;           // 32-col quarter
    const int g0 = blockIdx.x * GPT;
    const int ng = min(GPT, B - g0);
    const int rows_real = ng * NNODE;

    // ---- stage biases / encoder weights (transposed) / obs ----
    if (tid < H) {
        ((float*)(sm + OFF_BIAS + BO_BEB))[tid]  = be_b[tid];
        ((float*)(sm + OFF_BIAS + BO_BEJ))[tid]  = be_j[tid];
        ((float*)(sm + OFF_BIAS + BO_WDEC))[tid] = W_dec[tid];
    }
    for (int i = tid; i < NLAYER * H; i += NTHREADS)
        ((float*)(sm + OFF_BIAS + BO_BREL))[i] = b_rel[i];
    if (tid == 0) ((float*)(sm + OFF_BIAS + BO_BDEC))[0] = b_dec[0];
    for (int i = tid; i < H * BASE_F; i += NTHREADS) {
        int h = i / BASE_F, f = i - h * BASE_F;
        ((float*)(sm + OFF_WEB))[f * H + h] = We_b[i];
    }
    for (int i = tid; i < H * JOINT_F; i += NTHREADS) {
        int h = i / JOINT_F, f = i - h * JOINT_F;
        ((float*)(sm + OFF_WEJ))[f * H + h] = We_j[i];
    }
    for (int i = tid; i < ng * OBS_LEN; i += NTHREADS) {
        int g = i / OBS_LEN, k = i - g * OBS_LEN;
        ((float*)(sm + OFF_OBS))[g * 144 + k] = obs[(size_t)(g0 + g) * OBS_LEN + k];
    }
    __syncthreads();

    // ---- encoder: X hi/lo (zero the pad rows) ----
    for (int idx = tid; idx < MROWS * 16; idx += NTHREADS) {
        int row = idx >> 4, c0 = (idx & 15) << 3;
        uint32_t doff = (uint32_t)row * PITCHB + (uint32_t)c0 * 2;
        if (row >= rows_real) {
            uint4 z = make_uint4(0, 0, 0, 0);
            *(uint4*)(sm + OFF_XH + doff) = z;
            *(uint4*)(sm + OFF_XL + doff) = z;
            continue;
        }
        int g = row / NNODE, n = row - g * NNODE;
        const float* ob = (const float*)(sm + OFF_OBS) + g * 144;
        float acc[8];
        if (n == 0) {
            const float* be = (const float*)(sm + OFF_BIAS + BO_BEB);
#pragma unroll
            for (int e = 0; e < 8; e++) acc[e] = be[c0 + e];
#pragma unroll
            for (int t = 0; t < 3; t++)
#pragma unroll
                for (int i2 = 0; i2 < 11; i2++) {
                    float ft = ob[t * 47 + BIDX[i2]];
                    const float* w = (const float*)(sm + OFF_WEB) + (t * 11 + i2) * H + c0;
#pragma unroll
                    for (int e = 0; e < 8; e++) acc[e] = fmaf(ft, w[e], acc[e]);
                }
        } else {
            int j = n - 1;
            const float* be = (const float*)(sm + OFF_BIAS + BO_BEJ);
#pragma unroll
            for (int e = 0; e < 8; e++) acc[e] = be[c0 + e];
#pragma unroll
            for (int f = 0; f < 9; f++) {
                float ft = ob[(f / 3) * 47 + 9 + (f % 3) * 12 + j];
                const float* w = (const float*)(sm + OFF_WEJ) + f * H + c0;
#pragma unroll
                for (int e = 0; e < 8; e++) acc[e] = fmaf(ft, w[e], acc[e]);
            }
        }
#pragma unroll
        for (int e = 0; e < 8; e++) acc[e] = elu1(acc[e]);
        split_store8(sm, OFF_XH, OFF_XL, doff, acc);
    }

    // ---- layers:  x' = elu( S·(X@Wrel^T) + X@Wroot^T + b ) ----
    for (int l = 0; l < NLAYER; l++) {
        __syncthreads();  // X ready; W areas free (incl. encoder wts / Z1)

        // stage Wrel -> W1, Wroot -> W2 (hi/lo)
        {
            const uint4* relH = (const uint4*)&g_wsplit[l][0][0][0];
            const uint4* relL = (const uint4*)&g_wsplit[l][0][1][0];
            const uint4* rooH = (const uint4*)&g_wsplit[l][1][0][0];
            const uint4* rooL = (const uint4*)&g_wsplit[l][1][1][0];
            for (int idx = tid; idx < H * 16; idx += NTHREADS) {
                uint32_t d = (uint32_t)(idx >> 4) * PITCHB + (uint32_t)(idx & 15) * 16;
                *(uint4*)(sm + OFF_W1H + d) = relH[idx];
                *(uint4*)(sm + OFF_W1L + d) = relL[idx];
                *(uint4*)(sm + OFF_W2H + d) = rooH[idx];
                *(uint4*)(sm + OFF_W2L + d) = rooL[idx];
            }
        }
        __syncthreads();

        // merged dual 3-term GEMM over 32Mx32N tile:
        //   acc1 += X@W1^T terms, acc2 += X@W2^T terms, A fragments shared
        float acc1[2][2][2][4], acc2[2][2][2][4];   // [mt][nt][h][4]
#pragma unroll
        for (int mt = 0; mt < 2; mt++)
#pragma unroll
            for (int nt = 0; nt < 2; nt++)
#pragma unroll
                for (int hh = 0; hh < 2; hh++)
#pragma unroll
                    for (int e = 0; e < 4; e++) { acc1[mt][nt][hh][e] = 0.f; acc2[mt][nt][hh][e] = 0.f; }
        {
            const uint32_t arow = (uint32_t)(lane & 15);
            const uint32_t acol = (uint32_t)((lane >> 4) << 4);
            const uint32_t brow = (uint32_t)((lane & 7) + ((lane >> 4) << 3));
            const uint32_t bcol = (uint32_t)(((lane >> 3) & 1) << 4);
            const uint32_t aH0 = sb + OFF_XH + ((uint32_t)m0 + arow) * PITCHB + acol;
            const uint32_t aL0 = sb + OFF_XL + ((uint32_t)m0 + arow) * PITCHB + acol;
            const uint32_t bro = ((uint32_t)n0 + brow) * PITCHB + bcol;
            const uint32_t b1H0 = sb + OFF_W1H + bro;
            const uint32_t b1L0 = sb + OFF_W1L + bro;
            const uint32_t b2H0 = sb + OFF_W2H + bro;
            const uint32_t b2L0 = sb + OFF_W2L + bro;
#pragma unroll 2
            for (int k = 0; k < 8; k++) {
                const uint32_t kb = (uint32_t)k * 32u;
                uint32_t ah[2][4], al[2][4];
#pragma unroll
                for (int mt = 0; mt < 2; mt++) {
                    const uint32_t mo = (uint32_t)mt * (16u * PITCHB) + kb;
                    ldsm4(ah[mt][0], ah[mt][1], ah[mt][2], ah[mt][3], aH0 + mo);
                    ldsm4(al[mt][0], al[mt][1], al[mt][2], al[mt][3], aL0 + mo);
                }
#pragma unroll
                for (int nt = 0; nt < 2; nt++) {
                    const uint32_t noff = (uint32_t)nt * (16u * PITCHB) + kb;
                    uint32_t h0, h1, h2, h3, l0, l1, l2, l3;
                    // W1
                    ldsm4(h0, h1, h2, h3, b1H0 + noff);
                    ldsm4(l0, l1, l2, l3, b1L0 + noff);
#pragma unroll
                    for (int mt = 0; mt < 2; mt++) {
                        mma16816(acc1[mt][nt][0], ah[mt], h0, h1);
                        mma16816(acc1[mt][nt][1], ah[mt], h2, h3);
                        mma16816(acc1[mt][nt][0], al[mt], h0, h1);
                        mma16816(acc1[mt][nt][1], al[mt], h2, h3);
                        mma16816(acc1[mt][nt][0], ah[mt], l0, l1);
                        mma16816(acc1[mt][nt][1], ah[mt], l2, l3);
                    }
                    // W2
                    ldsm4(h0, h1, h2, h3, b2H0 + noff);
                    ldsm4(l0, l1, l2, l3, b2L0 + noff);
#pragma unroll
                    for (int mt = 0; mt < 2; mt++) {
                        mma16816(acc2[mt][nt][0], ah[mt], h0, h1);
                        mma16816(acc2[mt][nt][1], ah[mt], h2, h3);
                        mma16816(acc2[mt][nt][0], al[mt], h0, h1);
                        mma16816(acc2[mt][nt][1], al[mt], h2, h3);
                        mma16816(acc2[mt][nt][0], ah[mt], l0, l1);
                        mma16816(acc2[mt][nt][1], ah[mt], l2, l3);
                    }
                }
            }
        }
        __syncthreads();  // all warps done reading W1/W2 -> safe to overlay Z1

        // spill Z1 (fp32) into the W1 area
        {
            float* z1 = (float*)(sm + OFF_Z1);
            const int r0 = m0 + (lane >> 2);
            const int cb = n0 + 2 * (lane & 3);
#pragma unroll
            for (int mt = 0; mt < 2; mt++)
#pragma unroll
                for (int nt = 0; nt < 2; nt++)
#pragma unroll
                    for (int hh = 0; hh < 2; hh++) {
                        const int col = cb + nt * 16 + hh * 8;
                        const int r = r0 + mt * 16;
                        *(float2*)&z1[(uint32_t)r * PITCHZ + col] =
                            make_float2(acc1[mt][nt][hh][0], acc1[mt][nt][hh][1]);
                        *(float2*)&z1[(uint32_t)(r + 8) * PITCHZ + col] =
                            make_float2(acc1[mt][nt][hh][2], acc1[mt][nt][hh][3]);
                    }
        }
        __syncthreads();  // Z1 complete everywhere

        // fused epilogue: x' = elu( S·Z1 + Z2 + b ), split-store into X
        {
            const float* z1  = (const float*)(sm + OFF_Z1);
            const float* brl = (const float*)(sm + OFF_BIAS + BO_BREL) + l * H;
            const int r0 = m0 + (lane >> 2);
            const int cb = n0 + 2 * (lane & 3);
#pragma unroll
            for (int mt = 0; mt < 2; mt++)
#pragma unroll
                for (int half = 0; half < 2; half++) {
                    const int r = r0 + mt * 16 + half * 8;
                    if (r >= rows_real) continue;
                    const int g  = r / NNODE;
                    const int n  = r - g * NNODE;
                    const int gb = g * NNODE;
                    const int cnt = NSRC[n];
#pragma unroll
                    for (int nt = 0; nt < 2; nt++)
#pragma unroll
                        for (int hh = 0; hh < 2; hh++) {
                            const int col = cb + nt * 16 + hh * 8;
                            float v0 = acc2[mt][nt][hh][2 * half]     + brl[col];
                            float v1 = acc2[mt][nt][hh][2 * half + 1] + brl[col + 1];
                            for (int k2 = 0; k2 < cnt; k2++) {
                                const float* zr = &z1[(uint32_t)(gb + SRCS[n][k2]) * PITCHZ + col];
                                v0 += zr[0];
                                v1 += zr[1];
                            }
                            split_store2(sm, (uint32_t)r * PITCHB + (uint32_t)col * 2,
                                         elu1(v0), elu1(v1));
                        }
                }
        }
    }
    __syncthreads();

    // ---- decoder ----
    if (tid < ng * NJN) {
        int g = tid / NJN, j = tid - g * NJN;
        uint32_t roff = (uint32_t)(g * NNODE + 1 + j) * PITCHB;
        const float* wd = (const float*)(sm + OFF_BIAS + BO_WDEC);
        float acc = ((const float*)(sm + OFF_BIAS + BO_BDEC))[0];
        for (int c = 0; c < H; c += 8) {
            uint32_t soff = roff + (uint32_t)c * 2;
            float x[8] = {0.f, 0.f, 0.f, 0.f, 0.f, 0.f, 0.f, 0.f};
            acc8(x, *(const uint4*)(sm + OFF_XH + soff), *(const uint4*)(sm + OFF_XL + soff));
#pragma unroll
            for (int e = 0; e < 8; e++) acc = fmaf(x[e], wd[c + e], acc);
        }
        out[(size_t)(g0 + g) * NJN + j] = acc;
    }
}

extern "C" void kernel_launch(void* const* d_in, const int* in_sizes, int n_in,
                              void* d_out, int out_size)
{
    const float* obs    = (const float*)d_in[0];
    const float* We_b   = (const float*)d_in[1];
    const float* be_b   = (const float*)d_in[2];
    const float* We_j   = (const float*)d_in[3];
    const float* be_j   = (const float*)d_in[4];
    const float* W_rel  = (const float*)d_in[5];
    const float* W_root = (const float*)d_in[6];
    const float* b_rel  = (const float*)d_in[7];
    const float* W_dec  = (const float*)d_in[8];
    const float* b_dec  = (const float*)d_in[9];
    float*       out    = (float*)d_out;

    const int B = in_sizes[0] / OBS_LEN;

    split_weights_kernel<<<(NLAYER * 2 * H * H + 255) / 256, 256>>>(W_rel, W_root);

    const int ntiles = (B + GPT - 1) / GPT;
    cudaFuncSetAttribute(gnn_mma_kernel,
                         cudaFuncAttributeMaxDynamicSharedMemorySize, (int)SMEM_DYN);
    gnn_mma_kernel<<<ntiles, NTHREADS, SMEM_DYN>>>(
        obs, We_b, be_b, We_j, be_j, b_rel, W_dec, b_dec, out, B);
}

// round 8
// speedup vs baseline: 1.8234x; 1.1140x over previous
#include <cuda_runtime.h>
#include <cuda_bf16.h>
#include <stdint.h>
#include <math.h>

namespace {
constexpr int H = 128, NNODE = 13, NJN = 12, OBS_LEN = 141, NLAYER = 3;
constexpr int GPT = 9;               // graphs per CTA -> 117 rows, padded to 128
constexpr int MROWS = 128;
constexpr int NTHREADS = 1024;       // 32 warps: 8 M-slices x 4 N-quarters
constexpr int BASE_F = 33, JOINT_F = 9;

constexpr uint32_t PITCHB = 272;     // bf16 row: 128 elems + 8 pad (conflict-free ldmatrix)
constexpr uint32_t MATB   = MROWS * PITCHB;        // 34816
constexpr uint32_t PITCHZ = 132;     // Z1 fp32 row pitch (floats)

constexpr uint32_t OFF_XH  = 0;
constexpr uint32_t OFF_XL  = MATB;
constexpr uint32_t OFF_W1H = 2 * MATB;             // W_rel hi   (Z1 fp32 overlays W1H+W1L)
constexpr uint32_t OFF_W1L = 3 * MATB;
constexpr uint32_t OFF_W2H = 4 * MATB;             // W_root hi
constexpr uint32_t OFF_W2L = 5 * MATB;
constexpr uint32_t OFF_Z1  = OFF_W1H;              // 128*132*4 = 67584 <= 2*34816
constexpr uint32_t OFF_OBS = 6 * MATB;             // 9 x 144 floats
constexpr uint32_t OFF_BIAS = OFF_OBS + GPT * 144 * 4;
constexpr uint32_t BO_BEB = 0, BO_BEJ = 512, BO_BREL = 1024, BO_WDEC = 2560, BO_BDEC = 3072;
constexpr uint32_t OFF_WEB = OFF_W1H;              // encoder weights (pre-layer0 only)
constexpr uint32_t OFF_WEJ = OFF_W1H + 16896;
constexpr uint32_t SMEM_DYN = OFF_BIAS + 3104;     // ~212.1 KB

__device__ __constant__ int8_t NSRC[13] = {4,2,2,1,2,2,1,2,2,1,2,2,1};
__device__ __constant__ int8_t SRCS[13][4] = {
    {1,4,7,10},{0,2,0,0},{1,3,0,0},{2,0,0,0},{0,5,0,0},{4,6,0,0},{5,0,0,0},
    {0,8,0,0},{7,9,0,0},{8,0,0,0},{0,11,0,0},{10,12,0,0},{11,0,0,0}};
__device__ __constant__ int8_t BIDX[11] = {0,1,2,3,4,5,6,7,8,45,46};

// pre-split weights: [layer][rel=0/root=1][hi=0/lo=1][n*128+k]
__device__ __nv_bfloat16 g_wsplit[NLAYER][2][2][H * H];

__device__ __forceinline__ uint32_t smem_u32(const void* p) {
    uint32_t a;
    asm("{ .reg .u64 t; cvta.to.shared.u64 t, %1; cvt.u32.u64 %0, t; }" : "=r"(a) : "l"(p));
    return a;
}
__device__ __forceinline__ float elu1(float v) { return v > 0.f ? v : expm1f(v); }

__device__ __forceinline__ void ldsm4(uint32_t& r0, uint32_t& r1, uint32_t& r2, uint32_t& r3,
                                      uint32_t addr) {
    asm volatile("ldmatrix.sync.aligned.m8n8.x4.shared.b16 {%0,%1,%2,%3}, [%4];"
                 : "=r"(r0), "=r"(r1), "=r"(r2), "=r"(r3) : "r"(addr));
}
__device__ __forceinline__ void mma16816(float* c, const uint32_t* a, uint32_t b0, uint32_t b1) {
    asm volatile(
        "mma.sync.aligned.m16n8k16.row.col.f32.bf16.bf16.f32 "
        "{%0,%1,%2,%3}, {%4,%5,%6,%7}, {%8,%9}, {%0,%1,%2,%3};"
        : "+f"(c[0]), "+f"(c[1]), "+f"(c[2]), "+f"(c[3])
        : "r"(a[0]), "r"(a[1]), "r"(a[2]), "r"(a[3]), "r"(b0), "r"(b1));
}

__device__ __forceinline__ void split_store8(char* sm, uint32_t offH, uint32_t offL,
                                             uint32_t doff, const float* v) {
    uint4 hh, ll;
    uint32_t* ph = (uint32_t*)&hh;
    uint32_t* pl = (uint32_t*)&ll;
#pragma unroll
    for (int k = 0; k < 4; k++) {
        float a = v[2 * k], b = v[2 * k + 1];
        __nv_bfloat16 ha = __float2bfloat16_rn(a), hb = __float2bfloat16_rn(b);
        float ra = a - __bfloat162float(ha), rb = b - __bfloat162float(hb);
        __nv_bfloat16 la = __float2bfloat16_rn(ra), lb = __float2bfloat16_rn(rb);
        ph[k] = (uint32_t)__bfloat16_as_ushort(ha) | ((uint32_t)__bfloat16_as_ushort(hb) << 16);
        pl[k] = (uint32_t)__bfloat16_as_ushort(la) | ((uint32_t)__bfloat16_as_ushort(lb) << 16);
    }
    *(uint4*)(sm + offH + doff) = hh;
    *(uint4*)(sm + offL + doff) = ll;
}
__device__ __forceinline__ void acc8(float* s, uint4 hh, uint4 ll) {
    const uint32_t* ph = (const uint32_t*)&hh;
    const uint32_t* pl = (const uint32_t*)&ll;
#pragma unroll
    for (int k = 0; k < 4; k++) {
        uint32_t wh = ph[k], wl = pl[k];
        s[2 * k]     += __uint_as_float(wh << 16) + __uint_as_float(wl << 16);
        s[2 * k + 1] += __uint_as_float(wh & 0xffff0000u) + __uint_as_float(wl & 0xffff0000u);
    }
}
__device__ __forceinline__ void split_store2(char* sm, uint32_t doff, float a, float b) {
    __nv_bfloat16 ha = __float2bfloat16_rn(a), hb = __float2bfloat16_rn(b);
    float ra = a - __bfloat162float(ha), rb = b - __bfloat162float(hb);
    __nv_bfloat16 la = __float2bfloat16_rn(ra), lb = __float2bfloat16_rn(rb);
    *(uint32_t*)(sm + OFF_XH + doff) =
        (uint32_t)__bfloat16_as_ushort(ha) | ((uint32_t)__bfloat16_as_ushort(hb) << 16);
    *(uint32_t*)(sm + OFF_XL + doff) =
        (uint32_t)__bfloat16_as_ushort(la) | ((uint32_t)__bfloat16_as_ushort(lb) << 16);
}
} // namespace

__global__ void split_weights_kernel(const float* __restrict__ W_rel,
                                     const float* __restrict__ W_root) {
    int i = blockIdx.x * blockDim.x + threadIdx.x;
    if (i >= NLAYER * 2 * H * H) return;
    int l = i / (2 * H * H);
    int r = i % (2 * H * H);
    int g = r / (H * H);
    int e = r % (H * H);
    float w = (g == 0) ? W_rel[l * H * H + e] : W_root[l * H * H + e];
    __nv_bfloat16 hi = __float2bfloat16_rn(w);
    float rem = w - __bfloat162float(hi);
    g_wsplit[l][g][0][e] = hi;
    g_wsplit[l][g][1][e] = __float2bfloat16_rn(rem);
}

__global__ __launch_bounds__(NTHREADS, 1) void gnn_mma_kernel(
    const float* __restrict__ obs,
    const float* __restrict__ We_b, const float* __restrict__ be_b,
    const float* __restrict__ We_j, const float* __restrict__ be_j,
    const float* __restrict__ b_rel,
    const float* __restrict__ W_dec, const float* __restrict__ b_dec,
    float* __restrict__ out, int B)
{
    extern __shared__ char sm[];
    const uint32_t sb = smem_u32(sm);
    const int tid = threadIdx.x, lane = tid & 31, wid = tid >> 5;
    const int m0 = (wid >> 2) * 16;          // 16-row slice (8 slices)
    const int n0 = (wid & 3) * 32;           // 32-col quarter
    const int g0 = blockIdx.x * GPT;
    const int ng = min(GPT, B - g0);
    const int rows_real = ng * NNODE;

    // ---- stage biases / encoder weights (transposed) / obs ----
    if (tid < H) {
        ((float*)(sm + OFF_BIAS + BO_BEB))[tid]  = be_b[tid];
        ((float*)(sm + OFF_BIAS + BO_BEJ))[tid]  = be_j[tid];
        ((float*)(sm + OFF_BIAS + BO_WDEC))[tid] = W_dec[tid];
    }
    if (tid >= H && tid < H + NLAYER * H)
        ((float*)(sm + OFF_BIAS + BO_BREL))[tid - H] = b_rel[tid - H];
    if (tid == 0) ((float*)(sm + OFF_BIAS + BO_BDEC))[0] = b_dec[0];
    for (int i = tid; i < H * BASE_F; i += NTHREADS) {
        int h = i / BASE_F, f = i - h * BASE_F;
        ((float*)(sm + OFF_WEB))[f * H + h] = We_b[i];
    }
    for (int i = tid; i < H * JOINT_F; i += NTHREADS) {
        int h = i / JOINT_F, f = i - h * JOINT_F;
        ((float*)(sm + OFF_WEJ))[f * H + h] = We_j[i];
    }
    for (int i = tid; i < ng * OBS_LEN; i += NTHREADS) {
        int g = i / OBS_LEN, k = i - g * OBS_LEN;
        ((float*)(sm + OFF_OBS))[g * 144 + k] = obs[(size_t)(g0 + g) * OBS_LEN + k];
    }
    __syncthreads();

    // ---- encoder: X hi/lo (zero the pad rows) ----
    for (int idx = tid; idx < MROWS * 16; idx += NTHREADS) {
        int row = idx >> 4, c0 = (idx & 15) << 3;
        uint32_t doff = (uint32_t)row * PITCHB + (uint32_t)c0 * 2;
        if (row >= rows_real) {
            uint4 z = make_uint4(0, 0, 0, 0);
            *(uint4*)(sm + OFF_XH + doff) = z;
            *(uint4*)(sm + OFF_XL + doff) = z;
            continue;
        }
        int g = row / NNODE, n = row - g * NNODE;
        const float* ob = (const float*)(sm + OFF_OBS) + g * 144;
        float acc[8];
        if (n == 0) {
            const float* be = (const float*)(sm + OFF_BIAS + BO_BEB);
#pragma unroll
            for (int e = 0; e < 8; e++) acc[e] = be[c0 + e];
#pragma unroll
            for (int t = 0; t < 3; t++)
#pragma unroll
                for (int i2 = 0; i2 < 11; i2++) {
                    float ft = ob[t * 47 + BIDX[i2]];
                    const float* w = (const float*)(sm + OFF_WEB) + (t * 11 + i2) * H + c0;
#pragma unroll
                    for (int e = 0; e < 8; e++) acc[e] = fmaf(ft, w[e], acc[e]);
                }
        } else {
            int j = n - 1;
            const float* be = (const float*)(sm + OFF_BIAS + BO_BEJ);
#pragma unroll
            for (int e = 0; e < 8; e++) acc[e] = be[c0 + e];
#pragma unroll
            for (int f = 0; f < 9; f++) {
                float ft = ob[(f / 3) * 47 + 9 + (f % 3) * 12 + j];
                const float* w = (const float*)(sm + OFF_WEJ) + f * H + c0;
#pragma unroll
                for (int e = 0; e < 8; e++) acc[e] = fmaf(ft, w[e], acc[e]);
            }
        }
#pragma unroll
        for (int e = 0; e < 8; e++) acc[e] = elu1(acc[e]);
        split_store8(sm, OFF_XH, OFF_XL, doff, acc);
    }

    // ---- layers:  x' = elu( S·(X@Wrel^T) + X@Wroot^T + b ) ----
    for (int l = 0; l < NLAYER; l++) {
        __syncthreads();  // X ready; W areas free (incl. encoder wts / Z1)

        // stage Wrel -> W1, Wroot -> W2 (hi/lo)
        {
            const uint4* relH = (const uint4*)&g_wsplit[l][0][0][0];
            const uint4* relL = (const uint4*)&g_wsplit[l][0][1][0];
            const uint4* rooH = (const uint4*)&g_wsplit[l][1][0][0];
            const uint4* rooL = (const uint4*)&g_wsplit[l][1][1][0];
            for (int idx = tid; idx < H * 16; idx += NTHREADS) {
                uint32_t d = (uint32_t)(idx >> 4) * PITCHB + (uint32_t)(idx & 15) * 16;
                *(uint4*)(sm + OFF_W1H + d) = relH[idx];
                *(uint4*)(sm + OFF_W1L + d) = relL[idx];
                *(uint4*)(sm + OFF_W2H + d) = rooH[idx];
                *(uint4*)(sm + OFF_W2L + d) = rooL[idx];
            }
        }
        __syncthreads();

        // merged dual 3-term GEMM over 16Mx32N tile:
        //   acc1 += X@W1^T terms, acc2 += X@W2^T terms, A fragments shared
        float acc1[2][2][4], acc2[2][2][4];   // [nt][hh][4]
#pragma unroll
        for (int nt = 0; nt < 2; nt++)
#pragma unroll
            for (int hh = 0; hh < 2; hh++)
#pragma unroll
                for (int e = 0; e < 4; e++) { acc1[nt][hh][e] = 0.f; acc2[nt][hh][e] = 0.f; }
        {
            const uint32_t arow = (uint32_t)(lane & 15);
            const uint32_t acol = (uint32_t)((lane >> 4) << 4);
            const uint32_t brow = (uint32_t)((lane & 7) + ((lane >> 4) << 3));
            const uint32_t bcol = (uint32_t)(((lane >> 3) & 1) << 4);
            const uint32_t aH0 = sb + OFF_XH + ((uint32_t)m0 + arow) * PITCHB + acol;
            const uint32_t aL0 = sb + OFF_XL + ((uint32_t)m0 + arow) * PITCHB + acol;
            const uint32_t bro = ((uint32_t)n0 + brow) * PITCHB + bcol;
            const uint32_t b1H0 = sb + OFF_W1H + bro;
            const uint32_t b1L0 = sb + OFF_W1L + bro;
            const uint32_t b2H0 = sb + OFF_W2H + bro;
            const uint32_t b2L0 = sb + OFF_W2L + bro;
#pragma unroll 4
            for (int k = 0; k < 8; k++) {
                const uint32_t kb = (uint32_t)k * 32u;
                uint32_t ah[4], al[4];
                ldsm4(ah[0], ah[1], ah[2], ah[3], aH0 + kb);
                ldsm4(al[0], al[1], al[2], al[3], aL0 + kb);
#pragma unroll
                for (int nt = 0; nt < 2; nt++) {
                    const uint32_t noff = (uint32_t)nt * (16u * PITCHB) + kb;
                    uint32_t h0, h1, h2, h3, l0, l1, l2, l3;
                    // W1
                    ldsm4(h0, h1, h2, h3, b1H0 + noff);
                    ldsm4(l0, l1, l2, l3, b1L0 + noff);
                    mma16816(acc1[nt][0], ah, h0, h1);
                    mma16816(acc1[nt][1], ah, h2, h3);
                    mma16816(acc1[nt][0], al, h0, h1);
                    mma16816(acc1[nt][1], al, h2, h3);
                    mma16816(acc1[nt][0], ah, l0, l1);
                    mma16816(acc1[nt][1], ah, l2, l3);
                    // W2
                    ldsm4(h0, h1, h2, h3, b2H0 + noff);
                    ldsm4(l0, l1, l2, l3, b2L0 + noff);
                    mma16816(acc2[nt][0], ah, h0, h1);
                    mma16816(acc2[nt][1], ah, h2, h3);
                    mma16816(acc2[nt][0], al, h0, h1);
                    mma16816(acc2[nt][1], al, h2, h3);
                    mma16816(acc2[nt][0], ah, l0, l1);
                    mma16816(acc2[nt][1], ah, l2, l3);
                }
            }
        }
        __syncthreads();  // all warps done reading W1/W2 -> safe to overlay Z1

        // spill Z1 (fp32) into the W1 area
        {
            float* z1 = (float*)(sm + OFF_Z1);
            const int r0 = m0 + (lane >> 2);
            const int cb = n0 + 2 * (lane & 3);
#pragma unroll
            for (int nt = 0; nt < 2; nt++)
#pragma unroll
                for (int hh = 0; hh < 2; hh++) {
                    const int col = cb + nt * 16 + hh * 8;
                    *(float2*)&z1[(uint32_t)r0 * PITCHZ + col] =
                        make_float2(acc1[nt][hh][0], acc1[nt][hh][1]);
                    *(float2*)&z1[(uint32_t)(r0 + 8) * PITCHZ + col] =
                        make_float2(acc1[nt][hh][2], acc1[nt][hh][3]);
                }
        }
        __syncthreads();  // Z1 complete everywhere

        // fused epilogue: x' = elu( S·Z1 + Z2 + b ), split-store into X
        {
            const float* z1  = (const float*)(sm + OFF_Z1);
            const float* brl = (const float*)(sm + OFF_BIAS + BO_BREL) + l * H;
            const int r0 = m0 + (lane >> 2);
            const int cb = n0 + 2 * (lane & 3);
#pragma unroll
            for (int half = 0; half < 2; half++) {
                const int r = r0 + half * 8;
                if (r >= rows_real) continue;
                const int g  = r / NNODE;
                const int n  = r - g * NNODE;
                const int gb = g * NNODE;
                const int cnt = NSRC[n];
#pragma unroll
                for (int nt = 0; nt < 2; nt++)
#pragma unroll
                    for (int hh = 0; hh < 2; hh++) {
                        const int col = cb + nt * 16 + hh * 8;
                        float v0 = acc2[nt][hh][2 * half]     + brl[col];
                        float v1 = acc2[nt][hh][2 * half + 1] + brl[col + 1];
                        for (int k2 = 0; k2 < cnt; k2++) {
                            const float* zr = &z1[(uint32_t)(gb + SRCS[n][k2]) * PITCHZ + col];
                            v0 += zr[0];
                            v1 += zr[1];
                        }
                        split_store2(sm, (uint32_t)r * PITCHB + (uint32_t)col * 2,
                                     elu1(v0), elu1(v1));
                    }
            }
        }
    }
    __syncthreads();

    // ---- decoder ----
    if (tid < ng * NJN) {
        int g = tid / NJN, j = tid - g * NJN;
        uint32_t roff = (uint32_t)(g * NNODE + 1 + j) * PITCHB;
        const float* wd = (const float*)(sm + OFF_BIAS + BO_WDEC);
        float acc = ((const float*)(sm + OFF_BIAS + BO_BDEC))[0];
        for (int c = 0; c < H; c += 8) {
            uint32_t soff = roff + (uint32_t)c * 2;
            float x[8] = {0.f, 0.f, 0.f, 0.f, 0.f, 0.f, 0.f, 0.f};
            acc8(x, *(const uint4*)(sm + OFF_XH + soff), *(const uint4*)(sm + OFF_XL + soff));
#pragma unroll
            for (int e = 0; e < 8; e++) acc = fmaf(x[e], wd[c + e], acc);
        }
        out[(size_t)(g0 + g) * NJN + j] = acc;
    }
}

extern "C" void kernel_launch(void* const* d_in, const int* in_sizes, int n_in,
                              void* d_out, int out_size)
{
    const float* obs    = (const float*)d_in[0];
    const float* We_b   = (const float*)d_in[1];
    const float* be_b   = (const float*)d_in[2];
    const float* We_j   = (const float*)d_in[3];
    const float* be_j   = (const float*)d_in[4];
    const float* W_rel  = (const float*)d_in[5];
    const float* W_root = (const float*)d_in[6];
    const float* b_rel  = (const float*)d_in[7];
    const float* W_dec  = (const float*)d_in[8];
    const float* b_dec  = (const float*)d_in[9];
    float*       out    = (float*)d_out;

    const int B = in_sizes[0] / OBS_LEN;

    split_weights_kernel<<<(NLAYER * 2 * H * H + 255) / 256, 256>>>(W_rel, W_root);

    const int ntiles = (B + GPT - 1) / GPT;
    cudaFuncSetAttribute(gnn_mma_kernel,
                         cudaFuncAttributeMaxDynamicSharedMemorySize, (int)SMEM_DYN);
    gnn_mma_kernel<<<ntiles, NTHREADS, SMEM_DYN>>>(
        obs, We_b, be_b, We_j, be_j, b_rel, W_dec, b_dec, out, B);
}

// round 9
// speedup vs baseline: 2.1777x; 1.1943x over previous
#include <cuda_runtime.h>
#include <cuda_fp16.h>
#include <stdint.h>
#include <math.h>

namespace {
constexpr int H = 128, NNODE = 13, NJN = 12, OBS_LEN = 141, NLAYER = 3;
constexpr int GPT = 9;               // graphs per CTA -> 117 rows, padded to 128
constexpr int MROWS = 128;
constexpr int NTHREADS = 1024;       // 32 warps: 8 M-slices x 4 N-quarters
constexpr int BASE_F = 33, JOINT_F = 9;

constexpr uint32_t PITCHB = 272;     // fp16 row: 128 elems + 8 pad (conflict-free ldmatrix)
constexpr uint32_t MATB   = MROWS * PITCHB;        // 34816
constexpr uint32_t PITCHZ = 132;     // Z1 fp32 row pitch (floats)

constexpr uint32_t OFF_XH  = 0;
constexpr uint32_t OFF_XL  = MATB;
constexpr uint32_t OFF_W1  = 2 * MATB;             // W_rel fp16
constexpr uint32_t OFF_W2  = 3 * MATB;             // W_root fp16
constexpr uint32_t OFF_Z1  = 4 * MATB;             // fp32 Z1, own buffer (67584 B)
constexpr uint32_t OFF_OBS = OFF_Z1 + 67584;
constexpr uint32_t OFF_BIAS = OFF_OBS + GPT * 144 * 4;
constexpr uint32_t BO_BEB = 0, BO_BEJ = 512, BO_BREL = 1024, BO_WDEC = 2560, BO_BDEC = 3072;
constexpr uint32_t OFF_WEB = OFF_W1;               // encoder weights (pre-layer0 only)
constexpr uint32_t OFF_WEJ = OFF_W1 + 16896;
constexpr uint32_t SMEM_DYN = OFF_BIAS + 3104;     // ~210.1 KB

__device__ __constant__ int8_t NSRC[13] = {4,2,2,1,2,2,1,2,2,1,2,2,1};
__device__ __constant__ int8_t SRCS[13][4] = {
    {1,4,7,10},{0,2,0,0},{1,3,0,0},{2,0,0,0},{0,5,0,0},{4,6,0,0},{5,0,0,0},
    {0,8,0,0},{7,9,0,0},{8,0,0,0},{0,11,0,0},{10,12,0,0},{11,0,0,0}};
__device__ __constant__ int8_t BIDX[11] = {0,1,2,3,4,5,6,7,8,45,46};

// fp16 weights: [layer][rel=0/root=1][n*128+k]
__device__ __half g_wh[NLAYER][2][H * H];

__device__ __forceinline__ uint32_t smem_u32(const void* p) {
    uint32_t a;
    asm("{ .reg .u64 t; cvta.to.shared.u64 t, %1; cvt.u32.u64 %0, t; }" : "=r"(a) : "l"(p));
    return a;
}
__device__ __forceinline__ float elu1(float v) { return v > 0.f ? v : expm1f(v); }

__device__ __forceinline__ void ldsm4(uint32_t& r0, uint32_t& r1, uint32_t& r2, uint32_t& r3,
                                      uint32_t addr) {
    asm volatile("ldmatrix.sync.aligned.m8n8.x4.shared.b16 {%0,%1,%2,%3}, [%4];"
                 : "=r"(r0), "=r"(r1), "=r"(r2), "=r"(r3) : "r"(addr));
}
__device__ __forceinline__ void mma16816(float* c, const uint32_t* a, uint32_t b0, uint32_t b1) {
    asm volatile(
        "mma.sync.aligned.m16n8k16.row.col.f32.f16.f16.f32 "
        "{%0,%1,%2,%3}, {%4,%5,%6,%7}, {%8,%9}, {%0,%1,%2,%3};"
        : "+f"(c[0]), "+f"(c[1]), "+f"(c[2]), "+f"(c[3])
        : "r"(a[0]), "r"(a[1]), "r"(a[2]), "r"(a[3]), "r"(b0), "r"(b1));
}

__device__ __forceinline__ uint32_t pack2(__half a, __half b) {
    return (uint32_t)__half_as_ushort(a) | ((uint32_t)__half_as_ushort(b) << 16);
}
__device__ __forceinline__ void split_store8(char* sm, uint32_t offH, uint32_t offL,
                                             uint32_t doff, const float* v) {
    uint4 hh, ll;
    uint32_t* ph = (uint32_t*)&hh;
    uint32_t* pl = (uint32_t*)&ll;
#pragma unroll
    for (int k = 0; k < 4; k++) {
        float a = v[2 * k], b = v[2 * k + 1];
        __half ha = __float2half_rn(a), hb = __float2half_rn(b);
        float ra = a - __half2float(ha), rb = b - __half2float(hb);
        ph[k] = pack2(ha, hb);
        pl[k] = pack2(__float2half_rn(ra), __float2half_rn(rb));
    }
    *(uint4*)(sm + offH + doff) = hh;
    *(uint4*)(sm + offL + doff) = ll;
}
__device__ __forceinline__ void acc8(float* s, uint4 hh, uint4 ll) {
    const uint32_t* ph = (const uint32_t*)&hh;
    const uint32_t* pl = (const uint32_t*)&ll;
#pragma unroll
    for (int k = 0; k < 4; k++) {
        uint32_t wh = ph[k], wl = pl[k];
        s[2 * k]     += __half2float(__ushort_as_half((unsigned short)(wh & 0xffffu)))
                      + __half2float(__ushort_as_half((unsigned short)(wl & 0xffffu)));
        s[2 * k + 1] += __half2float(__ushort_as_half((unsigned short)(wh >> 16)))
                      + __half2float(__ushort_as_half((unsigned short)(wl >> 16)));
    }
}
__device__ __forceinline__ void split_store2(char* sm, uint32_t doff, float a, float b) {
    __half ha = __float2half_rn(a), hb = __float2half_rn(b);
    float ra = a - __half2float(ha), rb = b - __half2float(hb);
    *(uint32_t*)(sm + OFF_XH + doff) = pack2(ha, hb);
    *(uint32_t*)(sm + OFF_XL + doff) = pack2(__float2half_rn(ra), __float2half_rn(rb));
}
} // namespace

__global__ void conv_weights_kernel(const float* __restrict__ W_rel,
                                    const float* __restrict__ W_root) {
    int i = blockIdx.x * blockDim.x + threadIdx.x;
    if (i >= NLAYER * 2 * H * H) return;
    int l = i / (2 * H * H);
    int r = i % (2 * H * H);
    int g = r / (H * H);
    int e = r % (H * H);
    float w = (g == 0) ? W_rel[l * H * H + e] : W_root[l * H * H + e];
    g_wh[l][g][e] = __float2half_rn(w);
}

__global__ __launch_bounds__(NTHREADS, 1) void gnn_mma_kernel(
    const float* __restrict__ obs,
    const float* __restrict__ We_b, const float* __restrict__ be_b,
    const float* __restrict__ We_j, const float* __restrict__ be_j,
    const float* __restrict__ b_rel,
    const float* __restrict__ W_dec, const float* __restrict__ b_dec,
    float* __restrict__ out, int B)
{
    extern __shared__ char sm[];
    const uint32_t sb = smem_u32(sm);
    const int tid = threadIdx.x, lane = tid & 31, wid = tid >> 5;
    const int m0 = (wid >> 2) * 16;          // 16-row slice (8 slices)
    const int n0 = (wid & 3) * 32;           // 32-col quarter
    const int g0 = blockIdx.x * GPT;
    const int ng = min(GPT, B - g0);
    const int rows_real = ng * NNODE;

    // ---- stage biases / encoder weights (transposed) / obs ----
    if (tid < H) {
        ((float*)(sm + OFF_BIAS + BO_BEB))[tid]  = be_b[tid];
        ((float*)(sm + OFF_BIAS + BO_BEJ))[tid]  = be_j[tid];
        ((float*)(sm + OFF_BIAS + BO_WDEC))[tid] = W_dec[tid];
    }
    if (tid >= H && tid < H + NLAYER * H)
        ((float*)(sm + OFF_BIAS + BO_BREL))[tid - H] = b_rel[tid - H];
    if (tid == 0) ((float*)(sm + OFF_BIAS + BO_BDEC))[0] = b_dec[0];
    for (int i = tid; i < H * BASE_F; i += NTHREADS) {
        int h = i / BASE_F, f = i - h * BASE_F;
        ((float*)(sm + OFF_WEB))[f * H + h] = We_b[i];
    }
    for (int i = tid; i < H * JOINT_F; i += NTHREADS) {
        int h = i / JOINT_F, f = i - h * JOINT_F;
        ((float*)(sm + OFF_WEJ))[f * H + h] = We_j[i];
    }
    for (int i = tid; i < ng * OBS_LEN; i += NTHREADS) {
        int g = i / OBS_LEN, k = i - g * OBS_LEN;
        ((float*)(sm + OFF_OBS))[g * 144 + k] = obs[(size_t)(g0 + g) * OBS_LEN + k];
    }
    __syncthreads();

    // ---- encoder: X hi/lo fp16 (zero the pad rows) ----
    for (int idx = tid; idx < MROWS * 16; idx += NTHREADS) {
        int row = idx >> 4, c0 = (idx & 15) << 3;
        uint32_t doff = (uint32_t)row * PITCHB + (uint32_t)c0 * 2;
        if (row >= rows_real) {
            uint4 z = make_uint4(0, 0, 0, 0);
            *(uint4*)(sm + OFF_XH + doff) = z;
            *(uint4*)(sm + OFF_XL + doff) = z;
            continue;
        }
        int g = row / NNODE, n = row - g * NNODE;
        const float* ob = (const float*)(sm + OFF_OBS) + g * 144;
        float acc[8];
        if (n == 0) {
            const float* be = (const float*)(sm + OFF_BIAS + BO_BEB);
#pragma unroll
            for (int e = 0; e < 8; e++) acc[e] = be[c0 + e];
#pragma unroll
            for (int t = 0; t < 3; t++)
#pragma unroll
                for (int i2 = 0; i2 < 11; i2++) {
                    float ft = ob[t * 47 + BIDX[i2]];
                    const float* w = (const float*)(sm + OFF_WEB) + (t * 11 + i2) * H + c0;
#pragma unroll
                    for (int e = 0; e < 8; e++) acc[e] = fmaf(ft, w[e], acc[e]);
                }
        } else {
            int j = n - 1;
            const float* be = (const float*)(sm + OFF_BIAS + BO_BEJ);
#pragma unroll
            for (int e = 0; e < 8; e++) acc[e] = be[c0 + e];
#pragma unroll
            for (int f = 0; f < 9; f++) {
                float ft = ob[(f / 3) * 47 + 9 + (f % 3) * 12 + j];
                const float* w = (const float*)(sm + OFF_WEJ) + f * H + c0;
#pragma unroll
                for (int e = 0; e < 8; e++) acc[e] = fmaf(ft, w[e], acc[e]);
            }
        }
#pragma unroll
        for (int e = 0; e < 8; e++) acc[e] = elu1(acc[e]);
        split_store8(sm, OFF_XH, OFF_XL, doff, acc);
    }

    // ---- layers:  x' = elu( S·(X@Wrel^T) + X@Wroot^T + b ) ----
    for (int l = 0; l < NLAYER; l++) {
        __syncthreads();  // X ready; W areas free of readers (incl. encoder wts)

        // stage Wrel -> W1, Wroot -> W2 (fp16, single precision term)
        {
            const uint4* rel = (const uint4*)&g_wh[l][0][0];
            const uint4* roo = (const uint4*)&g_wh[l][1][0];
            for (int idx = tid; idx < H * 16; idx += NTHREADS) {
                uint32_t d = (uint32_t)(idx >> 4) * PITCHB + (uint32_t)(idx & 15) * 16;
                *(uint4*)(sm + OFF_W1 + d) = rel[idx];
                *(uint4*)(sm + OFF_W2 + d) = roo[idx];
            }
        }
        __syncthreads();

        // merged dual 2-term GEMM over 16Mx32N tile:
        //   acc1 = (XH+XL)@W1^T, acc2 = (XH+XL)@W2^T, A fragments shared
        float acc1[2][2][4], acc2[2][2][4];   // [nt][hh][4]
#pragma unroll
        for (int nt = 0; nt < 2; nt++)
#pragma unroll
            for (int hh = 0; hh < 2; hh++)
#pragma unroll
                for (int e = 0; e < 4; e++) { acc1[nt][hh][e] = 0.f; acc2[nt][hh][e] = 0.f; }
        {
            const uint32_t arow = (uint32_t)(lane & 15);
            const uint32_t acol = (uint32_t)((lane >> 4) << 4);
            const uint32_t brow = (uint32_t)((lane & 7) + ((lane >> 4) << 3));
            const uint32_t bcol = (uint32_t)(((lane >> 3) & 1) << 4);
            const uint32_t aH0 = sb + OFF_XH + ((uint32_t)m0 + arow) * PITCHB + acol;
            const uint32_t aL0 = sb + OFF_XL + ((uint32_t)m0 + arow) * PITCHB + acol;
            const uint32_t bro = ((uint32_t)n0 + brow) * PITCHB + bcol;
            const uint32_t b10 = sb + OFF_W1 + bro;
            const uint32_t b20 = sb + OFF_W2 + bro;
#pragma unroll 4
            for (int k = 0; k < 8; k++) {
                const uint32_t kb = (uint32_t)k * 32u;
                uint32_t ah[4], al[4];
                ldsm4(ah[0], ah[1], ah[2], ah[3], aH0 + kb);
                ldsm4(al[0], al[1], al[2], al[3], aL0 + kb);
#pragma unroll
                for (int nt = 0; nt < 2; nt++) {
                    const uint32_t noff = (uint32_t)nt * (16u * PITCHB) + kb;
                    uint32_t w0, w1, w2, w3;
                    // W1
                    ldsm4(w0, w1, w2, w3, b10 + noff);
                    mma16816(acc1[nt][0], ah, w0, w1);
                    mma16816(acc1[nt][1], ah, w2, w3);
                    mma16816(acc1[nt][0], al, w0, w1);
                    mma16816(acc1[nt][1], al, w2, w3);
                    // W2
                    ldsm4(w0, w1, w2, w3, b20 + noff);
                    mma16816(acc2[nt][0], ah, w0, w1);
                    mma16816(acc2[nt][1], ah, w2, w3);
                    mma16816(acc2[nt][0], al, w0, w1);
                    mma16816(acc2[nt][1], al, w2, w3);
                }
            }
        }

        // spill Z1 (fp32) into its own buffer (no barrier needed before: own acc)
        {
            float* z1 = (float*)(sm + OFF_Z1);
            const int r0 = m0 + (lane >> 2);
            const int cb = n0 + 2 * (lane & 3);
#pragma unroll
            for (int nt = 0; nt < 2; nt++)
#pragma unroll
                for (int hh = 0; hh < 2; hh++) {
                    const int col = cb + nt * 16 + hh * 8;
                    *(float2*)&z1[(uint32_t)r0 * PITCHZ + col] =
                        make_float2(acc1[nt][hh][0], acc1[nt][hh][1]);
                    *(float2*)&z1[(uint32_t)(r0 + 8) * PITCHZ + col] =
                        make_float2(acc1[nt][hh][2], acc1[nt][hh][3]);
                }
        }
        __syncthreads();  // Z1 complete everywhere; all GEMM X-reads done

        // fused epilogue: x' = elu( S·Z1 + Z2 + b ), split-store into X
        {
            const float* z1  = (const float*)(sm + OFF_Z1);
            const float* brl = (const float*)(sm + OFF_BIAS + BO_BREL) + l * H;
            const int r0 = m0 + (lane >> 2);
            const int cb = n0 + 2 * (lane & 3);
#pragma unroll
            for (int half = 0; half < 2; half++) {
                const int r = r0 + half * 8;
                if (r >= rows_real) continue;
                const int g  = r / NNODE;
                const int n  = r - g * NNODE;
                const int gb = g * NNODE;
                const int cnt = NSRC[n];
#pragma unroll
                for (int nt = 0; nt < 2; nt++)
#pragma unroll
                    for (int hh = 0; hh < 2; hh++) {
                        const int col = cb + nt * 16 + hh * 8;
                        float v0 = acc2[nt][hh][2 * half]     + brl[col];
                        float v1 = acc2[nt][hh][2 * half + 1] + brl[col + 1];
                        for (int k2 = 0; k2 < cnt; k2++) {
                            const float* zr = &z1[(uint32_t)(gb + SRCS[n][k2]) * PITCHZ + col];
                            v0 += zr[0];
                            v1 += zr[1];
                        }
                        split_store2(sm, (uint32_t)r * PITCHB + (uint32_t)col * 2,
                                     elu1(v0), elu1(v1));
                    }
            }
        }
    }
    __syncthreads();

    // ---- decoder ----
    if (tid < ng * NJN) {
        int g = tid / NJN, j = tid - g * NJN;
        uint32_t roff = (uint32_t)(g * NNODE + 1 + j) * PITCHB;
        const float* wd = (const float*)(sm + OFF_BIAS + BO_WDEC);
        float acc = ((const float*)(sm + OFF_BIAS + BO_BDEC))[0];
        for (int c = 0; c < H; c += 8) {
            uint32_t soff = roff + (uint32_t)c * 2;
            float x[8] = {0.f, 0.f, 0.f, 0.f, 0.f, 0.f, 0.f, 0.f};
            acc8(x, *(const uint4*)(sm + OFF_XH + soff), *(const uint4*)(sm + OFF_XL + soff));
#pragma unroll
            for (int e = 0; e < 8; e++) acc = fmaf(x[e], wd[c + e], acc);
        }
        out[(size_t)(g0 + g) * NJN + j] = acc;
    }
}

extern "C" void kernel_launch(void* const* d_in, const int* in_sizes, int n_in,
                              void* d_out, int out_size)
{
    const float* obs    = (const float*)d_in[0];
    const float* We_b   = (const float*)d_in[1];
    const float* be_b   = (const float*)d_in[2];
    const float* We_j   = (const float*)d_in[3];
    const float* be_j   = (const float*)d_in[4];
    const float* W_rel  = (const float*)d_in[5];
    const float* W_root = (const float*)d_in[6];
    const float* b_rel  = (const float*)d_in[7];
    const float* W_dec  = (const float*)d_in[8];
    const float* b_dec  = (const float*)d_in[9];
    float*       out    = (float*)d_out;

    const int B = in_sizes[0] / OBS_LEN;

    conv_weights_kernel<<<(NLAYER * 2 * H * H + 255) / 256, 256>>>(W_rel, W_root);

    const int ntiles = (B + GPT - 1) / GPT;
    cudaFuncSetAttribute(gnn_mma_kernel,
                         cudaFuncAttributeMaxDynamicSharedMemorySize, (int)SMEM_DYN);
    gnn_mma_kernel<<<ntiles, NTHREADS, SMEM_DYN>>>(
        obs, We_b, be_b, We_j, be_j, b_rel, W_dec, b_dec, out, B);
}

// round 10
// speedup vs baseline: 2.2322x; 1.0250x over previous
#include <cuda_runtime.h>
#include <cuda_fp16.h>
#include <stdint.h>
#include <math.h>

namespace {
constexpr int H = 128, NNODE = 13, NJN = 12, OBS_LEN = 141, NLAYER = 3;
constexpr int GPT = 9;               // graphs per CTA -> 117 rows, padded to 128
constexpr int MROWS = 128;
constexpr int NTHREADS = 1024;       // 32 warps: 8 M-slices x 4 N-quarters
constexpr int BASE_F = 33, JOINT_F = 9;

constexpr uint32_t PITCHB = 272;     // fp16 row: 128 elems + 8 pad (conflict-free ldmatrix)
constexpr uint32_t MATB   = MROWS * PITCHB;        // 34816
constexpr uint32_t PITCHZ = 132;     // fp32 row pitch (floats)

constexpr uint32_t OFF_XH  = 0;
constexpr uint32_t OFF_XL  = MATB;
constexpr uint32_t OFF_W1  = 2 * MATB;             // W_rel fp16
constexpr uint32_t OFF_W2  = 3 * MATB;             // W_root fp16
constexpr uint32_t OFF_Z1  = 4 * MATB;             // fp32 Z1 (67584 B); enc weights pre-layer0
constexpr uint32_t OFF_OBS = OFF_Z1 + 67584;
constexpr uint32_t OFF_BIAS = OFF_OBS + GPT * 144 * 4;
constexpr uint32_t BO_BEB = 0, BO_BEJ = 512, BO_BREL = 1024, BO_WDEC = 2560, BO_BDEC = 3072;
constexpr uint32_t OFF_WEB = OFF_Z1;               // encoder weights (pre-layer0 only)
constexpr uint32_t OFF_WEJ = OFF_Z1 + 16896;
constexpr uint32_t SMEM_DYN = OFF_BIAS + 3104;     // ~210.1 KB

__device__ __constant__ int8_t NSRC[13] = {4,2,2,1,2,2,1,2,2,1,2,2,1};
__device__ __constant__ int8_t SRCS[13][4] = {
    {1,4,7,10},{0,2,0,0},{1,3,0,0},{2,0,0,0},{0,5,0,0},{4,6,0,0},{5,0,0,0},
    {0,8,0,0},{7,9,0,0},{8,0,0,0},{0,11,0,0},{10,12,0,0},{11,0,0,0}};
__device__ __constant__ int8_t BIDX[11] = {0,1,2,3,4,5,6,7,8,45,46};

// fp16 weights: [layer][rel=0/root=1][n*128+k]
__device__ __half g_wh[NLAYER][2][H * H];

__device__ __forceinline__ uint32_t smem_u32(const void* p) {
    uint32_t a;
    asm("{ .reg .u64 t; cvta.to.shared.u64 t, %1; cvt.u32.u64 %0, t; }" : "=r"(a) : "l"(p));
    return a;
}
__device__ __forceinline__ float elu1(float v) { return v > 0.f ? v : expm1f(v); }

__device__ __forceinline__ void ldsm4(uint32_t& r0, uint32_t& r1, uint32_t& r2, uint32_t& r3,
                                      uint32_t addr) {
    asm volatile("ldmatrix.sync.aligned.m8n8.x4.shared.b16 {%0,%1,%2,%3}, [%4];"
                 : "=r"(r0), "=r"(r1), "=r"(r2), "=r"(r3) : "r"(addr));
}
__device__ __forceinline__ void mma16816(float* c, const uint32_t* a, uint32_t b0, uint32_t b1) {
    asm volatile(
        "mma.sync.aligned.m16n8k16.row.col.f32.f16.f16.f32 "
        "{%0,%1,%2,%3}, {%4,%5,%6,%7}, {%8,%9}, {%0,%1,%2,%3};"
        : "+f"(c[0]), "+f"(c[1]), "+f"(c[2]), "+f"(c[3])
        : "r"(a[0]), "r"(a[1]), "r"(a[2]), "r"(a[3]), "r"(b0), "r"(b1));
}

// packed f32x2 -> f16x2 (low = first arg). PTX: first source lands in HIGH half.
__device__ __forceinline__ uint32_t cvtpack(float lo, float hi) {
    uint32_t r;
    asm("cvt.rn.f16x2.f32 %0, %1, %2;" : "=r"(r) : "f"(hi), "f"(lo));
    return r;
}
__device__ __forceinline__ void hilo2(float a, float b, uint32_t& hh, uint32_t& ll) {
    hh = cvtpack(a, b);
    __half2 h2 = *reinterpret_cast<__half2*>(&hh);
    float2 back = __half22float2(h2);
    ll = cvtpack(a - back.x, b - back.y);
}
__device__ __forceinline__ void split_store8(char* sm, uint32_t offH, uint32_t offL,
                                             uint32_t doff, const float* v) {
    uint4 hh, ll;
    uint32_t* ph = (uint32_t*)&hh;
    uint32_t* pl = (uint32_t*)&ll;
#pragma unroll
    for (int k = 0; k < 4; k++) hilo2(v[2 * k], v[2 * k + 1], ph[k], pl[k]);
    *(uint4*)(sm + offH + doff) = hh;
    *(uint4*)(sm + offL + doff) = ll;
}
__device__ __forceinline__ void split_store2(char* sm, uint32_t doff, float a, float b) {
    uint32_t hh, ll;
    hilo2(a, b, hh, ll);
    *(uint32_t*)(sm + OFF_XH + doff) = hh;
    *(uint32_t*)(sm + OFF_XL + doff) = ll;
}
} // namespace

__global__ void conv_weights_kernel(const float* __restrict__ W_rel,
                                    const float* __restrict__ W_root) {
    int i = blockIdx.x * blockDim.x + threadIdx.x;
    if (i >= NLAYER * 2 * H * H) return;
    int l = i / (2 * H * H);
    int r = i % (2 * H * H);
    int g = r / (H * H);
    int e = r % (H * H);
    float w = (g == 0) ? W_rel[l * H * H + e] : W_root[l * H * H + e];
    g_wh[l][g][e] = __float2half_rn(w);
}

__global__ __launch_bounds__(NTHREADS, 1) void gnn_mma_kernel(
    const float* __restrict__ obs,
    const float* __restrict__ We_b, const float* __restrict__ be_b,
    const float* __restrict__ We_j, const float* __restrict__ be_j,
    const float* __restrict__ b_rel,
    const float* __restrict__ W_dec, const float* __restrict__ b_dec,
    float* __restrict__ out, int B)
{
    extern __shared__ char sm[];
    const uint32_t sb = smem_u32(sm);
    const int tid = threadIdx.x, lane = tid & 31, wid = tid >> 5;
    const int m0 = (wid >> 2) * 16;          // 16-row slice (8 slices)
    const int n0 = (wid & 3) * 32;           // 32-col quarter
    const int g0 = blockIdx.x * GPT;
    const int ng = min(GPT, B - g0);
    const int rows_real = ng * NNODE;

    // ---- stage biases / encoder weights (transposed, in Z1 area) / obs ----
    if (tid < H) {
        ((float*)(sm + OFF_BIAS + BO_BEB))[tid]  = be_b[tid];
        ((float*)(sm + OFF_BIAS + BO_BEJ))[tid]  = be_j[tid];
        ((float*)(sm + OFF_BIAS + BO_WDEC))[tid] = W_dec[tid];
    }
    if (tid >= H && tid < H + NLAYER * H)
        ((float*)(sm + OFF_BIAS + BO_BREL))[tid - H] = b_rel[tid - H];
    if (tid == 0) ((float*)(sm + OFF_BIAS + BO_BDEC))[0] = b_dec[0];
    for (int i = tid; i < H * BASE_F; i += NTHREADS) {
        int h = i / BASE_F, f = i - h * BASE_F;
        ((float*)(sm + OFF_WEB))[f * H + h] = We_b[i];
    }
    for (int i = tid; i < H * JOINT_F; i += NTHREADS) {
        int h = i / JOINT_F, f = i - h * JOINT_F;
        ((float*)(sm + OFF_WEJ))[f * H + h] = We_j[i];
    }
    for (int i = tid; i < ng * OBS_LEN; i += NTHREADS) {
        int g = i / OBS_LEN, k = i - g * OBS_LEN;
        ((float*)(sm + OFF_OBS))[g * 144 + k] = obs[(size_t)(g0 + g) * OBS_LEN + k];
    }
    __syncthreads();

    // ---- phase A: encoder (X hi/lo fp16) + stage W(0) concurrently ----
    {
        const uint4* rel = (const uint4*)&g_wh[0][0][0];
        const uint4* roo = (const uint4*)&g_wh[0][1][0];
        for (int idx = tid; idx < H * 16; idx += NTHREADS) {
            uint32_t d = (uint32_t)(idx >> 4) * PITCHB + (uint32_t)(idx & 15) * 16;
            *(uint4*)(sm + OFF_W1 + d) = rel[idx];
            *(uint4*)(sm + OFF_W2 + d) = roo[idx];
        }
    }
    for (int idx = tid; idx < MROWS * 16; idx += NTHREADS) {
        int row = idx >> 4, c0 = (idx & 15) << 3;
        uint32_t doff = (uint32_t)row * PITCHB + (uint32_t)c0 * 2;
        if (row >= rows_real) {
            uint4 z = make_uint4(0, 0, 0, 0);
            *(uint4*)(sm + OFF_XH + doff) = z;
            *(uint4*)(sm + OFF_XL + doff) = z;
            continue;
        }
        int g = row / NNODE, n = row - g * NNODE;
        const float* ob = (const float*)(sm + OFF_OBS) + g * 144;
        float acc[8];
        if (n == 0) {
            const float* be = (const float*)(sm + OFF_BIAS + BO_BEB);
#pragma unroll
            for (int e = 0; e < 8; e++) acc[e] = be[c0 + e];
#pragma unroll
            for (int t = 0; t < 3; t++)
#pragma unroll
                for (int i2 = 0; i2 < 11; i2++) {
                    float ft = ob[t * 47 + BIDX[i2]];
                    const float* w = (const float*)(sm + OFF_WEB) + (t * 11 + i2) * H + c0;
#pragma unroll
                    for (int e = 0; e < 8; e++) acc[e] = fmaf(ft, w[e], acc[e]);
                }
        } else {
            int j = n - 1;
            const float* be = (const float*)(sm + OFF_BIAS + BO_BEJ);
#pragma unroll
            for (int e = 0; e < 8; e++) acc[e] = be[c0 + e];
#pragma unroll
            for (int f = 0; f < 9; f++) {
                float ft = ob[(f / 3) * 47 + 9 + (f % 3) * 12 + j];
                const float* w = (const float*)(sm + OFF_WEJ) + f * H + c0;
#pragma unroll
                for (int e = 0; e < 8; e++) acc[e] = fmaf(ft, w[e], acc[e]);
            }
        }
#pragma unroll
        for (int e = 0; e < 8; e++) acc[e] = elu1(acc[e]);
        split_store8(sm, OFF_XH, OFF_XL, doff, acc);
    }

    // ---- layers:  x' = elu( S·(X@Wrel^T) + X@Wroot^T + b ) ----
    for (int l = 0; l < NLAYER; l++) {
        __syncthreads();  // X(l) + W(l) ready; Z1 free of readers

        // merged dual 2-term GEMM over 16Mx32N tile:
        //   acc1 = (XH+XL)@W1^T, acc2 = (XH+XL)@W2^T, A fragments shared
        float acc1[2][2][4], acc2[2][2][4];   // [nt][hh][4]
#pragma unroll
        for (int nt = 0; nt < 2; nt++)
#pragma unroll
            for (int hh = 0; hh < 2; hh++)
#pragma unroll
                for (int e = 0; e < 4; e++) { acc1[nt][hh][e] = 0.f; acc2[nt][hh][e] = 0.f; }
        {
            const uint32_t arow = (uint32_t)(lane & 15);
            const uint32_t acol = (uint32_t)((lane >> 4) << 4);
            const uint32_t brow = (uint32_t)((lane & 7) + ((lane >> 4) << 3));
            const uint32_t bcol = (uint32_t)(((lane >> 3) & 1) << 4);
            const uint32_t aH0 = sb + OFF_XH + ((uint32_t)m0 + arow) * PITCHB + acol;
            const uint32_t aL0 = sb + OFF_XL + ((uint32_t)m0 + arow) * PITCHB + acol;
            const uint32_t bro = ((uint32_t)n0 + brow) * PITCHB + bcol;
            const uint32_t b10 = sb + OFF_W1 + bro;
            const uint32_t b20 = sb + OFF_W2 + bro;
#pragma unroll 4
            for (int k = 0; k < 8; k++) {
                const uint32_t kb = (uint32_t)k * 32u;
                uint32_t ah[4], al[4];
                ldsm4(ah[0], ah[1], ah[2], ah[3], aH0 + kb);
                ldsm4(al[0], al[1], al[2], al[3], aL0 + kb);
#pragma unroll
                for (int nt = 0; nt < 2; nt++) {
                    const uint32_t noff = (uint32_t)nt * (16u * PITCHB) + kb;
                    uint32_t w0, w1, w2, w3;
                    // W1
                    ldsm4(w0, w1, w2, w3, b10 + noff);
                    mma16816(acc1[nt][0], ah, w0, w1);
                    mma16816(acc1[nt][1], ah, w2, w3);
                    mma16816(acc1[nt][0], al, w0, w1);
                    mma16816(acc1[nt][1], al, w2, w3);
                    // W2
                    ldsm4(w0, w1, w2, w3, b20 + noff);
                    mma16816(acc2[nt][0], ah, w0, w1);
                    mma16816(acc2[nt][1], ah, w2, w3);
                    mma16816(acc2[nt][0], al, w0, w1);
                    mma16816(acc2[nt][1], al, w2, w3);
                }
            }
        }

        // spill Z1 (fp32) into its own buffer
        {
            float* z1 = (float*)(sm + OFF_Z1);
            const int r0 = m0 + (lane >> 2);
            const int cb = n0 + 2 * (lane & 3);
#pragma unroll
            for (int nt = 0; nt < 2; nt++)
#pragma unroll
                for (int hh = 0; hh < 2; hh++) {
                    const int col = cb + nt * 16 + hh * 8;
                    *(float2*)&z1[(uint32_t)r0 * PITCHZ + col] =
                        make_float2(acc1[nt][hh][0], acc1[nt][hh][1]);
                    *(float2*)&z1[(uint32_t)(r0 + 8) * PITCHZ + col] =
                        make_float2(acc1[nt][hh][2], acc1[nt][hh][3]);
                }
        }
        __syncthreads();  // Z1 complete; all GEMM X/W reads done

        // fused epilogue: x' = elu( S·Z1 + Z2 + b )
        // last layer stores fp32 (no re-split); other layers split-store fp16 hi/lo
        {
            const float* z1  = (const float*)(sm + OFF_Z1);
            float* xf        = (float*)(sm + OFF_XH);   // fp32 view for last layer
            const float* brl = (const float*)(sm + OFF_BIAS + BO_BREL) + l * H;
            const int r0 = m0 + (lane >> 2);
            const int cb = n0 + 2 * (lane & 3);
            const bool last = (l == NLAYER - 1);
#pragma unroll
            for (int half = 0; half < 2; half++) {
                const int r = r0 + half * 8;
                if (r >= rows_real) continue;
                const int g  = r / NNODE;
                const int n  = r - g * NNODE;
                const int gb = g * NNODE;
                const int cnt = NSRC[n];
#pragma unroll
                for (int nt = 0; nt < 2; nt++)
#pragma unroll
                    for (int hh = 0; hh < 2; hh++) {
                        const int col = cb + nt * 16 + hh * 8;
                        float v0 = acc2[nt][hh][2 * half]     + brl[col];
                        float v1 = acc2[nt][hh][2 * half + 1] + brl[col + 1];
                        for (int k2 = 0; k2 < cnt; k2++) {
                            const float* zr = &z1[(uint32_t)(gb + SRCS[n][k2]) * PITCHZ + col];
                            v0 += zr[0];
                            v1 += zr[1];
                        }
                        v0 = elu1(v0);
                        v1 = elu1(v1);
                        if (last) {
                            *(float2*)&xf[(uint32_t)r * PITCHZ + col] = make_float2(v0, v1);
                        } else {
                            split_store2(sm, (uint32_t)r * PITCHB + (uint32_t)col * 2, v0, v1);
                        }
                    }
            }
        }

        // stage W(l+1) in the same phase (W buffers idle during epilogue)
        if (l + 1 < NLAYER) {
            const uint4* rel = (const uint4*)&g_wh[l + 1][0][0];
            const uint4* roo = (const uint4*)&g_wh[l + 1][1][0];
            for (int idx = tid; idx < H * 16; idx += NTHREADS) {
                uint32_t d = (uint32_t)(idx >> 4) * PITCHB + (uint32_t)(idx & 15) * 16;
                *(uint4*)(sm + OFF_W1 + d) = rel[idx];
                *(uint4*)(sm + OFF_W2 + d) = roo[idx];
            }
        }
    }
    __syncthreads();

    // ---- decoder (final X is fp32 at OFF_XH, pitch PITCHZ) ----
    if (tid < ng * NJN) {
        int g = tid / NJN, j = tid - g * NJN;
        const float* xf = (const float*)(sm + OFF_XH) + (uint32_t)(g * NNODE + 1 + j) * PITCHZ;
        const float* wd = (const float*)(sm + OFF_BIAS + BO_WDEC);
        float acc = ((const float*)(sm + OFF_BIAS + BO_BDEC))[0];
#pragma unroll 4
        for (int c = 0; c < H; c += 4) {
            float4 x4 = *(const float4*)&xf[c];
            float4 w4 = *(const float4*)&wd[c];
            acc = fmaf(x4.x, w4.x, acc);
            acc = fmaf(x4.y, w4.y, acc);
            acc = fmaf(x4.z, w4.z, acc);
            acc = fmaf(x4.w, w4.w, acc);
        }
        out[(size_t)(g0 + g) * NJN + j] = acc;
    }
}

extern "C" void kernel_launch(void* const* d_in, const int* in_sizes, int n_in,
                              void* d_out, int out_size)
{
    const float* obs    = (const float*)d_in[0];
    const float* We_b   = (const float*)d_in[1];
    const float* be_b   = (const float*)d_in[2];
    const float* We_j   = (const float*)d_in[3];
    const float* be_j   = (const float*)d_in[4];
    const float* W_rel  = (const float*)d_in[5];
    const float* W_root = (const float*)d_in[6];
    const float* b_rel  = (const float*)d_in[7];
    const float* W_dec  = (const float*)d_in[8];
    const float* b_dec  = (const float*)d_in[9];
    float*       out    = (float*)d_out;

    const int B = in_sizes[0] / OBS_LEN;

    conv_weights_kernel<<<(NLAYER * 2 * H * H + 255) / 256, 256>>>(W_rel, W_root);

    const int ntiles = (B + GPT - 1) / GPT;
    cudaFuncSetAttribute(gnn_mma_kernel,
                         cudaFuncAttributeMaxDynamicSharedMemorySize, (int)SMEM_DYN);
    gnn_mma_kernel<<<ntiles, NTHREADS, SMEM_DYN>>>(
        obs, We_b, be_b, We_j, be_j, b_rel, W_dec, b_dec, out, B);
}

// round 11
// speedup vs baseline: 2.5315x; 1.1341x over previous
#include <cuda_runtime.h>
#include <cuda_fp16.h>
#include <stdint.h>
#include <math.h>

namespace {
constexpr int H = 128, NNODE = 13, NJN = 12, OBS_LEN = 141, NLAYER = 3;
constexpr int GPT = 9;               // graphs per CTA -> 117 rows, padded to 128
constexpr int MROWS = 128;
constexpr int NTHREADS = 1024;       // 32 warps: 8 M-slices x 4 N-quarters
constexpr int BASE_F = 33, JOINT_F = 9;

constexpr uint32_t PITCHB = 272;     // fp16 row: 128 elems + 8 pad (conflict-free ldmatrix)
constexpr uint32_t MATB   = MROWS * PITCHB;        // 34816
constexpr uint32_t PITCHZ = 132;     // fp32 row pitch (floats)

constexpr uint32_t OFF_XH  = 0;      // X fp16 (single term); last layer spills fp32 here,
                                     // overflowing into the scratch region below
constexpr uint32_t OFF_SCR = MATB;   // scratch (last-layer fp32 X overflow)
constexpr uint32_t OFF_W1  = 2 * MATB;             // W_rel fp16
constexpr uint32_t OFF_W2  = 3 * MATB;             // W_root fp16
constexpr uint32_t OFF_Z1  = 4 * MATB;             // fp32 Z1 (67584 B); enc weights pre-layer0
constexpr uint32_t OFF_OBS = OFF_Z1 + 67584;
constexpr uint32_t OFF_BIAS = OFF_OBS + GPT * 144 * 4;
constexpr uint32_t BO_BEB = 0, BO_BEJ = 512, BO_BREL = 1024, BO_WDEC = 2560, BO_BDEC = 3072;
constexpr uint32_t OFF_WEB = OFF_Z1;               // encoder weights (pre-layer0 only)
constexpr uint32_t OFF_WEJ = OFF_Z1 + 16896;
constexpr uint32_t SMEM_DYN = OFF_BIAS + 3104;     // ~210.1 KB

__device__ __constant__ int8_t NSRC[13] = {4,2,2,1,2,2,1,2,2,1,2,2,1};
__device__ __constant__ int8_t SRCS[13][4] = {
    {1,4,7,10},{0,2,0,0},{1,3,0,0},{2,0,0,0},{0,5,0,0},{4,6,0,0},{5,0,0,0},
    {0,8,0,0},{7,9,0,0},{8,0,0,0},{0,11,0,0},{10,12,0,0},{11,0,0,0}};
__device__ __constant__ int8_t BIDX[11] = {0,1,2,3,4,5,6,7,8,45,46};

// fp16 weights: [layer][rel=0/root=1][n*128+k]
__device__ __half g_wh[NLAYER][2][H * H];

__device__ __forceinline__ uint32_t smem_u32(const void* p) {
    uint32_t a;
    asm("{ .reg .u64 t; cvta.to.shared.u64 t, %1; cvt.u32.u64 %0, t; }" : "=r"(a) : "l"(p));
    return a;
}
__device__ __forceinline__ float elu1(float v) { return v > 0.f ? v : expm1f(v); }

__device__ __forceinline__ void ldsm4(uint32_t& r0, uint32_t& r1, uint32_t& r2, uint32_t& r3,
                                      uint32_t addr) {
    asm volatile("ldmatrix.sync.aligned.m8n8.x4.shared.b16 {%0,%1,%2,%3}, [%4];"
                 : "=r"(r0), "=r"(r1), "=r"(r2), "=r"(r3) : "r"(addr));
}
__device__ __forceinline__ void mma16816(float* c, const uint32_t* a, uint32_t b0, uint32_t b1) {
    asm volatile(
        "mma.sync.aligned.m16n8k16.row.col.f32.f16.f16.f32 "
        "{%0,%1,%2,%3}, {%4,%5,%6,%7}, {%8,%9}, {%0,%1,%2,%3};"
        : "+f"(c[0]), "+f"(c[1]), "+f"(c[2]), "+f"(c[3])
        : "r"(a[0]), "r"(a[1]), "r"(a[2]), "r"(a[3]), "r"(b0), "r"(b1));
}

// packed f32x2 -> f16x2 (low half = first arg; PTX puts first source in HIGH half)
__device__ __forceinline__ uint32_t cvtpack(float lo, float hi) {
    uint32_t r;
    asm("cvt.rn.f16x2.f32 %0, %1, %2;" : "=r"(r) : "f"(hi), "f"(lo));
    return r;
}
__device__ __forceinline__ void store8h(char* sm, uint32_t doff, const float* v) {
    uint4 hh;
    uint32_t* ph = (uint32_t*)&hh;
#pragma unroll
    for (int k = 0; k < 4; k++) ph[k] = cvtpack(v[2 * k], v[2 * k + 1]);
    *(uint4*)(sm + OFF_XH + doff) = hh;
}
} // namespace

__global__ void conv_weights_kernel(const float* __restrict__ W_rel,
                                    const float* __restrict__ W_root) {
    int i = blockIdx.x * blockDim.x + threadIdx.x;
    if (i >= NLAYER * 2 * H * H) return;
    int l = i / (2 * H * H);
    int r = i % (2 * H * H);
    int g = r / (H * H);
    int e = r % (H * H);
    float w = (g == 0) ? W_rel[l * H * H + e] : W_root[l * H * H + e];
    g_wh[l][g][e] = __float2half_rn(w);
}

__global__ __launch_bounds__(NTHREADS, 1) void gnn_mma_kernel(
    const float* __restrict__ obs,
    const float* __restrict__ We_b, const float* __restrict__ be_b,
    const float* __restrict__ We_j, const float* __restrict__ be_j,
    const float* __restrict__ b_rel,
    const float* __restrict__ W_dec, const float* __restrict__ b_dec,
    float* __restrict__ out, int B)
{
    extern __shared__ char sm[];
    const uint32_t sb = smem_u32(sm);
    const int tid = threadIdx.x, lane = tid & 31, wid = tid >> 5;
    const int m0 = (wid >> 2) * 16;          // 16-row slice (8 slices)
    const int n0 = (wid & 3) * 32;           // 32-col quarter
    const int g0 = blockIdx.x * GPT;
    const int ng = min(GPT, B - g0);
    const int rows_real = ng * NNODE;

    // ---- stage biases / encoder weights (transposed, in Z1 area) / obs ----
    if (tid < H) {
        ((float*)(sm + OFF_BIAS + BO_BEB))[tid]  = be_b[tid];
        ((float*)(sm + OFF_BIAS + BO_BEJ))[tid]  = be_j[tid];
        ((float*)(sm + OFF_BIAS + BO_WDEC))[tid] = W_dec[tid];
    }
    if (tid >= H && tid < H + NLAYER * H)
        ((float*)(sm + OFF_BIAS + BO_BREL))[tid - H] = b_rel[tid - H];
    if (tid == 0) ((float*)(sm + OFF_BIAS + BO_BDEC))[0] = b_dec[0];
    for (int i = tid; i < H * BASE_F; i += NTHREADS) {
        int h = i / BASE_F, f = i - h * BASE_F;
        ((float*)(sm + OFF_WEB))[f * H + h] = We_b[i];
    }
    for (int i = tid; i < H * JOINT_F; i += NTHREADS) {
        int h = i / JOINT_F, f = i - h * JOINT_F;
        ((float*)(sm + OFF_WEJ))[f * H + h] = We_j[i];
    }
    for (int i = tid; i < ng * OBS_LEN; i += NTHREADS) {
        int g = i / OBS_LEN, k = i - g * OBS_LEN;
        ((float*)(sm + OFF_OBS))[g * 144 + k] = obs[(size_t)(g0 + g) * OBS_LEN + k];
    }
    __syncthreads();

    // ---- phase A: encoder (X fp16) + stage W(0) concurrently ----
    {
        const uint4* rel = (const uint4*)&g_wh[0][0][0];
        const uint4* roo = (const uint4*)&g_wh[0][1][0];
        for (int idx = tid; idx < H * 16; idx += NTHREADS) {
            uint32_t d = (uint32_t)(idx >> 4) * PITCHB + (uint32_t)(idx & 15) * 16;
            *(uint4*)(sm + OFF_W1 + d) = rel[idx];
            *(uint4*)(sm + OFF_W2 + d) = roo[idx];
        }
    }
    for (int idx = tid; idx < MROWS * 16; idx += NTHREADS) {
        int row = idx >> 4, c0 = (idx & 15) << 3;
        uint32_t doff = (uint32_t)row * PITCHB + (uint32_t)c0 * 2;
        if (row >= rows_real) {
            *(uint4*)(sm + OFF_XH + doff) = make_uint4(0, 0, 0, 0);
            continue;
        }
        int g = row / NNODE, n = row - g * NNODE;
        const float* ob = (const float*)(sm + OFF_OBS) + g * 144;
        float acc[8];
        if (n == 0) {
            const float* be = (const float*)(sm + OFF_BIAS + BO_BEB);
#pragma unroll
            for (int e = 0; e < 8; e++) acc[e] = be[c0 + e];
#pragma unroll
            for (int t = 0; t < 3; t++)
#pragma unroll
                for (int i2 = 0; i2 < 11; i2++) {
                    float ft = ob[t * 47 + BIDX[i2]];
                    const float* w = (const float*)(sm + OFF_WEB) + (t * 11 + i2) * H + c0;
#pragma unroll
                    for (int e = 0; e < 8; e++) acc[e] = fmaf(ft, w[e], acc[e]);
                }
        } else {
            int j = n - 1;
            const float* be = (const float*)(sm + OFF_BIAS + BO_BEJ);
#pragma unroll
            for (int e = 0; e < 8; e++) acc[e] = be[c0 + e];
#pragma unroll
            for (int f = 0; f < 9; f++) {
                float ft = ob[(f / 3) * 47 + 9 + (f % 3) * 12 + j];
                const float* w = (const float*)(sm + OFF_WEJ) + f * H + c0;
#pragma unroll
                for (int e = 0; e < 8; e++) acc[e] = fmaf(ft, w[e], acc[e]);
            }
        }
#pragma unroll
        for (int e = 0; e < 8; e++) acc[e] = elu1(acc[e]);
        store8h(sm, doff, acc);
    }

    // ---- layers:  x' = elu( S·(X@Wrel^T) + X@Wroot^T + b ) ----
    for (int l = 0; l < NLAYER; l++) {
        __syncthreads();  // X(l) + W(l) ready; Z1 free of readers

        // merged dual single-term GEMM over 16Mx32N tile:
        //   acc1 = X@W1^T, acc2 = X@W2^T, A fragments shared
        float acc1[2][2][4], acc2[2][2][4];   // [nt][hh][4]
#pragma unroll
        for (int nt = 0; nt < 2; nt++)
#pragma unroll
            for (int hh = 0; hh < 2; hh++)
#pragma unroll
                for (int e = 0; e < 4; e++) { acc1[nt][hh][e] = 0.f; acc2[nt][hh][e] = 0.f; }
        {
            const uint32_t arow = (uint32_t)(lane & 15);
            const uint32_t acol = (uint32_t)((lane >> 4) << 4);
            const uint32_t brow = (uint32_t)((lane & 7) + ((lane >> 4) << 3));
            const uint32_t bcol = (uint32_t)(((lane >> 3) & 1) << 4);
            const uint32_t aH0 = sb + OFF_XH + ((uint32_t)m0 + arow) * PITCHB + acol;
            const uint32_t bro = ((uint32_t)n0 + brow) * PITCHB + bcol;
            const uint32_t b10 = sb + OFF_W1 + bro;
            const uint32_t b20 = sb + OFF_W2 + bro;
#pragma unroll 4
            for (int k = 0; k < 8; k++) {
                const uint32_t kb = (uint32_t)k * 32u;
                uint32_t ah[4];
                ldsm4(ah[0], ah[1], ah[2], ah[3], aH0 + kb);
#pragma unroll
                for (int nt = 0; nt < 2; nt++) {
                    const uint32_t noff = (uint32_t)nt * (16u * PITCHB) + kb;
                    uint32_t w0, w1, w2, w3;
                    ldsm4(w0, w1, w2, w3, b10 + noff);
                    mma16816(acc1[nt][0], ah, w0, w1);
                    mma16816(acc1[nt][1], ah, w2, w3);
                    ldsm4(w0, w1, w2, w3, b20 + noff);
                    mma16816(acc2[nt][0], ah, w0, w1);
                    mma16816(acc2[nt][1], ah, w2, w3);
                }
            }
        }

        // spill Z1 (fp32) into its own buffer
        {
            float* z1 = (float*)(sm + OFF_Z1);
            const int r0 = m0 + (lane >> 2);
            const int cb = n0 + 2 * (lane & 3);
#pragma unroll
            for (int nt = 0; nt < 2; nt++)
#pragma unroll
                for (int hh = 0; hh < 2; hh++) {
                    const int col = cb + nt * 16 + hh * 8;
                    *(float2*)&z1[(uint32_t)r0 * PITCHZ + col] =
                        make_float2(acc1[nt][hh][0], acc1[nt][hh][1]);
                    *(float2*)&z1[(uint32_t)(r0 + 8) * PITCHZ + col] =
                        make_float2(acc1[nt][hh][2], acc1[nt][hh][3]);
                }
        }
        __syncthreads();  // Z1 complete; all GEMM X/W reads done

        // fused epilogue: x' = elu( S·Z1 + Z2 + b )
        // last layer stores fp32 (spans XH + scratch); others store fp16
        {
            const float* z1  = (const float*)(sm + OFF_Z1);
            float* xf        = (float*)(sm + OFF_XH);   // fp32 view for last layer
            const float* brl = (const float*)(sm + OFF_BIAS + BO_BREL) + l * H;
            const int r0 = m0 + (lane >> 2);
            const int cb = n0 + 2 * (lane & 3);
            const bool last = (l == NLAYER - 1);
#pragma unroll
            for (int half = 0; half < 2; half++) {
                const int r = r0 + half * 8;
                if (r >= rows_real) continue;
                const int g  = r / NNODE;
                const int n  = r - g * NNODE;
                const int gb = g * NNODE;
                const int cnt = NSRC[n];
#pragma unroll
                for (int nt = 0; nt < 2; nt++)
#pragma unroll
                    for (int hh = 0; hh < 2; hh++) {
                        const int col = cb + nt * 16 + hh * 8;
                        float v0 = acc2[nt][hh][2 * half]     + brl[col];
                        float v1 = acc2[nt][hh][2 * half + 1] + brl[col + 1];
                        for (int k2 = 0; k2 < cnt; k2++) {
                            const float* zr = &z1[(uint32_t)(gb + SRCS[n][k2]) * PITCHZ + col];
                            v0 += zr[0];
                            v1 += zr[1];
                        }
                        v0 = elu1(v0);
                        v1 = elu1(v1);
                        if (last) {
                            *(float2*)&xf[(uint32_t)r * PITCHZ + col] = make_float2(v0, v1);
                        } else {
                            *(uint32_t*)(sm + OFF_XH + (uint32_t)r * PITCHB + (uint32_t)col * 2) =
                                cvtpack(v0, v1);
                        }
                    }
            }
        }

        // stage W(l+1) in the same phase (W buffers idle during epilogue)
        if (l + 1 < NLAYER) {
            const uint4* rel = (const uint4*)&g_wh[l + 1][0][0];
            const uint4* roo = (const uint4*)&g_wh[l + 1][1][0];
            for (int idx = tid; idx < H * 16; idx += NTHREADS) {
                uint32_t d = (uint32_t)(idx >> 4) * PITCHB + (uint32_t)(idx & 15) * 16;
                *(uint4*)(sm + OFF_W1 + d) = rel[idx];
                *(uint4*)(sm + OFF_W2 + d) = roo[idx];
            }
        }
    }
    __syncthreads();

    // ---- decoder (final X is fp32 at OFF_XH, pitch PITCHZ) ----
    if (tid < ng * NJN) {
        int g = tid / NJN, j = tid - g * NJN;
        const float* xf = (const float*)(sm + OFF_XH) + (uint32_t)(g * NNODE + 1 + j) * PITCHZ;
        const float* wd = (const float*)(sm + OFF_BIAS + BO_WDEC);
        float acc = ((const float*)(sm + OFF_BIAS + BO_BDEC))[0];
#pragma unroll 4
        for (int c = 0; c < H; c += 4) {
            float4 x4 = *(const float4*)&xf[c];
            float4 w4 = *(const float4*)&wd[c];
            acc = fmaf(x4.x, w4.x, acc);
            acc = fmaf(x4.y, w4.y, acc);
            acc = fmaf(x4.z, w4.z, acc);
            acc = fmaf(x4.w, w4.w, acc);
        }
        out[(size_t)(g0 + g) * NJN + j] = acc;
    }
}

extern "C" void kernel_launch(void* const* d_in, const int* in_sizes, int n_in,
                              void* d_out, int out_size)
{
    const float* obs    = (const float*)d_in[0];
    const float* We_b   = (const float*)d_in[1];
    const float* be_b   = (const float*)d_in[2];
    const float* We_j   = (const float*)d_in[3];
    const float* be_j   = (const float*)d_in[4];
    const float* W_rel  = (const float*)d_in[5];
    const float* W_root = (const float*)d_in[6];
    const float* b_rel  = (const float*)d_in[7];
    const float* W_dec  = (const float*)d_in[8];
    const float* b_dec  = (const float*)d_in[9];
    float*       out    = (float*)d_out;

    const int B = in_sizes[0] / OBS_LEN;

    conv_weights_kernel<<<(NLAYER * 2 * H * H + 255) / 256, 256>>>(W_rel, W_root);

    const int ntiles = (B + GPT - 1) / GPT;
    cudaFuncSetAttribute(gnn_mma_kernel,
                         cudaFuncAttributeMaxDynamicSharedMemorySize, (int)SMEM_DYN);
    gnn_mma_kernel<<<ntiles, NTHREADS, SMEM_DYN>>>(
        obs, We_b, be_b, We_j, be_j, b_rel, W_dec, b_dec, out, B);
}

// round 12
// speedup vs baseline: 2.8523x; 1.1267x over previous
#include <cuda_runtime.h>
#include <cuda_fp16.h>
#include <stdint.h>
#include <math.h>

namespace {
constexpr int H = 128, NNODE = 13, NJN = 12, OBS_LEN = 141, NLAYER = 3;
constexpr int GPT = 9;               // graphs per CTA -> 117 rows, padded to 128
constexpr int MROWS = 128;
constexpr int NTHREADS = 1024;       // 32 warps: 4 M-slices x 8 N-slices
constexpr int BASE_F = 33, JOINT_F = 9;

constexpr uint32_t PITCHB = 272;     // fp16 row: 128 elems + 8 pad (conflict-free ldmatrix)
constexpr uint32_t MATB   = MROWS * PITCHB;        // 34816
constexpr uint32_t PITCHZ = 132;     // fp32 row pitch (floats)

constexpr uint32_t OFF_XH  = 0;      // X fp16; last layer spills fp32 here (+ overflow below)
constexpr uint32_t OFF_SCR = MATB;   // scratch (last-layer fp32 X overflow)
constexpr uint32_t OFF_W1  = 2 * MATB;             // W_rel fp16
constexpr uint32_t OFF_W2  = 3 * MATB;             // W_root fp16
constexpr uint32_t OFF_Z1  = 4 * MATB;             // fp32 Z1 (67584 B); enc weights pre-layer0
constexpr uint32_t OFF_OBS = OFF_Z1 + 67584;
constexpr uint32_t OFF_BIAS = OFF_OBS + GPT * 144 * 4;
constexpr uint32_t BO_BEB = 0, BO_BEJ = 512, BO_BREL = 1024, BO_WDEC = 2560, BO_BDEC = 3072;
constexpr uint32_t OFF_WEB = OFF_Z1;               // encoder weights (pre-layer0 only)
constexpr uint32_t OFF_WEJ = OFF_Z1 + 16896;
constexpr uint32_t SMEM_DYN = OFF_BIAS + 3104;     // ~210.1 KB

__device__ __constant__ int8_t NSRC[13] = {4,2,2,1,2,2,1,2,2,1,2,2,1};
__device__ __constant__ int8_t SRCS[13][4] = {
    {1,4,7,10},{0,2,0,0},{1,3,0,0},{2,0,0,0},{0,5,0,0},{4,6,0,0},{5,0,0,0},
    {0,8,0,0},{7,9,0,0},{8,0,0,0},{0,11,0,0},{10,12,0,0},{11,0,0,0}};
__device__ __constant__ int8_t BIDX[11] = {0,1,2,3,4,5,6,7,8,45,46};

// fp16 weights: [layer][rel=0/root=1][n*128+k]
__device__ __half g_wh[NLAYER][2][H * H];

__device__ __forceinline__ uint32_t smem_u32(const void* p) {
    uint32_t a;
    asm("{ .reg .u64 t; cvta.to.shared.u64 t, %1; cvt.u32.u64 %0, t; }" : "=r"(a) : "l"(p));
    return a;
}
// fast ELU: exp via MUFU.EX2 (error ~1e-7 abs on (0,1] — far under precision budget)
__device__ __forceinline__ float elu1(float v) { return v > 0.f ? v : __expf(v) - 1.f; }

__device__ __forceinline__ void ldsm4(uint32_t& r0, uint32_t& r1, uint32_t& r2, uint32_t& r3,
                                      uint32_t addr) {
    asm volatile("ldmatrix.sync.aligned.m8n8.x4.shared.b16 {%0,%1,%2,%3}, [%4];"
                 : "=r"(r0), "=r"(r1), "=r"(r2), "=r"(r3) : "r"(addr));
}
__device__ __forceinline__ void mma16816(float* c, const uint32_t* a, uint32_t b0, uint32_t b1) {
    asm volatile(
        "mma.sync.aligned.m16n8k16.row.col.f32.f16.f16.f32 "
        "{%0,%1,%2,%3}, {%4,%5,%6,%7}, {%8,%9}, {%0,%1,%2,%3};"
        : "+f"(c[0]), "+f"(c[1]), "+f"(c[2]), "+f"(c[3])
        : "r"(a[0]), "r"(a[1]), "r"(a[2]), "r"(a[3]), "r"(b0), "r"(b1));
}

// packed f32x2 -> f16x2 (low half = first arg; PTX puts first source in HIGH half)
__device__ __forceinline__ uint32_t cvtpack(float lo, float hi) {
    uint32_t r;
    asm("cvt.rn.f16x2.f32 %0, %1, %2;" : "=r"(r) : "f"(hi), "f"(lo));
    return r;
}
__device__ __forceinline__ void store8h(char* sm, uint32_t doff, const float* v) {
    uint4 hh;
    uint32_t* ph = (uint32_t*)&hh;
#pragma unroll
    for (int k = 0; k < 4; k++) ph[k] = cvtpack(v[2 * k], v[2 * k + 1]);
    *(uint4*)(sm + OFF_XH + doff) = hh;
}
} // namespace

__global__ void conv_weights_kernel(const float* __restrict__ W_rel,
                                    const float* __restrict__ W_root) {
    int i = blockIdx.x * blockDim.x + threadIdx.x;
    if (i >= NLAYER * 2 * H * H) return;
    int l = i / (2 * H * H);
    int r = i % (2 * H * H);
    int g = r / (H * H);
    int e = r % (H * H);
    float w = (g == 0) ? W_rel[l * H * H + e] : W_root[l * H * H + e];
    g_wh[l][g][e] = __float2half_rn(w);
}

__global__ __launch_bounds__(NTHREADS, 1) void gnn_mma_kernel(
    const float* __restrict__ obs,
    const float* __restrict__ We_b, const float* __restrict__ be_b,
    const float* __restrict__ We_j, const float* __restrict__ be_j,
    const float* __restrict__ b_rel,
    const float* __restrict__ W_dec, const float* __restrict__ b_dec,
    float* __restrict__ out, int B)
{
    extern __shared__ char sm[];
    const uint32_t sb = smem_u32(sm);
    const int tid = threadIdx.x, lane = tid & 31, wid = tid >> 5;
    const int m0 = (wid >> 3) * 32;          // 32-row slice (4 slices)
    const int n0 = (wid & 7) * 16;           // 16-col slice (8 slices)
    const int g0 = blockIdx.x * GPT;
    const int ng = min(GPT, B - g0);
    const int rows_real = ng * NNODE;

    // ---- stage biases / encoder weights (transposed, in Z1 area) / obs ----
    if (tid < H) {
        ((float*)(sm + OFF_BIAS + BO_BEB))[tid]  = be_b[tid];
        ((float*)(sm + OFF_BIAS + BO_BEJ))[tid]  = be_j[tid];
        ((float*)(sm + OFF_BIAS + BO_WDEC))[tid] = W_dec[tid];
    }
    if (tid >= H && tid < H + NLAYER * H)
        ((float*)(sm + OFF_BIAS + BO_BREL))[tid - H] = b_rel[tid - H];
    if (tid == 0) ((float*)(sm + OFF_BIAS + BO_BDEC))[0] = b_dec[0];
    for (int i = tid; i < H * BASE_F; i += NTHREADS) {
        int h = i / BASE_F, f = i - h * BASE_F;
        ((float*)(sm + OFF_WEB))[f * H + h] = We_b[i];
    }
    for (int i = tid; i < H * JOINT_F; i += NTHREADS) {
        int h = i / JOINT_F, f = i - h * JOINT_F;
        ((float*)(sm + OFF_WEJ))[f * H + h] = We_j[i];
    }
    for (int i = tid; i < ng * OBS_LEN; i += NTHREADS) {
        int g = i / OBS_LEN, k = i - g * OBS_LEN;
        ((float*)(sm + OFF_OBS))[g * 144 + k] = obs[(size_t)(g0 + g) * OBS_LEN + k];
    }
    __syncthreads();

    // ---- phase A: encoder (X fp16) + stage W(0) concurrently ----
    {
        const uint4* rel = (const uint4*)&g_wh[0][0][0];
        const uint4* roo = (const uint4*)&g_wh[0][1][0];
        for (int idx = tid; idx < H * 16; idx += NTHREADS) {
            uint32_t d = (uint32_t)(idx >> 4) * PITCHB + (uint32_t)(idx & 15) * 16;
            *(uint4*)(sm + OFF_W1 + d) = rel[idx];
            *(uint4*)(sm + OFF_W2 + d) = roo[idx];
        }
    }
    for (int idx = tid; idx < MROWS * 16; idx += NTHREADS) {
        int row = idx >> 4, c0 = (idx & 15) << 3;
        uint32_t doff = (uint32_t)row * PITCHB + (uint32_t)c0 * 2;
        if (row >= rows_real) {
            *(uint4*)(sm + OFF_XH + doff) = make_uint4(0, 0, 0, 0);
            continue;
        }
        int g = row / NNODE, n = row - g * NNODE;
        const float* ob = (const float*)(sm + OFF_OBS) + g * 144;
        float acc[8];
        if (n == 0) {
            const float* be = (const float*)(sm + OFF_BIAS + BO_BEB);
#pragma unroll
            for (int e = 0; e < 8; e++) acc[e] = be[c0 + e];
#pragma unroll
            for (int t = 0; t < 3; t++)
#pragma unroll
                for (int i2 = 0; i2 < 11; i2++) {
                    float ft = ob[t * 47 + BIDX[i2]];
                    const float* w = (const float*)(sm + OFF_WEB) + (t * 11 + i2) * H + c0;
#pragma unroll
                    for (int e = 0; e < 8; e++) acc[e] = fmaf(ft, w[e], acc[e]);
                }
        } else {
            int j = n - 1;
            const float* be = (const float*)(sm + OFF_BIAS + BO_BEJ);
#pragma unroll
            for (int e = 0; e < 8; e++) acc[e] = be[c0 + e];
#pragma unroll
            for (int f = 0; f < 9; f++) {
                float ft = ob[(f / 3) * 47 + 9 + (f % 3) * 12 + j];
                const float* w = (const float*)(sm + OFF_WEJ) + f * H + c0;
#pragma unroll
                for (int e = 0; e < 8; e++) acc[e] = fmaf(ft, w[e], acc[e]);
            }
        }
#pragma unroll
        for (int e = 0; e < 8; e++) acc[e] = elu1(acc[e]);
        store8h(sm, doff, acc);
    }

    // ---- layers:  x' = elu( S·(X@Wrel^T) + X@Wroot^T + b ) ----
    for (int l = 0; l < NLAYER; l++) {
        __syncthreads();  // X(l) + W(l) ready; Z1 free of readers

        // merged dual single-term GEMM over 32Mx16N tile:
        //   acc1 = X@W1^T, acc2 = X@W2^T; A fragments shared across mats
        float acc1[2][2][4], acc2[2][2][4];   // [mt][ns][4]
#pragma unroll
        for (int mt = 0; mt < 2; mt++)
#pragma unroll
            for (int ns = 0; ns < 2; ns++)
#pragma unroll
                for (int e = 0; e < 4; e++) { acc1[mt][ns][e] = 0.f; acc2[mt][ns][e] = 0.f; }
        {
            const uint32_t arow = (uint32_t)(lane & 15);
            const uint32_t acol = (uint32_t)((lane >> 4) << 4);
            const uint32_t brow = (uint32_t)((lane & 7) + ((lane >> 4) << 3));
            const uint32_t bcol = (uint32_t)(((lane >> 3) & 1) << 4);
            const uint32_t aH0 = sb + OFF_XH + ((uint32_t)m0 + arow) * PITCHB + acol;
            const uint32_t bro = ((uint32_t)n0 + brow) * PITCHB + bcol;
            const uint32_t b10 = sb + OFF_W1 + bro;
            const uint32_t b20 = sb + OFF_W2 + bro;
#pragma unroll 2
            for (int k = 0; k < 8; k++) {
                const uint32_t kb = (uint32_t)k * 32u;
                uint32_t ah[2][4];
                ldsm4(ah[0][0], ah[0][1], ah[0][2], ah[0][3], aH0 + kb);
                ldsm4(ah[1][0], ah[1][1], ah[1][2], ah[1][3], aH0 + 16u * PITCHB + kb);
                uint32_t w0, w1, w2, w3;
                ldsm4(w0, w1, w2, w3, b10 + kb);
#pragma unroll
                for (int mt = 0; mt < 2; mt++) {
                    mma16816(acc1[mt][0], ah[mt], w0, w1);
                    mma16816(acc1[mt][1], ah[mt], w2, w3);
                }
                ldsm4(w0, w1, w2, w3, b20 + kb);
#pragma unroll
                for (int mt = 0; mt < 2; mt++) {
                    mma16816(acc2[mt][0], ah[mt], w0, w1);
                    mma16816(acc2[mt][1], ah[mt], w2, w3);
                }
            }
        }

        // spill Z1 (fp32) into its own buffer
        {
            float* z1 = (float*)(sm + OFF_Z1);
            const int r0 = m0 + (lane >> 2);
            const int cb = n0 + 2 * (lane & 3);
#pragma unroll
            for (int mt = 0; mt < 2; mt++)
#pragma unroll
                for (int ns = 0; ns < 2; ns++) {
                    const int col = cb + ns * 8;
                    const int r = r0 + mt * 16;
                    *(float2*)&z1[(uint32_t)r * PITCHZ + col] =
                        make_float2(acc1[mt][ns][0], acc1[mt][ns][1]);
                    *(float2*)&z1[(uint32_t)(r + 8) * PITCHZ + col] =
                        make_float2(acc1[mt][ns][2], acc1[mt][ns][3]);
                }
        }
        __syncthreads();  // Z1 complete; all GEMM X/W reads done

        // fused epilogue: x' = elu( S·Z1 + Z2 + b )
        // last layer stores fp32 (spans XH + scratch); others store fp16
        {
            const float* z1  = (const float*)(sm + OFF_Z1);
            float* xf        = (float*)(sm + OFF_XH);   // fp32 view for last layer
            const float* brl = (const float*)(sm + OFF_BIAS + BO_BREL) + l * H;
            const int r0 = m0 + (lane >> 2);
            const int cb = n0 + 2 * (lane & 3);
            const bool last = (l == NLAYER - 1);
#pragma unroll
            for (int mt = 0; mt < 2; mt++)
#pragma unroll
                for (int half = 0; half < 2; half++) {
                    const int r = r0 + mt * 16 + half * 8;
                    if (r >= rows_real) continue;
                    const int g  = r / NNODE;
                    const int n  = r - g * NNODE;
                    const int gb = g * NNODE;
                    const int cnt = NSRC[n];
#pragma unroll
                    for (int ns = 0; ns < 2; ns++) {
                        const int col = cb + ns * 8;
                        float v0 = acc2[mt][ns][2 * half]     + brl[col];
                        float v1 = acc2[mt][ns][2 * half + 1] + brl[col + 1];
                        for (int k2 = 0; k2 < cnt; k2++) {
                            const float* zr = &z1[(uint32_t)(gb + SRCS[n][k2]) * PITCHZ + col];
                            v0 += zr[0];
                            v1 += zr[1];
                        }
                        v0 = elu1(v0);
                        v1 = elu1(v1);
                        if (last) {
                            *(float2*)&xf[(uint32_t)r * PITCHZ + col] = make_float2(v0, v1);
                        } else {
                            *(uint32_t*)(sm + OFF_XH + (uint32_t)r * PITCHB + (uint32_t)col * 2) =
                                cvtpack(v0, v1);
                        }
                    }
                }
        }

        // stage W(l+1) in the same phase (W buffers idle during epilogue)
        if (l + 1 < NLAYER) {
            const uint4* rel = (const uint4*)&g_wh[l + 1][0][0];
            const uint4* roo = (const uint4*)&g_wh[l + 1][1][0];
            for (int idx = tid; idx < H * 16; idx += NTHREADS) {
                uint32_t d = (uint32_t)(idx >> 4) * PITCHB + (uint32_t)(idx & 15) * 16;
                *(uint4*)(sm + OFF_W1 + d) = rel[idx];
                *(uint4*)(sm + OFF_W2 + d) = roo[idx];
            }
        }
    }
    __syncthreads();

    // ---- decoder (final X is fp32 at OFF_XH, pitch PITCHZ) ----
    if (tid < ng * NJN) {
        int g = tid / NJN, j = tid - g * NJN;
        const float* xf = (const float*)(sm + OFF_XH) + (uint32_t)(g * NNODE + 1 + j) * PITCHZ;
        const float* wd = (const float*)(sm + OFF_BIAS + BO_WDEC);
        float acc = ((const float*)(sm + OFF_BIAS + BO_BDEC))[0];
#pragma unroll 4
        for (int c = 0; c < H; c += 4) {
            float4 x4 = *(const float4*)&xf[c];
            float4 w4 = *(const float4*)&wd[c];
            acc = fmaf(x4.x, w4.x, acc);
            acc = fmaf(x4.y, w4.y, acc);
            acc = fmaf(x4.z, w4.z, acc);
            acc = fmaf(x4.w, w4.w, acc);
        }
        out[(size_t)(g0 + g) * NJN + j] = acc;
    }
}

extern "C" void kernel_launch(void* const* d_in, const int* in_sizes, int n_in,
                              void* d_out, int out_size)
{
    const float* obs    = (const float*)d_in[0];
    const float* We_b   = (const float*)d_in[1];
    const float* be_b   = (const float*)d_in[2];
    const float* We_j   = (const float*)d_in[3];
    const float* be_j   = (const float*)d_in[4];
    const float* W_rel  = (const float*)d_in[5];
    const float* W_root = (const float*)d_in[6];
    const float* b_rel  = (const float*)d_in[7];
    const float* W_dec  = (const float*)d_in[8];
    const float* b_dec  = (const float*)d_in[9];
    float*       out    = (float*)d_out;

    const int B = in_sizes[0] / OBS_LEN;

    conv_weights_kernel<<<(NLAYER * 2 * H * H + 255) / 256, 256>>>(W_rel, W_root);

    const int ntiles = (B + GPT - 1) / GPT;
    cudaFuncSetAttribute(gnn_mma_kernel,
                         cudaFuncAttributeMaxDynamicSharedMemorySize, (int)SMEM_DYN);
    gnn_mma_kernel<<<ntiles, NTHREADS, SMEM_DYN>>>(
        obs, We_b, be_b, We_j, be_j, b_rel, W_dec, b_dec, out, B);
}

// round 13
// speedup vs baseline: 3.8674x; 1.3559x over previous
#include <cuda_runtime.h>
#include <cuda_fp16.h>
#include <stdint.h>
#include <math.h>

namespace {
constexpr int H = 128, NNODE = 13, NJN = 12, OBS_LEN = 141, NLAYER = 3;
constexpr int GPT = 9;               // graphs per CTA -> 117 rows, padded to 128
constexpr int MROWS = 128;
constexpr int NTHREADS = 1024;       // 32 warps: 4 M-slices x 8 N-slices
constexpr int BASE_F = 33, JOINT_F = 9;

constexpr uint32_t PITCHB = 272;     // fp16 row: 128 elems + 8 pad (conflict-free ld/stmatrix)
constexpr uint32_t MATB   = MROWS * PITCHB;        // 34816

constexpr uint32_t OFF_XH  = 0;              // X fp16 (all layers; decoder reads fp16)
constexpr uint32_t OFF_Z1H = MATB;           // Z1 hi fp16
constexpr uint32_t OFF_Z1L = 2 * MATB;       // Z1 lo fp16 (hi/lo keeps agg path ~fp32)
constexpr uint32_t OFF_Z2  = 3 * MATB;       // Z2 fp16
constexpr uint32_t OFF_W1  = 4 * MATB;       // W_rel fp16
constexpr uint32_t OFF_W2  = 5 * MATB;       // W_root fp16
constexpr uint32_t OFF_OBS = 6 * MATB;
constexpr uint32_t OFF_BIAS = OFF_OBS + GPT * 144 * 4;
constexpr uint32_t BO_BEB = 0, BO_BEJ = 512, BO_BREL = 1024, BO_WDEC = 2560, BO_BDEC = 3072;
constexpr uint32_t OFF_WEB = OFF_Z1H;        // encoder weights (pre-layer0, in Z1 area)
constexpr uint32_t OFF_WEJ = OFF_Z1H + 16896;
constexpr uint32_t SMEM_DYN = OFF_BIAS + 3104;     // ~212.1 KB

__device__ __constant__ int8_t NSRC[13] = {4,2,2,1,2,2,1,2,2,1,2,2,1};
__device__ __constant__ int8_t SRCS[13][4] = {
    {1,4,7,10},{0,2,0,0},{1,3,0,0},{2,0,0,0},{0,5,0,0},{4,6,0,0},{5,0,0,0},
    {0,8,0,0},{7,9,0,0},{8,0,0,0},{0,11,0,0},{10,12,0,0},{11,0,0,0}};
__device__ __constant__ int8_t BIDX[11] = {0,1,2,3,4,5,6,7,8,45,46};

__device__ __half g_wh[NLAYER][2][H * H];    // fp16 weights [layer][rel/root][n*128+k]

__device__ __forceinline__ uint32_t smem_u32(const void* p) {
    uint32_t a;
    asm("{ .reg .u64 t; cvta.to.shared.u64 t, %1; cvt.u32.u64 %0, t; }" : "=r"(a) : "l"(p));
    return a;
}
__device__ __forceinline__ float elu1(float v) { return v > 0.f ? v : __expf(v) - 1.f; }

__device__ __forceinline__ void ldsm4(uint32_t& r0, uint32_t& r1, uint32_t& r2, uint32_t& r3,
                                      uint32_t addr) {
    asm volatile("ldmatrix.sync.aligned.m8n8.x4.shared.b16 {%0,%1,%2,%3}, [%4];"
                 : "=r"(r0), "=r"(r1), "=r"(r2), "=r"(r3) : "r"(addr));
}
__device__ __forceinline__ void stsm4(uint32_t addr, uint32_t r0, uint32_t r1,
                                      uint32_t r2, uint32_t r3) {
    asm volatile("stmatrix.sync.aligned.m8n8.x4.shared.b16 [%0], {%1,%2,%3,%4};"
                 :: "r"(addr), "r"(r0), "r"(r1), "r"(r2), "r"(r3) : "memory");
}
__device__ __forceinline__ void mma16816(float* c, const uint32_t* a, uint32_t b0, uint32_t b1) {
    asm volatile(
        "mma.sync.aligned.m16n8k16.row.col.f32.f16.f16.f32 "
        "{%0,%1,%2,%3}, {%4,%5,%6,%7}, {%8,%9}, {%0,%1,%2,%3};"
        : "+f"(c[0]), "+f"(c[1]), "+f"(c[2]), "+f"(c[3])
        : "r"(a[0]), "r"(a[1]), "r"(a[2]), "r"(a[3]), "r"(b0), "r"(b1));
}

// packed f32x2 -> f16x2 (low half = first arg; PTX puts first source in HIGH half)
__device__ __forceinline__ uint32_t cvtpack(float lo, float hi) {
    uint32_t r;
    asm("cvt.rn.f16x2.f32 %0, %1, %2;" : "=r"(r) : "f"(hi), "f"(lo));
    return r;
}
__device__ __forceinline__ uint32_t lopack(float a, float b, uint32_t hh) {
    float2 back = __half22float2(*reinterpret_cast<__half2*>(&hh));
    return cvtpack(a - back.x, b - back.y);
}
__device__ __forceinline__ void store8h(char* sm, uint32_t doff, const float* v) {
    uint4 hh;
    uint32_t* ph = (uint32_t*)&hh;
#pragma unroll
    for (int k = 0; k < 4; k++) ph[k] = cvtpack(v[2 * k], v[2 * k + 1]);
    *(uint4*)(sm + OFF_XH + doff) = hh;
}
// v[0..7] += 8 fp16 values packed in a uint4
__device__ __forceinline__ void addu4h(float* v, uint4 p) {
    const uint32_t* w = (const uint32_t*)&p;
#pragma unroll
    for (int k = 0; k < 4; k++) {
        float2 f = __half22float2(*reinterpret_cast<const __half2*>(&w[k]));
        v[2 * k] += f.x;
        v[2 * k + 1] += f.y;
    }
}
} // namespace

__global__ void conv_weights_kernel(const float* __restrict__ W_rel,
                                    const float* __restrict__ W_root) {
    int i = blockIdx.x * blockDim.x + threadIdx.x;
    if (i >= NLAYER * 2 * H * H) return;
    int l = i / (2 * H * H);
    int r = i % (2 * H * H);
    int g = r / (H * H);
    int e = r % (H * H);
    float w = (g == 0) ? W_rel[l * H * H + e] : W_root[l * H * H + e];
    g_wh[l][g][e] = __float2half_rn(w);
}

__global__ __launch_bounds__(NTHREADS, 1) void gnn_mma_kernel(
    const float* __restrict__ obs,
    const float* __restrict__ We_b, const float* __restrict__ be_b,
    const float* __restrict__ We_j, const float* __restrict__ be_j,
    const float* __restrict__ b_rel,
    const float* __restrict__ W_dec, const float* __restrict__ b_dec,
    float* __restrict__ out, int B)
{
    extern __shared__ char sm[];
    const uint32_t sb = smem_u32(sm);
    const int tid = threadIdx.x, lane = tid & 31, wid = tid >> 5;
    const int m0 = (wid >> 3) * 32;          // 32-row slice (4 slices)
    const int n0 = (wid & 7) * 16;           // 16-col slice (8 slices)
    const int g0 = blockIdx.x * GPT;
    const int ng = min(GPT, B - g0);
    const int rows_real = ng * NNODE;

    // ---- stage biases / encoder weights / obs ----
    if (tid < H) {
        ((float*)(sm + OFF_BIAS + BO_BEB))[tid]  = be_b[tid];
        ((float*)(sm + OFF_BIAS + BO_BEJ))[tid]  = be_j[tid];
        ((float*)(sm + OFF_BIAS + BO_WDEC))[tid] = W_dec[tid];
    }
    if (tid >= H && tid < H + NLAYER * H)
        ((float*)(sm + OFF_BIAS + BO_BREL))[tid - H] = b_rel[tid - H];
    if (tid == 0) ((float*)(sm + OFF_BIAS + BO_BDEC))[0] = b_dec[0];
    for (int i = tid; i < H * BASE_F; i += NTHREADS) {
        int h = i / BASE_F, f = i - h * BASE_F;
        ((float*)(sm + OFF_WEB))[f * H + h] = We_b[i];
    }
    for (int i = tid; i < H * JOINT_F; i += NTHREADS) {
        int h = i / JOINT_F, f = i - h * JOINT_F;
        ((float*)(sm + OFF_WEJ))[f * H + h] = We_j[i];
    }
    for (int i = tid; i < ng * OBS_LEN; i += NTHREADS) {
        int g = i / OBS_LEN, k = i - g * OBS_LEN;
        ((float*)(sm + OFF_OBS))[g * 144 + k] = obs[(size_t)(g0 + g) * OBS_LEN + k];
    }
    __syncthreads();

    // ---- phase A: encoder (X fp16) + stage W(0) concurrently ----
    {
        const uint4* rel = (const uint4*)&g_wh[0][0][0];
        const uint4* roo = (const uint4*)&g_wh[0][1][0];
        for (int idx = tid; idx < H * 16; idx += NTHREADS) {
            uint32_t d = (uint32_t)(idx >> 4) * PITCHB + (uint32_t)(idx & 15) * 16;
            *(uint4*)(sm + OFF_W1 + d) = rel[idx];
            *(uint4*)(sm + OFF_W2 + d) = roo[idx];
        }
    }
    for (int idx = tid; idx < MROWS * 16; idx += NTHREADS) {
        int row = idx >> 4, c0 = (idx & 15) << 3;
        uint32_t doff = (uint32_t)row * PITCHB + (uint32_t)c0 * 2;
        if (row >= rows_real) {
            *(uint4*)(sm + OFF_XH + doff) = make_uint4(0, 0, 0, 0);
            continue;
        }
        int g = row / NNODE, n = row - g * NNODE;
        const float* ob = (const float*)(sm + OFF_OBS) + g * 144;
        float acc[8];
        if (n == 0) {
            const float* be = (const float*)(sm + OFF_BIAS + BO_BEB);
#pragma unroll
            for (int e = 0; e < 8; e++) acc[e] = be[c0 + e];
#pragma unroll
            for (int t = 0; t < 3; t++)
#pragma unroll
                for (int i2 = 0; i2 < 11; i2++) {
                    float ft = ob[t * 47 + BIDX[i2]];
                    const float* w = (const float*)(sm + OFF_WEB) + (t * 11 + i2) * H + c0;
#pragma unroll
                    for (int e = 0; e < 8; e++) acc[e] = fmaf(ft, w[e], acc[e]);
                }
        } else {
            int j = n - 1;
            const float* be = (const float*)(sm + OFF_BIAS + BO_BEJ);
#pragma unroll
            for (int e = 0; e < 8; e++) acc[e] = be[c0 + e];
#pragma unroll
            for (int f = 0; f < 9; f++) {
                float ft = ob[(f / 3) * 47 + 9 + (f % 3) * 12 + j];
                const float* w = (const float*)(sm + OFF_WEJ) + f * H + c0;
#pragma unroll
                for (int e = 0; e < 8; e++) acc[e] = fmaf(ft, w[e], acc[e]);
            }
        }
#pragma unroll
        for (int e = 0; e < 8; e++) acc[e] = elu1(acc[e]);
        store8h(sm, doff, acc);
    }

    // ---- layers:  x' = elu( S·(X@Wrel^T) + X@Wroot^T + b ) ----
    for (int l = 0; l < NLAYER; l++) {
        __syncthreads();  // X(l)+W(l) ready; prev pass's Z reads done

        // merged dual single-term GEMM over 32Mx16N tile
        float acc1[2][2][4], acc2[2][2][4];   // [mt][ns][4]
#pragma unroll
        for (int mt = 0; mt < 2; mt++)
#pragma unroll
            for (int ns = 0; ns < 2; ns++)
#pragma unroll
                for (int e = 0; e < 4; e++) { acc1[mt][ns][e] = 0.f; acc2[mt][ns][e] = 0.f; }
        {
            const uint32_t arow = (uint32_t)(lane & 15);
            const uint32_t acol = (uint32_t)((lane >> 4) << 4);
            const uint32_t brow = (uint32_t)((lane & 7) + ((lane >> 4) << 3));
            const uint32_t bcol = (uint32_t)(((lane >> 3) & 1) << 4);
            const uint32_t aH0 = sb + OFF_XH + ((uint32_t)m0 + arow) * PITCHB + acol;
            const uint32_t bro = ((uint32_t)n0 + brow) * PITCHB + bcol;
            const uint32_t b10 = sb + OFF_W1 + bro;
            const uint32_t b20 = sb + OFF_W2 + bro;
#pragma unroll 2
            for (int k = 0; k < 8; k++) {
                const uint32_t kb = (uint32_t)k * 32u;
                uint32_t ah[2][4];
                ldsm4(ah[0][0], ah[0][1], ah[0][2], ah[0][3], aH0 + kb);
                ldsm4(ah[1][0], ah[1][1], ah[1][2], ah[1][3], aH0 + 16u * PITCHB + kb);
                uint32_t w0, w1, w2, w3;
                ldsm4(w0, w1, w2, w3, b10 + kb);
#pragma unroll
                for (int mt = 0; mt < 2; mt++) {
                    mma16816(acc1[mt][0], ah[mt], w0, w1);
                    mma16816(acc1[mt][1], ah[mt], w2, w3);
                }
                ldsm4(w0, w1, w2, w3, b20 + kb);
#pragma unroll
                for (int mt = 0; mt < 2; mt++) {
                    mma16816(acc2[mt][0], ah[mt], w0, w1);
                    mma16816(acc2[mt][1], ah[mt], w2, w3);
                }
            }
        }

        // coalesced spill via stmatrix: Z1 hi/lo (near-fp32), Z2 single fp16
        {
            const uint32_t t = (uint32_t)lane >> 3;          // tile 0..3
            const uint32_t srow = (uint32_t)m0 + ((t >> 1) << 3) + (lane & 7);
            const uint32_t scol = (uint32_t)n0 + (t & 1) * 8;
            const uint32_t boff = srow * PITCHB + scol * 2;
#pragma unroll
            for (int mt = 0; mt < 2; mt++) {
                const uint32_t off = boff + (uint32_t)mt * (16u * PITCHB);
                // reg r for tile t holds fragment (row lane>>2, col 2(lane&3)) of that tile:
                // t0=(half0,ns0) t1=(half0,ns1) t2=(half1,ns0) t3=(half1,ns1)
                uint32_t h0 = cvtpack(acc1[mt][0][0], acc1[mt][0][1]);
                uint32_t h1 = cvtpack(acc1[mt][1][0], acc1[mt][1][1]);
                uint32_t h2 = cvtpack(acc1[mt][0][2], acc1[mt][0][3]);
                uint32_t h3 = cvtpack(acc1[mt][1][2], acc1[mt][1][3]);
                stsm4(sb + OFF_Z1H + off, h0, h1, h2, h3);
                uint32_t l0 = lopack(acc1[mt][0][0], acc1[mt][0][1], h0);
                uint32_t l1 = lopack(acc1[mt][1][0], acc1[mt][1][1], h1);
                uint32_t l2 = lopack(acc1[mt][0][2], acc1[mt][0][3], h2);
                uint32_t l3 = lopack(acc1[mt][1][2], acc1[mt][1][3], h3);
                stsm4(sb + OFF_Z1L + off, l0, l1, l2, l3);
                uint32_t z0 = cvtpack(acc2[mt][0][0], acc2[mt][0][1]);
                uint32_t z1 = cvtpack(acc2[mt][1][0], acc2[mt][1][1]);
                uint32_t z2 = cvtpack(acc2[mt][0][2], acc2[mt][0][3]);
                uint32_t z3 = cvtpack(acc2[mt][1][2], acc2[mt][1][3]);
                stsm4(sb + OFF_Z2 + off, z0, z1, z2, z3);
            }
        }
        __syncthreads();  // Z complete; all GEMM X reads done -> XH writable

        // coalesced epilogue pass: x' = elu( S·Z1 + Z2 + b ) -> X fp16 (row-major)
        {
            const float* brl = (const float*)(sm + OFF_BIAS + BO_BREL) + l * H;
            for (int idx = tid; idx < MROWS * 16; idx += NTHREADS) {
                int row = idx >> 4, c0 = (idx & 15) << 3;
                uint32_t doff = (uint32_t)row * PITCHB + (uint32_t)c0 * 2;
                if (row >= rows_real) {
                    *(uint4*)(sm + OFF_XH + doff) = make_uint4(0, 0, 0, 0);
                    continue;
                }
                float v[8];
#pragma unroll
                for (int e = 0; e < 8; e++) v[e] = brl[c0 + e];
                addu4h(v, *(const uint4*)(sm + OFF_Z2 + doff));
                const int gb = (row / NNODE) * NNODE;
                const int n  = row - gb;
                const int cnt = NSRC[n];
                for (int k2 = 0; k2 < cnt; k2++) {
                    uint32_t soff = (uint32_t)(gb + SRCS[n][k2]) * PITCHB + (uint32_t)c0 * 2;
                    addu4h(v, *(const uint4*)(sm + OFF_Z1H + soff));
                    addu4h(v, *(const uint4*)(sm + OFF_Z1L + soff));
                }
#pragma unroll
                for (int e = 0; e < 8; e++) v[e] = elu1(v[e]);
                store8h(sm, doff, v);
            }
        }

        // stage W(l+1) in the same phase (W buffers idle during pass)
        if (l + 1 < NLAYER) {
            const uint4* rel = (const uint4*)&g_wh[l + 1][0][0];
            const uint4* roo = (const uint4*)&g_wh[l + 1][1][0];
            for (int idx = tid; idx < H * 16; idx += NTHREADS) {
                uint32_t d = (uint32_t)(idx >> 4) * PITCHB + (uint32_t)(idx & 15) * 16;
                *(uint4*)(sm + OFF_W1 + d) = rel[idx];
                *(uint4*)(sm + OFF_W2 + d) = roo[idx];
            }
        }
    }
    __syncthreads();

    // ---- decoder (final X fp16 at OFF_XH) ----
    if (tid < ng * NJN) {
        int g = tid / NJN, j = tid - g * NJN;
        const char* xrow = sm + OFF_XH + (uint32_t)(g * NNODE + 1 + j) * PITCHB;
        const float* wd = (const float*)(sm + OFF_BIAS + BO_WDEC);
        float acc = ((const float*)(sm + OFF_BIAS + BO_BDEC))[0];
#pragma unroll
        for (int c = 0; c < H; c += 8) {
            uint4 p = *(const uint4*)(xrow + c * 2);
            const uint32_t* w32 = (const uint32_t*)&p;
#pragma unroll
            for (int k = 0; k < 4; k++) {
                float2 f = __half22float2(*reinterpret_cast<const __half2*>(&w32[k]));
                acc = fmaf(f.x, wd[c + 2 * k], acc);
                acc = fmaf(f.y, wd[c + 2 * k + 1], acc);
            }
        }
        out[(size_t)(g0 + g) * NJN + j] = acc;
    }
}

extern "C" void kernel_launch(void* const* d_in, const int* in_sizes, int n_in,
                              void* d_out, int out_size)
{
    const float* obs    = (const float*)d_in[0];
    const float* We_b   = (const float*)d_in[1];
    const float* be_b   = (const float*)d_in[2];
    const float* We_j   = (const float*)d_in[3];
    const float* be_j   = (const float*)d_in[4];
    const float* W_rel  = (const float*)d_in[5];
    const float* W_root = (const float*)d_in[6];
    const float* b_rel  = (const float*)d_in[7];
    const float* W_dec  = (const float*)d_in[8];
    const float* b_dec  = (const float*)d_in[9];
    float*       out    = (float*)d_out;

    const int B = in_sizes[0] / OBS_LEN;

    conv_weights_kernel<<<(NLAYER * 2 * H * H + 255) / 256, 256>>>(W_rel, W_root);

    const int ntiles = (B + GPT - 1) / GPT;
    cudaFuncSetAttribute(gnn_mma_kernel,
                         cudaFuncAttributeMaxDynamicSharedMemorySize, (int)SMEM_DYN);
    gnn_mma_kernel<<<ntiles, NTHREADS, SMEM_DYN>>>(
        obs, We_b, be_b, We_j, be_j, b_rel, W_dec, b_dec, out, B);
}

// round 14
// speedup vs baseline: 4.0694x; 1.0523x over previous
#include <cuda_runtime.h>
#include <cuda_fp16.h>
#include <stdint.h>
#include <math.h>

namespace {
constexpr int H = 128, NNODE = 13, NJN = 12, OBS_LEN = 141, NLAYER = 3;
constexpr int GPT = 9;               // graphs per CTA -> 117 rows, padded to 128
constexpr int MROWS = 128;
constexpr int NTHREADS = 1024;       // 32 warps: 4 M-slices x 8 N-slices
constexpr int BASE_F = 33, JOINT_F = 9;

constexpr uint32_t PITCHB = 272;     // fp16 row: 128 elems + 8 pad (conflict-free ld/stmatrix)
constexpr uint32_t MATB   = MROWS * PITCHB;        // 34816

constexpr uint32_t OFF_XH  = 0;              // X fp16 (all layers; decoder reads fp16)
constexpr uint32_t OFF_Z1  = MATB;           // Z1 fp16 (single plane)
constexpr uint32_t OFF_Z2  = 2 * MATB;       // Z2 fp16
constexpr uint32_t OFF_W1  = 3 * MATB;       // W_rel fp16
constexpr uint32_t OFF_W2  = 4 * MATB;       // W_root fp16
constexpr uint32_t OFF_OBS = 5 * MATB;
constexpr uint32_t OFF_BIAS = OFF_OBS + GPT * 144 * 4;
constexpr uint32_t BO_BEB = 0, BO_BEJ = 512, BO_BREL = 1024, BO_WDEC = 2560, BO_BDEC = 3072;
constexpr uint32_t OFF_WEB = OFF_Z1;         // encoder weights (pre-layer0, in Z1 area)
constexpr uint32_t OFF_WEJ = OFF_Z1 + 16896;
constexpr uint32_t SMEM_DYN = OFF_BIAS + 3104;     // ~178.1 KB

__device__ __constant__ int8_t NSRC[13] = {4,2,2,1,2,2,1,2,2,1,2,2,1};
__device__ __constant__ int8_t SRCS[13][4] = {
    {1,4,7,10},{0,2,0,0},{1,3,0,0},{2,0,0,0},{0,5,0,0},{4,6,0,0},{5,0,0,0},
    {0,8,0,0},{7,9,0,0},{8,0,0,0},{0,11,0,0},{10,12,0,0},{11,0,0,0}};
__device__ __constant__ int8_t BIDX[11] = {0,1,2,3,4,5,6,7,8,45,46};

__device__ __half g_wh[NLAYER][2][H * H];    // fp16 weights [layer][rel/root][n*128+k]

__device__ __forceinline__ uint32_t smem_u32(const void* p) {
    uint32_t a;
    asm("{ .reg .u64 t; cvta.to.shared.u64 t, %1; cvt.u32.u64 %0, t; }" : "=r"(a) : "l"(p));
    return a;
}
__device__ __forceinline__ float elu1(float v) { return v > 0.f ? v : __expf(v) - 1.f; }

__device__ __forceinline__ void ldsm4(uint32_t& r0, uint32_t& r1, uint32_t& r2, uint32_t& r3,
                                      uint32_t addr) {
    asm volatile("ldmatrix.sync.aligned.m8n8.x4.shared.b16 {%0,%1,%2,%3}, [%4];"
                 : "=r"(r0), "=r"(r1), "=r"(r2), "=r"(r3) : "r"(addr));
}
__device__ __forceinline__ void stsm4(uint32_t addr, uint32_t r0, uint32_t r1,
                                      uint32_t r2, uint32_t r3) {
    asm volatile("stmatrix.sync.aligned.m8n8.x4.shared.b16 [%0], {%1,%2,%3,%4};"
                 :: "r"(addr), "r"(r0), "r"(r1), "r"(r2), "r"(r3) : "memory");
}
__device__ __forceinline__ void mma16816(float* c, const uint32_t* a, uint32_t b0, uint32_t b1) {
    asm volatile(
        "mma.sync.aligned.m16n8k16.row.col.f32.f16.f16.f32 "
        "{%0,%1,%2,%3}, {%4,%5,%6,%7}, {%8,%9}, {%0,%1,%2,%3};"
        : "+f"(c[0]), "+f"(c[1]), "+f"(c[2]), "+f"(c[3])
        : "r"(a[0]), "r"(a[1]), "r"(a[2]), "r"(a[3]), "r"(b0), "r"(b1));
}

// packed f32x2 -> f16x2 (low half = first arg; PTX puts first source in HIGH half)
__device__ __forceinline__ uint32_t cvtpack(float lo, float hi) {
    uint32_t r;
    asm("cvt.rn.f16x2.f32 %0, %1, %2;" : "=r"(r) : "f"(hi), "f"(lo));
    return r;
}
__device__ __forceinline__ void store8h(char* sm, uint32_t doff, const float* v) {
    uint4 hh;
    uint32_t* ph = (uint32_t*)&hh;
#pragma unroll
    for (int k = 0; k < 4; k++) ph[k] = cvtpack(v[2 * k], v[2 * k + 1]);
    *(uint4*)(sm + OFF_XH + doff) = hh;
}
// v[0..7] += 8 fp16 values packed in a uint4
__device__ __forceinline__ void addu4h(float* v, uint4 p) {
    const uint32_t* w = (const uint32_t*)&p;
#pragma unroll
    for (int k = 0; k < 4; k++) {
        float2 f = __half22float2(*reinterpret_cast<const __half2*>(&w[k]));
        v[2 * k] += f.x;
        v[2 * k + 1] += f.y;
    }
}
} // namespace

__global__ void conv_weights_kernel(const float* __restrict__ W_rel,
                                    const float* __restrict__ W_root) {
    int i = blockIdx.x * blockDim.x + threadIdx.x;
    if (i >= NLAYER * 2 * H * H) return;
    int l = i / (2 * H * H);
    int r = i % (2 * H * H);
    int g = r / (H * H);
    int e = r % (H * H);
    float w = (g == 0) ? W_rel[l * H * H + e] : W_root[l * H * H + e];
    g_wh[l][g][e] = __float2half_rn(w);
}

__global__ __launch_bounds__(NTHREADS, 1) void gnn_mma_kernel(
    const float* __restrict__ obs,
    const float* __restrict__ We_b, const float* __restrict__ be_b,
    const float* __restrict__ We_j, const float* __restrict__ be_j,
    const float* __restrict__ b_rel,
    const float* __restrict__ W_dec, const float* __restrict__ b_dec,
    float* __restrict__ out, int B)
{
    extern __shared__ char sm[];
    const uint32_t sb = smem_u32(sm);
    const int tid = threadIdx.x, lane = tid & 31, wid = tid >> 5;
    const int m0 = (wid >> 3) * 32;          // 32-row slice (4 slices)
    const int n0 = (wid & 7) * 16;           // 16-col slice (8 slices)
    const int g0 = blockIdx.x * GPT;
    const int ng = min(GPT, B - g0);
    const int rows_real = ng * NNODE;

    // ---- stage biases / encoder weights / obs ----
    if (tid < H) {
        ((float*)(sm + OFF_BIAS + BO_BEB))[tid]  = be_b[tid];
        ((float*)(sm + OFF_BIAS + BO_BEJ))[tid]  = be_j[tid];
        ((float*)(sm + OFF_BIAS + BO_WDEC))[tid] = W_dec[tid];
    }
    if (tid >= H && tid < H + NLAYER * H)
        ((float*)(sm + OFF_BIAS + BO_BREL))[tid - H] = b_rel[tid - H];
    if (tid == 0) ((float*)(sm + OFF_BIAS + BO_BDEC))[0] = b_dec[0];
    for (int i = tid; i < H * BASE_F; i += NTHREADS) {
        int h = i / BASE_F, f = i - h * BASE_F;
        ((float*)(sm + OFF_WEB))[f * H + h] = We_b[i];
    }
    for (int i = tid; i < H * JOINT_F; i += NTHREADS) {
        int h = i / JOINT_F, f = i - h * JOINT_F;
        ((float*)(sm + OFF_WEJ))[f * H + h] = We_j[i];
    }
    for (int i = tid; i < ng * OBS_LEN; i += NTHREADS) {
        int g = i / OBS_LEN, k = i - g * OBS_LEN;
        ((float*)(sm + OFF_OBS))[g * 144 + k] = obs[(size_t)(g0 + g) * OBS_LEN + k];
    }
    __syncthreads();

    // ---- phase A: encoder (X fp16) + stage W(0) concurrently ----
    {
        const uint4* rel = (const uint4*)&g_wh[0][0][0];
        const uint4* roo = (const uint4*)&g_wh[0][1][0];
        for (int idx = tid; idx < H * 16; idx += NTHREADS) {
            uint32_t d = (uint32_t)(idx >> 4) * PITCHB + (uint32_t)(idx & 15) * 16;
            *(uint4*)(sm + OFF_W1 + d) = rel[idx];
            *(uint4*)(sm + OFF_W2 + d) = roo[idx];
        }
    }
    for (int idx = tid; idx < MROWS * 16; idx += NTHREADS) {
        int row = idx >> 4, c0 = (idx & 15) << 3;
        uint32_t doff = (uint32_t)row * PITCHB + (uint32_t)c0 * 2;
        if (row >= rows_real) {
            *(uint4*)(sm + OFF_XH + doff) = make_uint4(0, 0, 0, 0);  // zero pads ONCE
            continue;
        }
        int g = row / NNODE, n = row - g * NNODE;
        const float* ob = (const float*)(sm + OFF_OBS) + g * 144;
        float acc[8];
        if (n == 0) {
            const float* be = (const float*)(sm + OFF_BIAS + BO_BEB);
#pragma unroll
            for (int e = 0; e < 8; e++) acc[e] = be[c0 + e];
#pragma unroll
            for (int t = 0; t < 3; t++)
#pragma unroll
                for (int i2 = 0; i2 < 11; i2++) {
                    float ft = ob[t * 47 + BIDX[i2]];
                    const float* w = (const float*)(sm + OFF_WEB) + (t * 11 + i2) * H + c0;
#pragma unroll
                    for (int e = 0; e < 8; e++) acc[e] = fmaf(ft, w[e], acc[e]);
                }
        } else {
            int j = n - 1;
            const float* be = (const float*)(sm + OFF_BIAS + BO_BEJ);
#pragma unroll
            for (int e = 0; e < 8; e++) acc[e] = be[c0 + e];
#pragma unroll
            for (int f = 0; f < 9; f++) {
                float ft = ob[(f / 3) * 47 + 9 + (f % 3) * 12 + j];
                const float* w = (const float*)(sm + OFF_WEJ) + f * H + c0;
#pragma unroll
                for (int e = 0; e < 8; e++) acc[e] = fmaf(ft, w[e], acc[e]);
            }
        }
#pragma unroll
        for (int e = 0; e < 8; e++) acc[e] = elu1(acc[e]);
        store8h(sm, doff, acc);
    }

    // ---- layers:  x' = elu( S·(X@Wrel^T) + X@Wroot^T + b ) ----
    for (int l = 0; l < NLAYER; l++) {
        __syncthreads();  // X(l)+W(l) ready; prev pass's Z reads done

        // merged dual single-term GEMM over 32Mx16N tile
        float acc1[2][2][4], acc2[2][2][4];   // [mt][ns][4]
#pragma unroll
        for (int mt = 0; mt < 2; mt++)
#pragma unroll
            for (int ns = 0; ns < 2; ns++)
#pragma unroll
                for (int e = 0; e < 4; e++) { acc1[mt][ns][e] = 0.f; acc2[mt][ns][e] = 0.f; }
        {
            const uint32_t arow = (uint32_t)(lane & 15);
            const uint32_t acol = (uint32_t)((lane >> 4) << 4);
            const uint32_t brow = (uint32_t)((lane & 7) + ((lane >> 4) << 3));
            const uint32_t bcol = (uint32_t)(((lane >> 3) & 1) << 4);
            const uint32_t aH0 = sb + OFF_XH + ((uint32_t)m0 + arow) * PITCHB + acol;
            const uint32_t bro = ((uint32_t)n0 + brow) * PITCHB + bcol;
            const uint32_t b10 = sb + OFF_W1 + bro;
            const uint32_t b20 = sb + OFF_W2 + bro;
#pragma unroll 2
            for (int k = 0; k < 8; k++) {
                const uint32_t kb = (uint32_t)k * 32u;
                uint32_t ah[2][4];
                ldsm4(ah[0][0], ah[0][1], ah[0][2], ah[0][3], aH0 + kb);
                ldsm4(ah[1][0], ah[1][1], ah[1][2], ah[1][3], aH0 + 16u * PITCHB + kb);
                uint32_t w0, w1, w2, w3;
                ldsm4(w0, w1, w2, w3, b10 + kb);
#pragma unroll
                for (int mt = 0; mt < 2; mt++) {
                    mma16816(acc1[mt][0], ah[mt], w0, w1);
                    mma16816(acc1[mt][1], ah[mt], w2, w3);
                }
                ldsm4(w0, w1, w2, w3, b20 + kb);
#pragma unroll
                for (int mt = 0; mt < 2; mt++) {
                    mma16816(acc2[mt][0], ah[mt], w0, w1);
                    mma16816(acc2[mt][1], ah[mt], w2, w3);
                }
            }
        }

        // coalesced spill via stmatrix: Z1 fp16, Z2 fp16
        {
            const uint32_t t = (uint32_t)lane >> 3;          // tile 0..3
            const uint32_t srow = (uint32_t)m0 + ((t >> 1) << 3) + (lane & 7);
            const uint32_t scol = (uint32_t)n0 + (t & 1) * 8;
            const uint32_t boff = srow * PITCHB + scol * 2;
#pragma unroll
            for (int mt = 0; mt < 2; mt++) {
                const uint32_t off = boff + (uint32_t)mt * (16u * PITCHB);
                // reg r for tile t: t0=(half0,ns0) t1=(half0,ns1) t2=(half1,ns0) t3=(half1,ns1)
                stsm4(sb + OFF_Z1 + off,
                      cvtpack(acc1[mt][0][0], acc1[mt][0][1]),
                      cvtpack(acc1[mt][1][0], acc1[mt][1][1]),
                      cvtpack(acc1[mt][0][2], acc1[mt][0][3]),
                      cvtpack(acc1[mt][1][2], acc1[mt][1][3]));
                stsm4(sb + OFF_Z2 + off,
                      cvtpack(acc2[mt][0][0], acc2[mt][0][1]),
                      cvtpack(acc2[mt][1][0], acc2[mt][1][1]),
                      cvtpack(acc2[mt][0][2], acc2[mt][0][3]),
                      cvtpack(acc2[mt][1][2], acc2[mt][1][3]));
            }
        }
        __syncthreads();  // Z complete; all GEMM X reads done -> XH writable

        // coalesced epilogue pass: x' = elu( S·Z1 + Z2 + b ) -> X fp16 (row-major)
        // pad rows skipped entirely: their X stays zero from the encoder
        {
            const float* brl = (const float*)(sm + OFF_BIAS + BO_BREL) + l * H;
            for (int idx = tid; idx < MROWS * 16; idx += NTHREADS) {
                int row = idx >> 4, c0 = (idx & 15) << 3;
                if (row >= rows_real) continue;
                uint32_t doff = (uint32_t)row * PITCHB + (uint32_t)c0 * 2;
                float v[8];
#pragma unroll
                for (int e = 0; e < 8; e++) v[e] = brl[c0 + e];
                addu4h(v, *(const uint4*)(sm + OFF_Z2 + doff));
                const int gb = (row / NNODE) * NNODE;
                const int n  = row - gb;
                const int cnt = NSRC[n];
                for (int k2 = 0; k2 < cnt; k2++) {
                    uint32_t soff = (uint32_t)(gb + SRCS[n][k2]) * PITCHB + (uint32_t)c0 * 2;
                    addu4h(v, *(const uint4*)(sm + OFF_Z1 + soff));
                }
#pragma unroll
                for (int e = 0; e < 8; e++) v[e] = elu1(v[e]);
                store8h(sm, doff, v);
            }
        }

        // stage W(l+1) in the same phase (W buffers idle during pass)
        if (l + 1 < NLAYER) {
            const uint4* rel = (const uint4*)&g_wh[l + 1][0][0];
            const uint4* roo = (const uint4*)&g_wh[l + 1][1][0];
            for (int idx = tid; idx < H * 16; idx += NTHREADS) {
                uint32_t d = (uint32_t)(idx >> 4) * PITCHB + (uint32_t)(idx & 15) * 16;
                *(uint4*)(sm + OFF_W1 + d) = rel[idx];
                *(uint4*)(sm + OFF_W2 + d) = roo[idx];
            }
        }
    }
    __syncthreads();

    // ---- decoder (final X fp16 at OFF_XH) ----
    if (tid < ng * NJN) {
        int g = tid / NJN, j = tid - g * NJN;
        const char* xrow = sm + OFF_XH + (uint32_t)(g * NNODE + 1 + j) * PITCHB;
        const float* wd = (const float*)(sm + OFF_BIAS + BO_WDEC);
        float acc = ((const float*)(sm + OFF_BIAS + BO_BDEC))[0];
#pragma unroll
        for (int c = 0; c < H; c += 8) {
            uint4 p = *(const uint4*)(xrow + c * 2);
            const uint32_t* w32 = (const uint32_t*)&p;
#pragma unroll
            for (int k = 0; k < 4; k++) {
                float2 f = __half22float2(*reinterpret_cast<const __half2*>(&w32[k]));
                acc = fmaf(f.x, wd[c + 2 * k], acc);
                acc = fmaf(f.y, wd[c + 2 * k + 1], acc);
            }
        }
        out[(size_t)(g0 + g) * NJN + j] = acc;
    }
}

extern "C" void kernel_launch(void* const* d_in, const int* in_sizes, int n_in,
                              void* d_out, int out_size)
{
    const float* obs    = (const float*)d_in[0];
    const float* We_b   = (const float*)d_in[1];
    const float* be_b   = (const float*)d_in[2];
    const float* We_j   = (const float*)d_in[3];
    const float* be_j   = (const float*)d_in[4];
    const float* W_rel  = (const float*)d_in[5];
    const float* W_root = (const float*)d_in[6];
    const float* b_rel  = (const float*)d_in[7];
    const float* W_dec  = (const float*)d_in[8];
    const float* b_dec  = (const float*)d_in[9];
    float*       out    = (float*)d_out;

    const int B = in_sizes[0] / OBS_LEN;

    conv_weights_kernel<<<(NLAYER * 2 * H * H + 255) / 256, 256>>>(W_rel, W_root);

    const int ntiles = (B + GPT - 1) / GPT;
    cudaFuncSetAttribute(gnn_mma_kernel,
                         cudaFuncAttributeMaxDynamicSharedMemorySize, (int)SMEM_DYN);
    gnn_mma_kernel<<<ntiles, NTHREADS, SMEM_DYN>>>(
        obs, We_b, be_b, We_j, be_j, b_rel, W_dec, b_dec, out, B);
}